// round 5
// baseline (speedup 1.0000x reference)
#include <cuda_runtime.h>
#include <math.h>
#include <stdint.h>

// ---------------- problem constants ----------------
constexpr int BB   = 32;
constexpr int NSEQ = 256;
constexpr int DIM  = 1024;
constexpr int NH   = 16;
constexpr int HDIM = 64;
constexpr int CDIM = 1024;
constexpr int NE   = 4;
constexpr int DFFC = 4096;
constexpr int RHC  = 2048;
constexpr int TT   = BB * NSEQ;   // 8192 tokens

// ---------------- scratch (device globals; no allocation allowed) ----------------
__device__ float g_h1[TT * DIM];
__device__ float g_qkv[TT * 3 * DIM];
__device__ float g_S[(size_t)BB * NH * NSEQ * NSEQ];
__device__ float g_o[TT * DIM];
__device__ float g_x1[TT * DIM];
__device__ float g_h2[TT * DIM];
__device__ float g_condc[BB * RHC];
__device__ float g_gh[(size_t)TT * RHC];
__device__ float g_hid[(size_t)TT * DFFC];
__device__ int   g_cnt[NE];
__device__ int   g_idx[NE * TT];
__device__ float g_wgt[NE * TT];

// ---------------- helpers ----------------
__device__ __forceinline__ float warpsum(float v) {
    #pragma unroll
    for (int o = 16; o; o >>= 1) v += __shfl_xor_sync(0xFFFFFFFFu, v, o);
    return v;
}
__device__ __forceinline__ float warpmax(float v) {
    #pragma unroll
    for (int o = 16; o; o >>= 1) v = fmaxf(v, __shfl_xor_sync(0xFFFFFFFFu, v, o));
    return v;
}
__device__ __forceinline__ float gelu_f(float x) {
    return 0.5f * x * (1.0f + erff(x * 0.70710678118654752f));
}
__device__ __forceinline__ unsigned f2tf(float x) {
    unsigned u; asm("cvt.rna.tf32.f32 %0, %1;" : "=r"(u) : "f"(x)); return u;
}
// split x into hi (tf32) and lo (tf32 of remainder)
__device__ __forceinline__ void tfsplit(float x, unsigned& hi, unsigned& lo) {
    hi = f2tf(x);
    lo = f2tf(x - __uint_as_float(hi));
}
__device__ __forceinline__ void mma8(float* c, const unsigned* a, const unsigned* b) {
    asm("mma.sync.aligned.m16n8k8.row.col.f32.tf32.tf32.f32 "
        "{%0,%1,%2,%3}, {%4,%5,%6,%7}, {%8,%9}, {%0,%1,%2,%3};"
        : "+f"(c[0]), "+f"(c[1]), "+f"(c[2]), "+f"(c[3])
        : "r"(a[0]), "r"(a[1]), "r"(a[2]), "r"(a[3]), "r"(b[0]), "r"(b[1]));
}

// ---------------- LayerNorm: one block per token, 256 threads ----------------
__global__ __launch_bounds__(256) void ln_kernel(
    const float* __restrict__ x, const float* __restrict__ g,
    const float* __restrict__ bta, float* __restrict__ out)
{
    int t = blockIdx.x, tid = threadIdx.x;
    float4 v = ((const float4*)(x + (size_t)t * DIM))[tid];
    float s  = v.x + v.y + v.z + v.w;
    float sq = v.x * v.x + v.y * v.y + v.z * v.z + v.w * v.w;
    __shared__ float sh[8], sh2[8];
    float ws = warpsum(s), wq = warpsum(sq);
    if ((tid & 31) == 0) { sh[tid >> 5] = ws; sh2[tid >> 5] = wq; }
    __syncthreads();
    if (tid < 32) {
        float a  = (tid < 8) ? sh[tid]  : 0.f;
        float b2 = (tid < 8) ? sh2[tid] : 0.f;
        a = warpsum(a); b2 = warpsum(b2);
        if (tid == 0) { sh[0] = a; sh2[0] = b2; }
    }
    __syncthreads();
    float mu  = sh[0] * (1.0f / DIM);
    float var = sh2[0] * (1.0f / DIM) - mu * mu;
    float inv = rsqrtf(var + 1e-5f);
    float4 gg = ((const float4*)g)[tid], bb = ((const float4*)bta)[tid];
    float4 o;
    o.x = (v.x - mu) * inv * gg.x + bb.x;
    o.y = (v.y - mu) * inv * gg.y + bb.y;
    o.z = (v.z - mu) * inv * gg.z + bb.z;
    o.w = (v.w - mu) * inv * gg.w + bb.w;
    ((float4*)(out + (size_t)t * DIM))[tid] = o;
}

// ---------------- 3xTF32 tensor-core GEMM 128x128x16, 256 thr ----------------
// C[M,Nn] = A[M,K] @ B[K,Nn] row-major; Nn % 128 == 0, K % 16 == 0.
// warp grid 2(m) x 4(n); warp tile 64x32 via m16n8k8 tf32 mma.
// fp32 accuracy restored via hi/lo split: Ahi*Bhi + Ahi*Blo + Alo*Bhi.
template<bool GATHER, bool SCATTER, bool BIAS, bool GELU, bool RESID, bool CONDC>
__global__ __launch_bounds__(256) void gemm_tc(
    const float* __restrict__ A, const float* __restrict__ Bm, float* __restrict__ C,
    int M, int Nn, int K,
    const float* __restrict__ bias, const float* __restrict__ res,
    const float* __restrict__ condc,
    const int* __restrict__ gidx, const float* __restrict__ wrow,
    const int* __restrict__ cntp)
{
    if (cntp) M = *cntp;
    int row0 = blockIdx.y * 128;
    if (row0 >= M) return;
    int col0 = blockIdx.x * 128;

    // raw fp32 tiles; A as [m][k] stride 20, B as [k][n] stride 136
    __shared__ float As[2][128][20];
    __shared__ float Bs[2][16][136];

    int tid  = threadIdx.x;
    int lane = tid & 31;
    int warp = tid >> 5;
    int grp  = lane >> 2;      // 0..7
    int qid  = lane & 3;       // 0..3
    int warp_m = warp >> 2;    // 0..1
    int warp_n = warp & 3;     // 0..3
    int m_base = warp_m * 64;
    int n_base = warp_n * 32;

    // A loader: 2 rows per thread, float4 along k
    int a_r  = tid >> 2;           // 0..63
    int a_k4 = (tid & 3) * 4;
    int ar1 = row0 + a_r;
    int ar2 = row0 + a_r + 64;
    bool av1 = ar1 < M, av2 = ar2 < M;
    int arow1 = av1 ? (GATHER ? gidx[ar1] : ar1) : 0;
    int arow2 = av2 ? (GATHER ? gidx[ar2] : ar2) : 0;

    // B loader: 2 k-rows per thread, float4 along n
    int b_k  = tid >> 5;           // 0..7 (and +8)
    int b_n4 = (tid & 31) * 4;

    float acc[4][4][4];
    #pragma unroll
    for (int i = 0; i < 4; i++)
        #pragma unroll
        for (int j = 0; j < 4; j++)
            #pragma unroll
            for (int q = 0; q < 4; q++) acc[i][j][q] = 0.f;

    int nt = K / 16;
    float4 ra0, ra1, rb0, rb1;

    // prologue: load tile 0
    ra0 = av1 ? *(const float4*)(A + (size_t)arow1 * K + a_k4) : make_float4(0,0,0,0);
    ra1 = av2 ? *(const float4*)(A + (size_t)arow2 * K + a_k4) : make_float4(0,0,0,0);
    rb0 = *(const float4*)(Bm + (size_t)b_k * Nn + col0 + b_n4);
    rb1 = *(const float4*)(Bm + (size_t)(b_k + 8) * Nn + col0 + b_n4);
    *(float4*)&As[0][a_r][a_k4]      = ra0;
    *(float4*)&As[0][a_r + 64][a_k4] = ra1;
    *(float4*)&Bs[0][b_k][b_n4]      = rb0;
    *(float4*)&Bs[0][b_k + 8][b_n4]  = rb1;
    __syncthreads();

    for (int t = 0; t < nt; t++) {
        int cur = t & 1;
        if (t + 1 < nt) {
            int k0 = (t + 1) * 16;
            ra0 = av1 ? *(const float4*)(A + (size_t)arow1 * K + k0 + a_k4) : make_float4(0,0,0,0);
            ra1 = av2 ? *(const float4*)(A + (size_t)arow2 * K + k0 + a_k4) : make_float4(0,0,0,0);
            rb0 = *(const float4*)(Bm + (size_t)(k0 + b_k) * Nn + col0 + b_n4);
            rb1 = *(const float4*)(Bm + (size_t)(k0 + b_k + 8) * Nn + col0 + b_n4);
        }
        // compute on buffer cur: two k8 steps, 3xTF32 compensated
        #pragma unroll
        for (int k8 = 0; k8 < 16; k8 += 8) {
            unsigned ah[4][4], al[4][4], bh[4][2], bl[4][2];
            #pragma unroll
            for (int mi = 0; mi < 4; mi++) {
                int rm = m_base + mi * 16 + grp;
                tfsplit(As[cur][rm][k8 + qid],          ah[mi][0], al[mi][0]);
                tfsplit(As[cur][rm + 8][k8 + qid],      ah[mi][1], al[mi][1]);
                tfsplit(As[cur][rm][k8 + qid + 4],      ah[mi][2], al[mi][2]);
                tfsplit(As[cur][rm + 8][k8 + qid + 4],  ah[mi][3], al[mi][3]);
            }
            #pragma unroll
            for (int ni = 0; ni < 4; ni++) {
                int cn = n_base + ni * 8 + grp;
                tfsplit(Bs[cur][k8 + qid][cn],          bh[ni][0], bl[ni][0]);
                tfsplit(Bs[cur][k8 + qid + 4][cn],      bh[ni][1], bl[ni][1]);
            }
            #pragma unroll
            for (int mi = 0; mi < 4; mi++)
                #pragma unroll
                for (int ni = 0; ni < 4; ni++) {
                    mma8(acc[mi][ni], ah[mi], bl[ni]);   // hi*lo
                    mma8(acc[mi][ni], al[mi], bh[ni]);   // lo*hi
                    mma8(acc[mi][ni], ah[mi], bh[ni]);   // hi*hi
                }
        }
        if (t + 1 < nt) {
            int nxt = (t + 1) & 1;
            *(float4*)&As[nxt][a_r][a_k4]      = ra0;
            *(float4*)&As[nxt][a_r + 64][a_k4] = ra1;
            *(float4*)&Bs[nxt][b_k][b_n4]      = rb0;
            *(float4*)&Bs[nxt][b_k + 8][b_n4]  = rb1;
            __syncthreads();
        }
    }

    // ---------------- epilogue ----------------
    #pragma unroll
    for (int mi = 0; mi < 4; mi++) {
        int r0 = row0 + m_base + mi * 16 + grp;
        int r1 = r0 + 8;
        bool v0 = r0 < M, v1 = r1 < M;
        size_t cr0 = 0, cr1 = 0;
        float w0 = 1.f, w1 = 1.f;
        if (v0) { cr0 = SCATTER ? (size_t)gidx[r0] : (size_t)r0; if (SCATTER) w0 = wrow[r0]; }
        if (v1) { cr1 = SCATTER ? (size_t)gidx[r1] : (size_t)r1; if (SCATTER) w1 = wrow[r1]; }
        #pragma unroll
        for (int ni = 0; ni < 4; ni++) {
            int cb = col0 + n_base + ni * 8 + qid * 2;
            #pragma unroll
            for (int half = 0; half < 2; half++) {
                bool valid = half ? v1 : v0;
                if (!valid) continue;
                int rr = half ? r1 : r0;
                size_t cr = half ? cr1 : cr0;
                float w = half ? w1 : w0;
                float e0 = acc[mi][ni][half * 2 + 0];
                float e1 = acc[mi][ni][half * 2 + 1];
                if (BIAS)  { e0 += bias[cb]; e1 += bias[cb + 1]; }
                if (CONDC) {
                    const float* cc = condc + (size_t)(rr >> 8) * Nn + cb;
                    e0 += cc[0]; e1 += cc[1];
                }
                if (GELU)  { e0 = gelu_f(e0); e1 = gelu_f(e1); }
                if (RESID) {
                    const float* rp = res + (size_t)rr * Nn + cb;
                    e0 += rp[0]; e1 += rp[1];
                }
                float* cp = C + cr * Nn + cb;
                if (SCATTER) {
                    float2 old = *(float2*)cp;
                    e0 = old.x + w * e0;
                    e1 = old.y + w * e1;
                }
                *(float2*)cp = make_float2(e0, e1);
            }
        }
    }
}

// ---------------- attention: S = scale * Q K^T  (64x64 tiles, k=64) ----------------
__global__ __launch_bounds__(256) void attn_scores(
    const float* __restrict__ qkv, float* __restrict__ S)
{
    int kt = blockIdx.x, qt = blockIdx.y, bh = blockIdx.z;
    int b = bh >> 4, h = bh & 15;
    int q0 = qt * 64, k0 = kt * 64;
    __shared__ float Qs[64][65];
    __shared__ float Ks[64][65];
    int tid = threadIdx.x;
    #pragma unroll
    for (int i = 0; i < 4; i++) {
        int lin = tid + i * 256;
        int row = lin >> 4;
        int c4  = (lin & 15) * 4;
        float4 qv = *(const float4*)(qkv + (size_t)(b * NSEQ + q0 + row) * 3 * DIM + h * HDIM + c4);
        Qs[row][c4] = qv.x; Qs[row][c4 + 1] = qv.y; Qs[row][c4 + 2] = qv.z; Qs[row][c4 + 3] = qv.w;
        float4 kv = *(const float4*)(qkv + (size_t)(b * NSEQ + k0 + row) * 3 * DIM + DIM + h * HDIM + c4);
        Ks[row][c4] = kv.x; Ks[row][c4 + 1] = kv.y; Ks[row][c4 + 2] = kv.z; Ks[row][c4 + 3] = kv.w;
    }
    __syncthreads();
    int ty = tid >> 4, tx = tid & 15;
    float acc[4][4];
    #pragma unroll
    for (int i = 0; i < 4; i++)
        #pragma unroll
        for (int j = 0; j < 4; j++) acc[i][j] = 0.f;
    #pragma unroll 16
    for (int kk = 0; kk < 64; kk++) {
        float a[4], bv[4];
        #pragma unroll
        for (int i = 0; i < 4; i++) a[i]  = Qs[ty * 4 + i][kk];
        #pragma unroll
        for (int j = 0; j < 4; j++) bv[j] = Ks[tx * 4 + j][kk];
        #pragma unroll
        for (int i = 0; i < 4; i++)
            #pragma unroll
            for (int j = 0; j < 4; j++) acc[i][j] += a[i] * bv[j];
    }
    float* Sp = S + (size_t)bh * NSEQ * NSEQ;
    #pragma unroll
    for (int i = 0; i < 4; i++) {
        float4 v = make_float4(acc[i][0] * 0.125f, acc[i][1] * 0.125f,
                               acc[i][2] * 0.125f, acc[i][3] * 0.125f);
        *(float4*)(Sp + (size_t)(q0 + ty * 4 + i) * NSEQ + k0 + tx * 4) = v;
    }
}

// ---------------- softmax over rows of 256 (one warp/row) ----------------
__global__ __launch_bounds__(128) void softmax_kernel(float* __restrict__ S) {
    size_t row = (size_t)blockIdx.x * 4 + (threadIdx.x >> 5);
    int lane = threadIdx.x & 31;
    float* p = S + row * NSEQ;
    float v[8];
    float m = -1e30f;
    #pragma unroll
    for (int i = 0; i < 8; i++) { v[i] = p[lane + i * 32]; m = fmaxf(m, v[i]); }
    m = warpmax(m);
    float s = 0.f;
    #pragma unroll
    for (int i = 0; i < 8; i++) { v[i] = expf(v[i] - m); s += v[i]; }
    s = warpsum(s);
    float inv = 1.0f / s;
    #pragma unroll
    for (int i = 0; i < 8; i++) p[lane + i * 32] = v[i] * inv;
}

// ---------------- O = P @ V  (64 q-rows x 64 cols per block) ----------------
__global__ __launch_bounds__(256) void attn_av(
    const float* __restrict__ qkv, const float* __restrict__ S, float* __restrict__ o)
{
    int qt = blockIdx.x, bh = blockIdx.y;
    int b = bh >> 4, h = bh & 15;
    int q0 = qt * 64;
    __shared__ float Ps[64][17];
    __shared__ float Vs[16][64];
    int tid = threadIdx.x;
    int ty = tid >> 4, tx = tid & 15;
    float acc[4][4];
    #pragma unroll
    for (int i = 0; i < 4; i++)
        #pragma unroll
        for (int j = 0; j < 4; j++) acc[i][j] = 0.f;
    const float* Sp = S + (size_t)bh * NSEQ * NSEQ;
    for (int k0 = 0; k0 < NSEQ; k0 += 16) {
        {
            int row = tid >> 2, c = (tid & 3) * 4;
            float4 pv = *(const float4*)(Sp + (size_t)(q0 + row) * NSEQ + k0 + c);
            Ps[row][c] = pv.x; Ps[row][c + 1] = pv.y; Ps[row][c + 2] = pv.z; Ps[row][c + 3] = pv.w;
        }
        {
            int kr = tid >> 4, c = (tid & 15) * 4;
            float4 vv = *(const float4*)(qkv + (size_t)(b * NSEQ + k0 + kr) * 3 * DIM + 2 * DIM + h * HDIM + c);
            *(float4*)&Vs[kr][c] = vv;
        }
        __syncthreads();
        #pragma unroll
        for (int kk = 0; kk < 16; kk++) {
            float a[4], bv[4];
            #pragma unroll
            for (int i = 0; i < 4; i++) a[i]  = Ps[ty * 4 + i][kk];
            #pragma unroll
            for (int j = 0; j < 4; j++) bv[j] = Vs[kk][tx * 4 + j];
            #pragma unroll
            for (int i = 0; i < 4; i++)
                #pragma unroll
                for (int j = 0; j < 4; j++) acc[i][j] += a[i] * bv[j];
        }
        __syncthreads();
    }
    #pragma unroll
    for (int i = 0; i < 4; i++) {
        float4 v = make_float4(acc[i][0], acc[i][1], acc[i][2], acc[i][3]);
        *(float4*)(o + (size_t)(b * NSEQ + q0 + ty * 4 + i) * DIM + h * HDIM + tx * 4) = v;
    }
}

// ---------------- router fc2 + softmax + top2 + scatter lists ----------------
__global__ __launch_bounds__(128) void router_kernel(
    const float* __restrict__ gh, const float* __restrict__ W, const float* __restrict__ bias)
{
    int t = blockIdx.x;
    int wid = threadIdx.x >> 5, lane = threadIdx.x & 31;
    const float* row = gh + (size_t)t * RHC;
    float s = 0.f;
    for (int k = lane; k < RHC; k += 32) s += row[k] * W[k * NE + wid];
    s = warpsum(s);
    __shared__ float logits[NE];
    if (lane == 0) logits[wid] = s + bias[wid];
    __syncthreads();
    if (threadIdx.x == 0) {
        float l[NE], m = -1e30f;
        #pragma unroll
        for (int e = 0; e < NE; e++) { l[e] = logits[e]; m = fmaxf(m, l[e]); }
        float ssum = 0.f;
        #pragma unroll
        for (int e = 0; e < NE; e++) { l[e] = expf(l[e] - m); ssum += l[e]; }
        float p[NE];
        #pragma unroll
        for (int e = 0; e < NE; e++)
            p[e] = fminf(fmaxf(l[e] / ssum, 1e-9f), 1.0f - 1e-9f);
        int i1 = 0;
        #pragma unroll
        for (int e = 1; e < NE; e++) if (p[e] > p[i1]) i1 = e;
        int i2 = -1;
        #pragma unroll
        for (int e = 0; e < NE; e++) {
            if (e == i1) continue;
            if (i2 < 0 || p[e] > p[i2]) i2 = e;
        }
        float wsum = p[i1] + p[i2];
        int pos = atomicAdd(&g_cnt[i1], 1);
        g_idx[i1 * TT + pos] = t; g_wgt[i1 * TT + pos] = p[i1] / wsum;
        pos = atomicAdd(&g_cnt[i2], 1);
        g_idx[i2 * TT + pos] = t; g_wgt[i2 * TT + pos] = p[i2] / wsum;
    }
}

__global__ void zero_cnt_kernel() {
    if (threadIdx.x < NE) g_cnt[threadIdx.x] = 0;
}

__global__ __launch_bounds__(256) void copy_kernel(const float* __restrict__ a, float* __restrict__ b) {
    size_t i = (size_t)blockIdx.x * blockDim.x + threadIdx.x;
    ((float4*)b)[i] = ((const float4*)a)[i];
}

// ---------------- host launcher ----------------
static void* symaddr(const void* s) {
    void* p = nullptr;
    cudaGetSymbolAddress(&p, s);
    return p;
}

extern "C" void kernel_launch(void* const* d_in, const int* in_sizes, int n_in,
                              void* d_out, int out_size) {
    const float* x       = (const float*)d_in[0];
    const float* cond    = (const float*)d_in[1];
    const float* ln1_g   = (const float*)d_in[2];
    const float* ln1_b   = (const float*)d_in[3];
    const float* qkv_w   = (const float*)d_in[4];
    const float* proj_w  = (const float*)d_in[5];
    const float* proj_b  = (const float*)d_in[6];
    const float* ln2_g   = (const float*)d_in[7];
    const float* ln2_b   = (const float*)d_in[8];
    const float* r_fc1_w = (const float*)d_in[9];
    const float* r_fc1_b = (const float*)d_in[10];
    const float* r_fc2_w = (const float*)d_in[11];
    const float* r_fc2_b = (const float*)d_in[12];
    const float* e_w1    = (const float*)d_in[13];
    const float* e_b1    = (const float*)d_in[14];
    const float* e_w2    = (const float*)d_in[15];
    const float* e_b2    = (const float*)d_in[16];
    float* out = (float*)d_out;

    float* h1    = (float*)symaddr(g_h1);
    float* qkv   = (float*)symaddr(g_qkv);
    float* S     = (float*)symaddr(g_S);
    float* o     = (float*)symaddr(g_o);
    float* x1    = (float*)symaddr(g_x1);
    float* h2    = (float*)symaddr(g_h2);
    float* condc = (float*)symaddr(g_condc);
    float* gh    = (float*)symaddr(g_gh);
    float* hid   = (float*)symaddr(g_hid);
    int*   cnt   = (int*)symaddr(g_cnt);
    int*   idx   = (int*)symaddr(g_idx);
    float* wgt   = (float*)symaddr(g_wgt);

    zero_cnt_kernel<<<1, 32>>>();

    // LN1
    ln_kernel<<<TT, 256>>>(x, ln1_g, ln1_b, h1);

    // QKV = h1 @ qkv_w   [8192,3072]
    gemm_tc<false,false,false,false,false,false>
        <<<dim3(3 * DIM / 128, TT / 128), 256>>>(h1, qkv_w, qkv, TT, 3 * DIM, DIM,
            nullptr, nullptr, nullptr, nullptr, nullptr, nullptr);

    // attention
    attn_scores<<<dim3(4, 4, BB * NH), 256>>>(qkv, S);
    softmax_kernel<<<BB * NH * NSEQ / 4, 128>>>(S);
    attn_av<<<dim3(4, BB * NH), 256>>>(qkv, S, o);

    // x1 = x + o @ proj_w + proj_b
    gemm_tc<false,false,true,false,true,false>
        <<<dim3(DIM / 128, TT / 128), 256>>>(o, proj_w, x1, TT, DIM, DIM,
            proj_b, x, nullptr, nullptr, nullptr, nullptr);

    // LN2
    ln_kernel<<<TT, 256>>>(x1, ln2_g, ln2_b, h2);

    // condc[b] = cond[b] @ r_fc1_w[D:, :]   [32,2048]
    gemm_tc<false,false,false,false,false,false>
        <<<dim3(RHC / 128, 1), 256>>>(cond, r_fc1_w + (size_t)DIM * RHC, condc,
            BB, RHC, CDIM, nullptr, nullptr, nullptr, nullptr, nullptr, nullptr);

    // gh = gelu(h2 @ r_fc1_w[:D] + condc[b] + b1)
    gemm_tc<false,false,true,true,false,true>
        <<<dim3(RHC / 128, TT / 128), 256>>>(h2, r_fc1_w, gh, TT, RHC, DIM,
            r_fc1_b, nullptr, condc, nullptr, nullptr, nullptr);

    // router: fc2 + softmax + top2 + per-expert lists
    router_kernel<<<TT, 128>>>(gh, r_fc2_w, r_fc2_b);

    // out = x1
    copy_kernel<<<TT * DIM / 4 / 256, 256>>>(x1, out);

    // experts: gather rows of h2 -> hid = gelu(. @ w1 + b1); out[tok] += w * (hid @ w2 + b2)
    for (int e = 0; e < NE; e++) {
        gemm_tc<true,false,true,true,false,false>
            <<<dim3(DFFC / 128, TT / 128), 256>>>(h2, e_w1 + (size_t)e * DIM * DFFC, hid,
                TT, DFFC, DIM, e_b1 + e * DFFC, nullptr, nullptr,
                idx + e * TT, nullptr, cnt + e);
        gemm_tc<false,true,true,false,false,false>
            <<<dim3(DIM / 128, TT / 128), 256>>>(hid, e_w2 + (size_t)e * DFFC * DIM, out,
                TT, DIM, DFFC, e_b2 + e * DIM, nullptr, nullptr,
                idx + e * TT, wgt + e * TT, cnt + e);
    }
}

// round 7
// speedup vs baseline: 2.5381x; 2.5381x over previous
#include <cuda_runtime.h>
#include <cuda_bf16.h>
#include <math.h>
#include <stdint.h>

// ---------------- problem constants ----------------
constexpr int BB   = 32;
constexpr int NSEQ = 256;
constexpr int DIM  = 1024;
constexpr int NH   = 16;
constexpr int HDIM = 64;
constexpr int CDIM = 1024;
constexpr int NE   = 4;
constexpr int DFFC = 4096;
constexpr int RHC  = 2048;
constexpr int TT   = BB * NSEQ;   // 8192 tokens

// ---------------- scratch (device globals; no allocation allowed) ----------------
__device__ float g_h1[TT * DIM];
__device__ float g_qkv[TT * 3 * DIM];
__device__ float g_S[(size_t)BB * NH * NSEQ * NSEQ];
__device__ float g_o[TT * DIM];
__device__ float g_x1[TT * DIM];
__device__ float g_h2[TT * DIM];
__device__ float g_condc[BB * RHC];
__device__ float g_gh[(size_t)TT * RHC];
__device__ float g_hid[(size_t)TT * DFFC];
__device__ int   g_cnt[NE];
__device__ int   g_idx[NE * TT];
__device__ float g_wgt[NE * TT];

// ---------------- helpers ----------------
__device__ __forceinline__ float warpsum(float v) {
    #pragma unroll
    for (int o = 16; o; o >>= 1) v += __shfl_xor_sync(0xFFFFFFFFu, v, o);
    return v;
}
__device__ __forceinline__ float warpmax(float v) {
    #pragma unroll
    for (int o = 16; o; o >>= 1) v = fmaxf(v, __shfl_xor_sync(0xFFFFFFFFu, v, o));
    return v;
}
__device__ __forceinline__ float gelu_f(float x) {
    return 0.5f * x * (1.0f + erff(x * 0.70710678118654752f));
}
// split (x0,x1) into packed bf16x2 hi and lo (x ~= hi + lo)
__device__ __forceinline__ void bfsplit2(float x0, float x1, uint32_t& hi, uint32_t& lo) {
    __nv_bfloat162 h = __floats2bfloat162_rn(x0, x1);
    float r0 = x0 - __bfloat162float(h.x);
    float r1 = x1 - __bfloat162float(h.y);
    __nv_bfloat162 l = __floats2bfloat162_rn(r0, r1);
    hi = *reinterpret_cast<uint32_t*>(&h);
    lo = *reinterpret_cast<uint32_t*>(&l);
}
__device__ __forceinline__ void mma16(float* c, const uint32_t* a, const uint32_t* b) {
    asm("mma.sync.aligned.m16n8k16.row.col.f32.bf16.bf16.f32 "
        "{%0,%1,%2,%3}, {%4,%5,%6,%7}, {%8,%9}, {%0,%1,%2,%3};"
        : "+f"(c[0]), "+f"(c[1]), "+f"(c[2]), "+f"(c[3])
        : "r"(a[0]), "r"(a[1]), "r"(a[2]), "r"(a[3]), "r"(b[0]), "r"(b[1]));
}

// ---------------- LayerNorm: one block per token, 256 threads ----------------
__global__ __launch_bounds__(256) void ln_kernel(
    const float* __restrict__ x, const float* __restrict__ g,
    const float* __restrict__ bta, float* __restrict__ out)
{
    int t = blockIdx.x, tid = threadIdx.x;
    float4 v = ((const float4*)(x + (size_t)t * DIM))[tid];
    float s  = v.x + v.y + v.z + v.w;
    float sq = v.x * v.x + v.y * v.y + v.z * v.z + v.w * v.w;
    __shared__ float sh[8], sh2[8];
    float ws = warpsum(s), wq = warpsum(sq);
    if ((tid & 31) == 0) { sh[tid >> 5] = ws; sh2[tid >> 5] = wq; }
    __syncthreads();
    if (tid < 32) {
        float a  = (tid < 8) ? sh[tid]  : 0.f;
        float b2 = (tid < 8) ? sh2[tid] : 0.f;
        a = warpsum(a); b2 = warpsum(b2);
        if (tid == 0) { sh[0] = a; sh2[0] = b2; }
    }
    __syncthreads();
    float mu  = sh[0] * (1.0f / DIM);
    float var = sh2[0] * (1.0f / DIM) - mu * mu;
    float inv = rsqrtf(var + 1e-5f);
    float4 gg = ((const float4*)g)[tid], bb = ((const float4*)bta)[tid];
    float4 o;
    o.x = (v.x - mu) * inv * gg.x + bb.x;
    o.y = (v.y - mu) * inv * gg.y + bb.y;
    o.z = (v.z - mu) * inv * gg.z + bb.z;
    o.w = (v.w - mu) * inv * gg.w + bb.w;
    ((float4*)(out + (size_t)t * DIM))[tid] = o;
}

// ---------------- 3x-bf16 tensor-core GEMM 128x128x16, 256 thr ----------------
// C[M,Nn] = A[M,K] @ B[K,Nn] row-major; Nn % 128 == 0, K % 16 == 0.
// warp grid 2(m) x 4(n); warp tile 64x32 via m16n8k16 bf16 mma.
// fp32-like accuracy via hi/lo split done ONCE at smem-store time:
// A*B ~= Ahi*Bhi + Ahi*Blo + Alo*Bhi   (drop lo*lo, ~2^-18 relative)
template<bool GATHER, bool SCATTER, bool BIAS, bool GELU, bool RESID, bool CONDC>
__global__ __launch_bounds__(256) void gemm_tc(
    const float* __restrict__ A, const float* __restrict__ Bm, float* __restrict__ C,
    int M, int Nn, int K,
    const float* __restrict__ bias, const float* __restrict__ res,
    const float* __restrict__ condc,
    const int* __restrict__ gidx, const float* __restrict__ wrow,
    const int* __restrict__ cntp)
{
    if (cntp) M = *cntp;
    int row0 = blockIdx.y * 128;
    if (row0 >= M) return;
    int col0 = blockIdx.x * 128;

    // packed bf16x2 k-pair tiles
    __shared__ uint32_t Ah[2][128][9];   // [row][kpair], pad 9
    __shared__ uint32_t Al[2][128][9];
    __shared__ uint32_t Bh[2][8][132];   // [kpair][n], pad 132
    __shared__ uint32_t Bl[2][8][132];

    int tid  = threadIdx.x;
    int lane = tid & 31;
    int warp = tid >> 5;
    int grp  = lane >> 2;      // 0..7
    int qid  = lane & 3;       // 0..3
    int warp_m = warp >> 2;    // 0..1
    int warp_n = warp & 3;     // 0..3
    int m_base = warp_m * 64;
    int n_base = warp_n * 32;

    // A loader: 2 rows per thread, float4 along k (kpairs 2*(tid&3), +1)
    int a_r  = tid >> 2;           // 0..63
    int a_k4 = (tid & 3) * 4;
    int a_kp = (tid & 3) * 2;
    int ar1 = row0 + a_r;
    int ar2 = row0 + a_r + 64;
    bool av1 = ar1 < M, av2 = ar2 < M;
    int arow1 = av1 ? (GATHER ? gidx[ar1] : ar1) : 0;
    int arow2 = av2 ? (GATHER ? gidx[ar2] : ar2) : 0;

    // B loader: kpair = tid>>5 (0..7), 4 consecutive n; loads k rows 2kp, 2kp+1
    int b_kp = tid >> 5;
    int b_n4 = (tid & 31) * 4;

    float acc[4][4][4];
    #pragma unroll
    for (int i = 0; i < 4; i++)
        #pragma unroll
        for (int j = 0; j < 4; j++)
            #pragma unroll
            for (int q = 0; q < 4; q++) acc[i][j][q] = 0.f;

    int nt = K / 16;
    float4 ra0, ra1, rbE, rbO;

    // prologue: load + split + store tile 0
    ra0 = av1 ? *(const float4*)(A + (size_t)arow1 * K + a_k4) : make_float4(0,0,0,0);
    ra1 = av2 ? *(const float4*)(A + (size_t)arow2 * K + a_k4) : make_float4(0,0,0,0);
    rbE = *(const float4*)(Bm + (size_t)(2 * b_kp)     * Nn + col0 + b_n4);
    rbO = *(const float4*)(Bm + (size_t)(2 * b_kp + 1) * Nn + col0 + b_n4);
    {
        uint32_t h0, l0, h1, l1;
        bfsplit2(ra0.x, ra0.y, h0, l0); bfsplit2(ra0.z, ra0.w, h1, l1);
        Ah[0][a_r][a_kp] = h0; Ah[0][a_r][a_kp + 1] = h1;
        Al[0][a_r][a_kp] = l0; Al[0][a_r][a_kp + 1] = l1;
        bfsplit2(ra1.x, ra1.y, h0, l0); bfsplit2(ra1.z, ra1.w, h1, l1);
        Ah[0][a_r + 64][a_kp] = h0; Ah[0][a_r + 64][a_kp + 1] = h1;
        Al[0][a_r + 64][a_kp] = l0; Al[0][a_r + 64][a_kp + 1] = l1;
        uint32_t bh4[4], bl4[4];
        bfsplit2(rbE.x, rbO.x, bh4[0], bl4[0]);
        bfsplit2(rbE.y, rbO.y, bh4[1], bl4[1]);
        bfsplit2(rbE.z, rbO.z, bh4[2], bl4[2]);
        bfsplit2(rbE.w, rbO.w, bh4[3], bl4[3]);
        *(uint4*)&Bh[0][b_kp][b_n4] = *(uint4*)bh4;
        *(uint4*)&Bl[0][b_kp][b_n4] = *(uint4*)bl4;
    }
    __syncthreads();

    for (int t = 0; t < nt; t++) {
        int cur = t & 1;
        if (t + 1 < nt) {
            int k0 = (t + 1) * 16;
            ra0 = av1 ? *(const float4*)(A + (size_t)arow1 * K + k0 + a_k4) : make_float4(0,0,0,0);
            ra1 = av2 ? *(const float4*)(A + (size_t)arow2 * K + k0 + a_k4) : make_float4(0,0,0,0);
            rbE = *(const float4*)(Bm + (size_t)(k0 + 2 * b_kp)     * Nn + col0 + b_n4);
            rbO = *(const float4*)(Bm + (size_t)(k0 + 2 * b_kp + 1) * Nn + col0 + b_n4);
        }
        // fragments: pure LDS, no conversion
        uint32_t a_h[4][4], a_l[4][4], b_h[4][2], b_l[4][2];
        #pragma unroll
        for (int mi = 0; mi < 4; mi++) {
            int rm = m_base + mi * 16 + grp;
            a_h[mi][0] = Ah[cur][rm][qid];         a_l[mi][0] = Al[cur][rm][qid];
            a_h[mi][1] = Ah[cur][rm + 8][qid];     a_l[mi][1] = Al[cur][rm + 8][qid];
            a_h[mi][2] = Ah[cur][rm][qid + 4];     a_l[mi][2] = Al[cur][rm][qid + 4];
            a_h[mi][3] = Ah[cur][rm + 8][qid + 4]; a_l[mi][3] = Al[cur][rm + 8][qid + 4];
        }
        #pragma unroll
        for (int ni = 0; ni < 4; ni++) {
            int cn = n_base + ni * 8 + grp;
            b_h[ni][0] = Bh[cur][qid][cn];     b_l[ni][0] = Bl[cur][qid][cn];
            b_h[ni][1] = Bh[cur][qid + 4][cn]; b_l[ni][1] = Bl[cur][qid + 4][cn];
        }
        #pragma unroll
        for (int mi = 0; mi < 4; mi++)
            #pragma unroll
            for (int ni = 0; ni < 4; ni++) {
                mma16(acc[mi][ni], a_h[mi], b_l[ni]);   // hi*lo
                mma16(acc[mi][ni], a_l[mi], b_h[ni]);   // lo*hi
                mma16(acc[mi][ni], a_h[mi], b_h[ni]);   // hi*hi
            }
        if (t + 1 < nt) {
            int nxt = (t + 1) & 1;
            uint32_t h0, l0, h1, l1;
            bfsplit2(ra0.x, ra0.y, h0, l0); bfsplit2(ra0.z, ra0.w, h1, l1);
            Ah[nxt][a_r][a_kp] = h0; Ah[nxt][a_r][a_kp + 1] = h1;
            Al[nxt][a_r][a_kp] = l0; Al[nxt][a_r][a_kp + 1] = l1;
            bfsplit2(ra1.x, ra1.y, h0, l0); bfsplit2(ra1.z, ra1.w, h1, l1);
            Ah[nxt][a_r + 64][a_kp] = h0; Ah[nxt][a_r + 64][a_kp + 1] = h1;
            Al[nxt][a_r + 64][a_kp] = l0; Al[nxt][a_r + 64][a_kp + 1] = l1;
            uint32_t bh4[4], bl4[4];
            bfsplit2(rbE.x, rbO.x, bh4[0], bl4[0]);
            bfsplit2(rbE.y, rbO.y, bh4[1], bl4[1]);
            bfsplit2(rbE.z, rbO.z, bh4[2], bl4[2]);
            bfsplit2(rbE.w, rbO.w, bh4[3], bl4[3]);
            *(uint4*)&Bh[nxt][b_kp][b_n4] = *(uint4*)bh4;
            *(uint4*)&Bl[nxt][b_kp][b_n4] = *(uint4*)bl4;
            __syncthreads();
        }
    }

    // ---------------- epilogue ----------------
    #pragma unroll
    for (int mi = 0; mi < 4; mi++) {
        int r0 = row0 + m_base + mi * 16 + grp;
        int r1 = r0 + 8;
        bool v0 = r0 < M, v1 = r1 < M;
        size_t cr0 = 0, cr1 = 0;
        float w0 = 1.f, w1 = 1.f;
        if (v0) { cr0 = SCATTER ? (size_t)gidx[r0] : (size_t)r0; if (SCATTER) w0 = wrow[r0]; }
        if (v1) { cr1 = SCATTER ? (size_t)gidx[r1] : (size_t)r1; if (SCATTER) w1 = wrow[r1]; }
        #pragma unroll
        for (int ni = 0; ni < 4; ni++) {
            int cb = col0 + n_base + ni * 8 + qid * 2;
            #pragma unroll
            for (int half = 0; half < 2; half++) {
                bool valid = half ? v1 : v0;
                if (!valid) continue;
                int rr = half ? r1 : r0;
                size_t cr = half ? cr1 : cr0;
                float w = half ? w1 : w0;
                float e0 = acc[mi][ni][half * 2 + 0];
                float e1 = acc[mi][ni][half * 2 + 1];
                if (BIAS)  { e0 += bias[cb]; e1 += bias[cb + 1]; }
                if (CONDC) {
                    const float* cc = condc + (size_t)(rr >> 8) * Nn + cb;
                    e0 += cc[0]; e1 += cc[1];
                }
                if (GELU)  { e0 = gelu_f(e0); e1 = gelu_f(e1); }
                if (RESID) {
                    const float* rp = res + (size_t)rr * Nn + cb;
                    e0 += rp[0]; e1 += rp[1];
                }
                float* cp = C + cr * Nn + cb;
                if (SCATTER) {
                    float2 old = *(float2*)cp;
                    e0 = old.x + w * e0;
                    e1 = old.y + w * e1;
                }
                *(float2*)cp = make_float2(e0, e1);
            }
        }
    }
}

// ---------------- attention: S = scale * Q K^T  (64x64 tiles, k=64) ----------------
__global__ __launch_bounds__(256) void attn_scores(
    const float* __restrict__ qkv, float* __restrict__ S)
{
    int kt = blockIdx.x, qt = blockIdx.y, bh = blockIdx.z;
    int b = bh >> 4, h = bh & 15;
    int q0 = qt * 64, k0 = kt * 64;
    __shared__ float Qs[64][65];
    __shared__ float Ks[64][65];
    int tid = threadIdx.x;
    #pragma unroll
    for (int i = 0; i < 4; i++) {
        int lin = tid + i * 256;
        int row = lin >> 4;
        int c4  = (lin & 15) * 4;
        float4 qv = *(const float4*)(qkv + (size_t)(b * NSEQ + q0 + row) * 3 * DIM + h * HDIM + c4);
        Qs[row][c4] = qv.x; Qs[row][c4 + 1] = qv.y; Qs[row][c4 + 2] = qv.z; Qs[row][c4 + 3] = qv.w;
        float4 kv = *(const float4*)(qkv + (size_t)(b * NSEQ + k0 + row) * 3 * DIM + DIM + h * HDIM + c4);
        Ks[row][c4] = kv.x; Ks[row][c4 + 1] = kv.y; Ks[row][c4 + 2] = kv.z; Ks[row][c4 + 3] = kv.w;
    }
    __syncthreads();
    int ty = tid >> 4, tx = tid & 15;
    float acc[4][4];
    #pragma unroll
    for (int i = 0; i < 4; i++)
        #pragma unroll
        for (int j = 0; j < 4; j++) acc[i][j] = 0.f;
    #pragma unroll 16
    for (int kk = 0; kk < 64; kk++) {
        float a[4], bv[4];
        #pragma unroll
        for (int i = 0; i < 4; i++) a[i]  = Qs[ty * 4 + i][kk];
        #pragma unroll
        for (int j = 0; j < 4; j++) bv[j] = Ks[tx * 4 + j][kk];
        #pragma unroll
        for (int i = 0; i < 4; i++)
            #pragma unroll
            for (int j = 0; j < 4; j++) acc[i][j] += a[i] * bv[j];
    }
    float* Sp = S + (size_t)bh * NSEQ * NSEQ;
    #pragma unroll
    for (int i = 0; i < 4; i++) {
        float4 v = make_float4(acc[i][0] * 0.125f, acc[i][1] * 0.125f,
                               acc[i][2] * 0.125f, acc[i][3] * 0.125f);
        *(float4*)(Sp + (size_t)(q0 + ty * 4 + i) * NSEQ + k0 + tx * 4) = v;
    }
}

// ---------------- softmax over rows of 256 (one warp/row) ----------------
__global__ __launch_bounds__(128) void softmax_kernel(float* __restrict__ S) {
    size_t row = (size_t)blockIdx.x * 4 + (threadIdx.x >> 5);
    int lane = threadIdx.x & 31;
    float* p = S + row * NSEQ;
    float v[8];
    float m = -1e30f;
    #pragma unroll
    for (int i = 0; i < 8; i++) { v[i] = p[lane + i * 32]; m = fmaxf(m, v[i]); }
    m = warpmax(m);
    float s = 0.f;
    #pragma unroll
    for (int i = 0; i < 8; i++) { v[i] = expf(v[i] - m); s += v[i]; }
    s = warpsum(s);
    float inv = 1.0f / s;
    #pragma unroll
    for (int i = 0; i < 8; i++) p[lane + i * 32] = v[i] * inv;
}

// ---------------- O = P @ V  (64 q-rows x 64 cols per block) ----------------
__global__ __launch_bounds__(256) void attn_av(
    const float* __restrict__ qkv, const float* __restrict__ S, float* __restrict__ o)
{
    int qt = blockIdx.x, bh = blockIdx.y;
    int b = bh >> 4, h = bh & 15;
    int q0 = qt * 64;
    __shared__ float Ps[64][17];
    __shared__ float Vs[16][64];
    int tid = threadIdx.x;
    int ty = tid >> 4, tx = tid & 15;
    float acc[4][4];
    #pragma unroll
    for (int i = 0; i < 4; i++)
        #pragma unroll
        for (int j = 0; j < 4; j++) acc[i][j] = 0.f;
    const float* Sp = S + (size_t)bh * NSEQ * NSEQ;
    for (int k0 = 0; k0 < NSEQ; k0 += 16) {
        {
            int row = tid >> 2, c = (tid & 3) * 4;
            float4 pv = *(const float4*)(Sp + (size_t)(q0 + row) * NSEQ + k0 + c);
            Ps[row][c] = pv.x; Ps[row][c + 1] = pv.y; Ps[row][c + 2] = pv.z; Ps[row][c + 3] = pv.w;
        }
        {
            int kr = tid >> 4, c = (tid & 15) * 4;
            float4 vv = *(const float4*)(qkv + (size_t)(b * NSEQ + k0 + kr) * 3 * DIM + 2 * DIM + h * HDIM + c);
            *(float4*)&Vs[kr][c] = vv;
        }
        __syncthreads();
        #pragma unroll
        for (int kk = 0; kk < 16; kk++) {
            float a[4], bv[4];
            #pragma unroll
            for (int i = 0; i < 4; i++) a[i]  = Ps[ty * 4 + i][kk];
            #pragma unroll
            for (int j = 0; j < 4; j++) bv[j] = Vs[kk][tx * 4 + j];
            #pragma unroll
            for (int i = 0; i < 4; i++)
                #pragma unroll
                for (int j = 0; j < 4; j++) acc[i][j] += a[i] * bv[j];
        }
        __syncthreads();
    }
    #pragma unroll
    for (int i = 0; i < 4; i++) {
        float4 v = make_float4(acc[i][0], acc[i][1], acc[i][2], acc[i][3]);
        *(float4*)(o + (size_t)(b * NSEQ + q0 + ty * 4 + i) * DIM + h * HDIM + tx * 4) = v;
    }
}

// ---------------- router fc2 + softmax + top2 + scatter lists ----------------
__global__ __launch_bounds__(128) void router_kernel(
    const float* __restrict__ gh, const float* __restrict__ W, const float* __restrict__ bias)
{
    int t = blockIdx.x;
    int wid = threadIdx.x >> 5, lane = threadIdx.x & 31;
    const float* row = gh + (size_t)t * RHC;
    float s = 0.f;
    for (int k = lane; k < RHC; k += 32) s += row[k] * W[k * NE + wid];
    s = warpsum(s);
    __shared__ float logits[NE];
    if (lane == 0) logits[wid] = s + bias[wid];
    __syncthreads();
    if (threadIdx.x == 0) {
        float l[NE], m = -1e30f;
        #pragma unroll
        for (int e = 0; e < NE; e++) { l[e] = logits[e]; m = fmaxf(m, l[e]); }
        float ssum = 0.f;
        #pragma unroll
        for (int e = 0; e < NE; e++) { l[e] = expf(l[e] - m); ssum += l[e]; }
        float p[NE];
        #pragma unroll
        for (int e = 0; e < NE; e++)
            p[e] = fminf(fmaxf(l[e] / ssum, 1e-9f), 1.0f - 1e-9f);
        int i1 = 0;
        #pragma unroll
        for (int e = 1; e < NE; e++) if (p[e] > p[i1]) i1 = e;
        int i2 = -1;
        #pragma unroll
        for (int e = 0; e < NE; e++) {
            if (e == i1) continue;
            if (i2 < 0 || p[e] > p[i2]) i2 = e;
        }
        float wsum = p[i1] + p[i2];
        int pos = atomicAdd(&g_cnt[i1], 1);
        g_idx[i1 * TT + pos] = t; g_wgt[i1 * TT + pos] = p[i1] / wsum;
        pos = atomicAdd(&g_cnt[i2], 1);
        g_idx[i2 * TT + pos] = t; g_wgt[i2 * TT + pos] = p[i2] / wsum;
    }
}

__global__ void zero_cnt_kernel() {
    if (threadIdx.x < NE) g_cnt[threadIdx.x] = 0;
}

__global__ __launch_bounds__(256) void copy_kernel(const float* __restrict__ a, float* __restrict__ b) {
    size_t i = (size_t)blockIdx.x * blockDim.x + threadIdx.x;
    ((float4*)b)[i] = ((const float4*)a)[i];
}

// ---------------- host launcher ----------------
static void* symaddr(const void* s) {
    void* p = nullptr;
    cudaGetSymbolAddress(&p, s);
    return p;
}

extern "C" void kernel_launch(void* const* d_in, const int* in_sizes, int n_in,
                              void* d_out, int out_size) {
    const float* x       = (const float*)d_in[0];
    const float* cond    = (const float*)d_in[1];
    const float* ln1_g   = (const float*)d_in[2];
    const float* ln1_b   = (const float*)d_in[3];
    const float* qkv_w   = (const float*)d_in[4];
    const float* proj_w  = (const float*)d_in[5];
    const float* proj_b  = (const float*)d_in[6];
    const float* ln2_g   = (const float*)d_in[7];
    const float* ln2_b   = (const float*)d_in[8];
    const float* r_fc1_w = (const float*)d_in[9];
    const float* r_fc1_b = (const float*)d_in[10];
    const float* r_fc2_w = (const float*)d_in[11];
    const float* r_fc2_b = (const float*)d_in[12];
    const float* e_w1    = (const float*)d_in[13];
    const float* e_b1    = (const float*)d_in[14];
    const float* e_w2    = (const float*)d_in[15];
    const float* e_b2    = (const float*)d_in[16];
    float* out = (float*)d_out;

    float* h1    = (float*)symaddr(g_h1);
    float* qkv   = (float*)symaddr(g_qkv);
    float* S     = (float*)symaddr(g_S);
    float* o     = (float*)symaddr(g_o);
    float* x1    = (float*)symaddr(g_x1);
    float* h2    = (float*)symaddr(g_h2);
    float* condc = (float*)symaddr(g_condc);
    float* gh    = (float*)symaddr(g_gh);
    float* hid   = (float*)symaddr(g_hid);
    int*   cnt   = (int*)symaddr(g_cnt);
    int*   idx   = (int*)symaddr(g_idx);
    float* wgt   = (float*)symaddr(g_wgt);

    zero_cnt_kernel<<<1, 32>>>();

    // LN1
    ln_kernel<<<TT, 256>>>(x, ln1_g, ln1_b, h1);

    // QKV = h1 @ qkv_w   [8192,3072]
    gemm_tc<false,false,false,false,false,false>
        <<<dim3(3 * DIM / 128, TT / 128), 256>>>(h1, qkv_w, qkv, TT, 3 * DIM, DIM,
            nullptr, nullptr, nullptr, nullptr, nullptr, nullptr);

    // attention
    attn_scores<<<dim3(4, 4, BB * NH), 256>>>(qkv, S);
    softmax_kernel<<<BB * NH * NSEQ / 4, 128>>>(S);
    attn_av<<<dim3(4, BB * NH), 256>>>(qkv, S, o);

    // x1 = x + o @ proj_w + proj_b
    gemm_tc<false,false,true,false,true,false>
        <<<dim3(DIM / 128, TT / 128), 256>>>(o, proj_w, x1, TT, DIM, DIM,
            proj_b, x, nullptr, nullptr, nullptr, nullptr);

    // LN2
    ln_kernel<<<TT, 256>>>(x1, ln2_g, ln2_b, h2);

    // condc[b] = cond[b] @ r_fc1_w[D:, :]   [32,2048]
    gemm_tc<false,false,false,false,false,false>
        <<<dim3(RHC / 128, 1), 256>>>(cond, r_fc1_w + (size_t)DIM * RHC, condc,
            BB, RHC, CDIM, nullptr, nullptr, nullptr, nullptr, nullptr, nullptr);

    // gh = gelu(h2 @ r_fc1_w[:D] + condc[b] + b1)
    gemm_tc<false,false,true,true,false,true>
        <<<dim3(RHC / 128, TT / 128), 256>>>(h2, r_fc1_w, gh, TT, RHC, DIM,
            r_fc1_b, nullptr, condc, nullptr, nullptr, nullptr);

    // router: fc2 + softmax + top2 + per-expert lists
    router_kernel<<<TT, 128>>>(gh, r_fc2_w, r_fc2_b);

    // out = x1
    copy_kernel<<<TT * DIM / 4 / 256, 256>>>(x1, out);

    // experts: gather rows of h2 -> hid = gelu(. @ w1 + b1); out[tok] += w * (hid @ w2 + b2)
    for (int e = 0; e < NE; e++) {
        gemm_tc<true,false,true,true,false,false>
            <<<dim3(DFFC / 128, TT / 128), 256>>>(h2, e_w1 + (size_t)e * DIM * DFFC, hid,
                TT, DFFC, DIM, e_b1 + e * DFFC, nullptr, nullptr,
                idx + e * TT, nullptr, cnt + e);
        gemm_tc<false,true,true,false,false,false>
            <<<dim3(DIM / 128, TT / 128), 256>>>(hid, e_w2 + (size_t)e * DFFC * DIM, out,
                TT, DIM, DFFC, e_b2 + e * DIM, nullptr, nullptr,
                idx + e * TT, wgt + e * TT, cnt + e);
    }
}

// round 9
// speedup vs baseline: 2.6244x; 1.0340x over previous
#include <cuda_runtime.h>
#include <cuda_bf16.h>
#include <math.h>
#include <stdint.h>

// ---------------- problem constants ----------------
constexpr int BB   = 32;
constexpr int NSEQ = 256;
constexpr int DIM  = 1024;
constexpr int NH   = 16;
constexpr int HDIM = 64;
constexpr int CDIM = 1024;
constexpr int NE   = 4;
constexpr int DFFC = 4096;
constexpr int RHC  = 2048;
constexpr int TT   = BB * NSEQ;   // 8192 tokens

// ---------------- scratch (device globals; no allocation allowed) ----------------
__device__ float g_h1[TT * DIM];
__device__ float g_qkv[TT * 3 * DIM];
__device__ float g_S[(size_t)BB * NH * NSEQ * NSEQ];
__device__ float g_o[TT * DIM];
__device__ float g_x1[TT * DIM];
__device__ float g_h2[TT * DIM];
__device__ float g_condc[BB * RHC];
__device__ float g_gh[(size_t)TT * RHC];
__device__ float g_hid[(size_t)TT * DFFC];
__device__ int   g_cnt[NE];
__device__ int   g_idx[NE * TT];
__device__ float g_wgt[NE * TT];

// pre-split K-major weights: [N][K] bf16 hi/lo
__device__ __nv_bfloat16 g_wqkv_h[(size_t)3 * DIM * DIM];
__device__ __nv_bfloat16 g_wqkv_l[(size_t)3 * DIM * DIM];
__device__ __nv_bfloat16 g_wproj_h[(size_t)DIM * DIM];
__device__ __nv_bfloat16 g_wproj_l[(size_t)DIM * DIM];
__device__ __nv_bfloat16 g_wfc1_h[(size_t)RHC * DIM];
__device__ __nv_bfloat16 g_wfc1_l[(size_t)RHC * DIM];
__device__ __nv_bfloat16 g_we1_h[(size_t)NE * DFFC * DIM];
__device__ __nv_bfloat16 g_we1_l[(size_t)NE * DFFC * DIM];
__device__ __nv_bfloat16 g_we2_h[(size_t)NE * DIM * DFFC];
__device__ __nv_bfloat16 g_we2_l[(size_t)NE * DIM * DFFC];

// ---------------- helpers ----------------
__device__ __forceinline__ float warpsum(float v) {
    #pragma unroll
    for (int o = 16; o; o >>= 1) v += __shfl_xor_sync(0xFFFFFFFFu, v, o);
    return v;
}
__device__ __forceinline__ float warpmax(float v) {
    #pragma unroll
    for (int o = 16; o; o >>= 1) v = fmaxf(v, __shfl_xor_sync(0xFFFFFFFFu, v, o));
    return v;
}
__device__ __forceinline__ float gelu_f(float x) {
    return 0.5f * x * (1.0f + erff(x * 0.70710678118654752f));
}
__device__ __forceinline__ void bfsplit2(float x0, float x1, uint32_t& hi, uint32_t& lo) {
    __nv_bfloat162 h = __floats2bfloat162_rn(x0, x1);
    float r0 = x0 - __bfloat162float(h.x);
    float r1 = x1 - __bfloat162float(h.y);
    __nv_bfloat162 l = __floats2bfloat162_rn(r0, r1);
    hi = *reinterpret_cast<uint32_t*>(&h);
    lo = *reinterpret_cast<uint32_t*>(&l);
}
__device__ __forceinline__ void mma16(float* c, const uint32_t* a, const uint32_t* b) {
    asm("mma.sync.aligned.m16n8k16.row.col.f32.bf16.bf16.f32 "
        "{%0,%1,%2,%3}, {%4,%5,%6,%7}, {%8,%9}, {%0,%1,%2,%3};"
        : "+f"(c[0]), "+f"(c[1]), "+f"(c[2]), "+f"(c[3])
        : "r"(a[0]), "r"(a[1]), "r"(a[2]), "r"(a[3]), "r"(b[0]), "r"(b[1]));
}
__device__ __forceinline__ void ldmx4(uint32_t* r, uint32_t a) {
    asm volatile("ldmatrix.sync.aligned.m8n8.x4.shared.b16 {%0,%1,%2,%3}, [%4];"
        : "=r"(r[0]), "=r"(r[1]), "=r"(r[2]), "=r"(r[3]) : "r"(a));
}
__device__ __forceinline__ void ldmx2(uint32_t* r, uint32_t a) {
    asm volatile("ldmatrix.sync.aligned.m8n8.x2.shared.b16 {%0,%1}, [%2];"
        : "=r"(r[0]), "=r"(r[1]) : "r"(a));
}
__device__ __forceinline__ uint32_t smem_u32(const void* p) {
    uint32_t a;
    asm("{ .reg .u64 t; cvta.to.shared.u64 t, %1; cvt.u32.u64 %0, t; }" : "=r"(a) : "l"(p));
    return a;
}
__device__ __forceinline__ void cp16(uint32_t dst, const void* src) {
    asm volatile("cp.async.ca.shared.global [%0], [%1], 16;" :: "r"(dst), "l"(src));
}
__device__ __forceinline__ void cp_commit() { asm volatile("cp.async.commit_group;" ::: "memory"); }
__device__ __forceinline__ void cp_wait0()  { asm volatile("cp.async.wait_group 0;" ::: "memory"); }

// ---------------- weight transpose + split: W[K,N] -> Wh/Wl[N,K] bf16 ----------------
__global__ __launch_bounds__(256) void wsplit_kernel(
    const float* __restrict__ W, __nv_bfloat16* __restrict__ Wh, __nv_bfloat16* __restrict__ Wl,
    int K, int Nn, int ld, size_t wz, size_t oz)
{
    __shared__ float ts[32][33];
    int z = blockIdx.z;
    const float* Wp = W + (size_t)z * wz;
    int n0 = blockIdx.x * 32, k0 = blockIdx.y * 32;
    int tx = threadIdx.x & 31, ty = threadIdx.x >> 5;
    #pragma unroll
    for (int i = 0; i < 4; i++)
        ts[ty + i * 8][tx] = Wp[(size_t)(k0 + ty + i * 8) * ld + n0 + tx];
    __syncthreads();
    #pragma unroll
    for (int i = 0; i < 4; i++) {
        int n = n0 + ty + i * 8, k = k0 + tx;
        float v = ts[tx][ty + i * 8];
        __nv_bfloat16 h = __float2bfloat16(v);
        __nv_bfloat16 l = __float2bfloat16(v - __bfloat162float(h));
        Wh[(size_t)z * oz + (size_t)n * K + k] = h;
        Wl[(size_t)z * oz + (size_t)n * K + k] = l;
    }
}

// ---------------- bf16 3-term split GEMM, ldmatrix + cp.async, K32 stages ----------
// C[M,Nn] = A[M,K](fp32) @ W(pre-split bf16 [Nn][K]); CTA 128x128, 8 warps 2m x 4n.
// smem per stage: Ah[128][20]u32 | Al | Bh[128 n][20]u32 | Bl  (rows: 16 u32 used + 4 pad)
constexpr int G_AH = 0;
constexpr int G_AL = 10240;
constexpr int G_BH = 20480;
constexpr int G_BL = 30720;
constexpr int G_STG = 40960;
constexpr int G_SMEM = 2 * G_STG;     // 81920

template<bool GATHER, bool SCATTER, bool BIAS, bool GELU, bool RESID, bool CONDC>
__global__ __launch_bounds__(256) void gemm_tc2(
    const float* __restrict__ A,
    const __nv_bfloat16* __restrict__ Bh, const __nv_bfloat16* __restrict__ Bl,
    float* __restrict__ C, int M, int Nn, int K,
    const float* __restrict__ bias, const float* __restrict__ res,
    const float* __restrict__ condc,
    const int* __restrict__ gidx, const float* __restrict__ wrow,
    const int* __restrict__ cntp)
{
    extern __shared__ char sm[];
    if (cntp) M = *cntp;
    int row0 = blockIdx.y * 128;
    if (row0 >= M) return;
    int col0 = blockIdx.x * 128;

    uint32_t sb = smem_u32(sm);
    int tid = threadIdx.x, lane = tid & 31, warp = tid >> 5;
    int m_base = (warp >> 2) * 64, n_base = (warp & 3) * 32;

    // ---- loader mapping ----
    int l_row  = tid >> 1;           // 0..127
    int l_half = tid & 1;            // k-half within 32-chunk
    int gar = row0 + l_row;
    bool gav = gar < M;
    int garow = gav ? (GATHER ? gidx[gar] : gar) : 0;
    const float* ap = A + (size_t)garow * K;
    const char* bhp = (const char*)(Bh + (size_t)(col0 + l_row) * K);
    const char* blp = (const char*)(Bl + (size_t)(col0 + l_row) * K);
    uint32_t a_sts = sb + (uint32_t)(l_row * 20 + l_half * 8) * 4;   // +G_AH / +G_AL
    uint32_t b_sts = sb + (uint32_t)(l_row * 20 + l_half * 8) * 4;   // +G_BH / +G_BL

    // ---- ldmatrix per-thread addresses (byte offsets within a stage) ----
    uint32_t a_lrow = (uint32_t)(m_base + (lane & 7) + ((lane >> 3) & 1) * 8);
    uint32_t a_lcol = (uint32_t)((lane >> 4) * 4);
    int bl15 = lane & 15;
    uint32_t b_lrow = (uint32_t)(n_base + (bl15 & 7));
    uint32_t b_lcol = (uint32_t)(((bl15 >> 3) & 1) * 4);

    float acc[4][4][4];
    #pragma unroll
    for (int i = 0; i < 4; i++)
        #pragma unroll
        for (int j = 0; j < 4; j++)
            #pragma unroll
            for (int q = 0; q < 4; q++) acc[i][j][q] = 0.f;

    int nt = K >> 5;   // K32 stages
    float4 pa[4];

    // ---- stage loader pieces ----
    auto ldgA = [&](int kt) {
        const float* p = ap + kt * 32 + l_half * 16;
        if (gav) {
            pa[0] = *(const float4*)(p);
            pa[1] = *(const float4*)(p + 4);
            pa[2] = *(const float4*)(p + 8);
            pa[3] = *(const float4*)(p + 12);
        } else {
            pa[0] = pa[1] = pa[2] = pa[3] = make_float4(0.f, 0.f, 0.f, 0.f);
        }
    };
    auto cpB = [&](int kt, int buf) {
        uint32_t d = b_sts + buf * G_STG;
        const char* sh = bhp + (size_t)kt * 64 + l_half * 32;
        const char* sl = blp + (size_t)kt * 64 + l_half * 32;
        cp16(d + G_BH,      sh);
        cp16(d + G_BH + 16, sh + 16);
        cp16(d + G_BL,      sl);
        cp16(d + G_BL + 16, sl + 16);
        cp_commit();
    };
    auto stsA = [&](int buf) {
        uint32_t h[8], l[8];
        bfsplit2(pa[0].x, pa[0].y, h[0], l[0]); bfsplit2(pa[0].z, pa[0].w, h[1], l[1]);
        bfsplit2(pa[1].x, pa[1].y, h[2], l[2]); bfsplit2(pa[1].z, pa[1].w, h[3], l[3]);
        bfsplit2(pa[2].x, pa[2].y, h[4], l[4]); bfsplit2(pa[2].z, pa[2].w, h[5], l[5]);
        bfsplit2(pa[3].x, pa[3].y, h[6], l[6]); bfsplit2(pa[3].z, pa[3].w, h[7], l[7]);
        uint32_t d = a_sts + buf * G_STG;
        *(uint4*)(sm + (d - sb) + G_AH)      = *(uint4*)(h);
        *(uint4*)(sm + (d - sb) + G_AH + 16) = *(uint4*)(h + 4);
        *(uint4*)(sm + (d - sb) + G_AL)      = *(uint4*)(l);
        *(uint4*)(sm + (d - sb) + G_AL + 16) = *(uint4*)(l + 4);
    };

    // prologue
    ldgA(0); cpB(0, 0); stsA(0);
    cp_wait0();
    __syncthreads();

    for (int t = 0; t < nt; t++) {
        int cur = t & 1;
        if (t + 1 < nt) { ldgA(t + 1); cpB(t + 1, cur ^ 1); }
        uint32_t stage = sb + cur * G_STG;
        #pragma unroll
        for (int j = 0; j < 2; j++) {
            uint32_t a_h[4][4], a_l[4][4], b_h[4][2], b_l[4][2];
            #pragma unroll
            for (int mi = 0; mi < 4; mi++) {
                uint32_t ad = stage + ((a_lrow + mi * 16) * 20 + j * 8 + a_lcol) * 4;
                ldmx4(a_h[mi], ad + G_AH);
                ldmx4(a_l[mi], ad + G_AL);
            }
            #pragma unroll
            for (int ni = 0; ni < 4; ni++) {
                uint32_t bd = stage + ((b_lrow + ni * 8) * 20 + j * 8 + b_lcol) * 4;
                ldmx2(b_h[ni], bd + G_BH);
                ldmx2(b_l[ni], bd + G_BL);
            }
            #pragma unroll
            for (int mi = 0; mi < 4; mi++)
                #pragma unroll
                for (int ni = 0; ni < 4; ni++) {
                    mma16(acc[mi][ni], a_h[mi], b_l[ni]);
                    mma16(acc[mi][ni], a_l[mi], b_h[ni]);
                    mma16(acc[mi][ni], a_h[mi], b_h[ni]);
                }
        }
        if (t + 1 < nt) {
            stsA(cur ^ 1);
            cp_wait0();
            __syncthreads();
        }
    }

    // ---------------- epilogue (same layout as R7) ----------------
    int grp = lane >> 2, qid = lane & 3;
    #pragma unroll
    for (int mi = 0; mi < 4; mi++) {
        int r0 = row0 + m_base + mi * 16 + grp;
        int r1 = r0 + 8;
        bool v0 = r0 < M, v1 = r1 < M;
        size_t cr0 = 0, cr1 = 0;
        float w0 = 1.f, w1 = 1.f;
        if (v0) { cr0 = SCATTER ? (size_t)gidx[r0] : (size_t)r0; if (SCATTER) w0 = wrow[r0]; }
        if (v1) { cr1 = SCATTER ? (size_t)gidx[r1] : (size_t)r1; if (SCATTER) w1 = wrow[r1]; }
        #pragma unroll
        for (int ni = 0; ni < 4; ni++) {
            int cb = col0 + n_base + ni * 8 + qid * 2;
            #pragma unroll
            for (int half = 0; half < 2; half++) {
                bool valid = half ? v1 : v0;
                if (!valid) continue;
                int rr = half ? r1 : r0;
                size_t cr = half ? cr1 : cr0;
                float w = half ? w1 : w0;
                float e0 = acc[mi][ni][half * 2 + 0];
                float e1 = acc[mi][ni][half * 2 + 1];
                if (BIAS)  { e0 += bias[cb]; e1 += bias[cb + 1]; }
                if (CONDC) {
                    const float* cc = condc + (size_t)(rr >> 8) * Nn + cb;
                    e0 += cc[0]; e1 += cc[1];
                }
                if (GELU)  { e0 = gelu_f(e0); e1 = gelu_f(e1); }
                if (RESID) {
                    const float* rp = res + (size_t)rr * Nn + cb;
                    e0 += rp[0]; e1 += rp[1];
                }
                float* cp = C + cr * Nn + cb;
                if (SCATTER) {
                    float2 old = *(float2*)cp;
                    e0 = old.x + w * e0;
                    e1 = old.y + w * e1;
                }
                *(float2*)cp = make_float2(e0, e1);
            }
        }
    }
}

// ---------------- legacy mma.sync split GEMM (tiny condc only) ----------------
__global__ __launch_bounds__(256) void gemm_tc_plain(
    const float* __restrict__ A, const float* __restrict__ Bm, float* __restrict__ C,
    int M, int Nn, int K)
{
    int row0 = blockIdx.y * 128;
    if (row0 >= M) return;
    int col0 = blockIdx.x * 128;
    __shared__ uint32_t Ah[2][128][9];
    __shared__ uint32_t Al[2][128][9];
    __shared__ uint32_t Bh[2][8][132];
    __shared__ uint32_t Bl[2][8][132];
    int tid = threadIdx.x, lane = tid & 31, warp = tid >> 5;
    int grp = lane >> 2, qid = lane & 3;
    int m_base = (warp >> 2) * 64, n_base = (warp & 3) * 32;
    int a_r = tid >> 2, a_k4 = (tid & 3) * 4, a_kp = (tid & 3) * 2;
    int ar1 = row0 + a_r, ar2 = row0 + a_r + 64;
    bool av1 = ar1 < M, av2 = ar2 < M;
    int b_kp = tid >> 5, b_n4 = (tid & 31) * 4;
    float acc[4][4][4];
    #pragma unroll
    for (int i = 0; i < 4; i++)
        #pragma unroll
        for (int j = 0; j < 4; j++)
            #pragma unroll
            for (int q = 0; q < 4; q++) acc[i][j][q] = 0.f;
    int nt = K / 16;
    float4 ra0, ra1, rbE, rbO;
    ra0 = av1 ? *(const float4*)(A + (size_t)ar1 * K + a_k4) : make_float4(0,0,0,0);
    ra1 = av2 ? *(const float4*)(A + (size_t)ar2 * K + a_k4) : make_float4(0,0,0,0);
    rbE = *(const float4*)(Bm + (size_t)(2 * b_kp) * Nn + col0 + b_n4);
    rbO = *(const float4*)(Bm + (size_t)(2 * b_kp + 1) * Nn + col0 + b_n4);
    {
        uint32_t h0, l0, h1, l1;
        bfsplit2(ra0.x, ra0.y, h0, l0); bfsplit2(ra0.z, ra0.w, h1, l1);
        Ah[0][a_r][a_kp] = h0; Ah[0][a_r][a_kp+1] = h1; Al[0][a_r][a_kp] = l0; Al[0][a_r][a_kp+1] = l1;
        bfsplit2(ra1.x, ra1.y, h0, l0); bfsplit2(ra1.z, ra1.w, h1, l1);
        Ah[0][a_r+64][a_kp] = h0; Ah[0][a_r+64][a_kp+1] = h1; Al[0][a_r+64][a_kp] = l0; Al[0][a_r+64][a_kp+1] = l1;
        uint32_t bh4[4], bl4[4];
        bfsplit2(rbE.x, rbO.x, bh4[0], bl4[0]); bfsplit2(rbE.y, rbO.y, bh4[1], bl4[1]);
        bfsplit2(rbE.z, rbO.z, bh4[2], bl4[2]); bfsplit2(rbE.w, rbO.w, bh4[3], bl4[3]);
        *(uint4*)&Bh[0][b_kp][b_n4] = *(uint4*)bh4;
        *(uint4*)&Bl[0][b_kp][b_n4] = *(uint4*)bl4;
    }
    __syncthreads();
    for (int t = 0; t < nt; t++) {
        int cur = t & 1;
        if (t + 1 < nt) {
            int k0 = (t + 1) * 16;
            ra0 = av1 ? *(const float4*)(A + (size_t)ar1 * K + k0 + a_k4) : make_float4(0,0,0,0);
            ra1 = av2 ? *(const float4*)(A + (size_t)ar2 * K + k0 + a_k4) : make_float4(0,0,0,0);
            rbE = *(const float4*)(Bm + (size_t)(k0 + 2 * b_kp) * Nn + col0 + b_n4);
            rbO = *(const float4*)(Bm + (size_t)(k0 + 2 * b_kp + 1) * Nn + col0 + b_n4);
        }
        uint32_t a_h[4][4], a_l[4][4], b_h[4][2], b_l[4][2];
        #pragma unroll
        for (int mi = 0; mi < 4; mi++) {
            int rm = m_base + mi * 16 + grp;
            a_h[mi][0] = Ah[cur][rm][qid];         a_l[mi][0] = Al[cur][rm][qid];
            a_h[mi][1] = Ah[cur][rm + 8][qid];     a_l[mi][1] = Al[cur][rm + 8][qid];
            a_h[mi][2] = Ah[cur][rm][qid + 4];     a_l[mi][2] = Al[cur][rm][qid + 4];
            a_h[mi][3] = Ah[cur][rm + 8][qid + 4]; a_l[mi][3] = Al[cur][rm + 8][qid + 4];
        }
        #pragma unroll
        for (int ni = 0; ni < 4; ni++) {
            int cn = n_base + ni * 8 + grp;
            b_h[ni][0] = Bh[cur][qid][cn];     b_l[ni][0] = Bl[cur][qid][cn];
            b_h[ni][1] = Bh[cur][qid + 4][cn]; b_l[ni][1] = Bl[cur][qid + 4][cn];
        }
        #pragma unroll
        for (int mi = 0; mi < 4; mi++)
            #pragma unroll
            for (int ni = 0; ni < 4; ni++) {
                mma16(acc[mi][ni], a_h[mi], b_l[ni]);
                mma16(acc[mi][ni], a_l[mi], b_h[ni]);
                mma16(acc[mi][ni], a_h[mi], b_h[ni]);
            }
        if (t + 1 < nt) {
            int nxt = (t + 1) & 1;
            uint32_t h0, l0, h1, l1;
            bfsplit2(ra0.x, ra0.y, h0, l0); bfsplit2(ra0.z, ra0.w, h1, l1);
            Ah[nxt][a_r][a_kp] = h0; Ah[nxt][a_r][a_kp+1] = h1; Al[nxt][a_r][a_kp] = l0; Al[nxt][a_r][a_kp+1] = l1;
            bfsplit2(ra1.x, ra1.y, h0, l0); bfsplit2(ra1.z, ra1.w, h1, l1);
            Ah[nxt][a_r+64][a_kp] = h0; Ah[nxt][a_r+64][a_kp+1] = h1; Al[nxt][a_r+64][a_kp] = l0; Al[nxt][a_r+64][a_kp+1] = l1;
            uint32_t bh4[4], bl4[4];
            bfsplit2(rbE.x, rbO.x, bh4[0], bl4[0]); bfsplit2(rbE.y, rbO.y, bh4[1], bl4[1]);
            bfsplit2(rbE.z, rbO.z, bh4[2], bl4[2]); bfsplit2(rbE.w, rbO.w, bh4[3], bl4[3]);
            *(uint4*)&Bh[nxt][b_kp][b_n4] = *(uint4*)bh4;
            *(uint4*)&Bl[nxt][b_kp][b_n4] = *(uint4*)bl4;
            __syncthreads();
        }
    }
    #pragma unroll
    for (int mi = 0; mi < 4; mi++) {
        int r0 = row0 + m_base + mi * 16 + grp;
        int r1 = r0 + 8;
        #pragma unroll
        for (int ni = 0; ni < 4; ni++) {
            int cb = col0 + n_base + ni * 8 + qid * 2;
            if (r0 < M) *(float2*)(C + (size_t)r0 * Nn + cb) = make_float2(acc[mi][ni][0], acc[mi][ni][1]);
            if (r1 < M) *(float2*)(C + (size_t)r1 * Nn + cb) = make_float2(acc[mi][ni][2], acc[mi][ni][3]);
        }
    }
}

// ---------------- LayerNorm ----------------
__global__ __launch_bounds__(256) void ln_kernel(
    const float* __restrict__ x, const float* __restrict__ g,
    const float* __restrict__ bta, float* __restrict__ out)
{
    int t = blockIdx.x, tid = threadIdx.x;
    float4 v = ((const float4*)(x + (size_t)t * DIM))[tid];
    float s  = v.x + v.y + v.z + v.w;
    float sq = v.x * v.x + v.y * v.y + v.z * v.z + v.w * v.w;
    __shared__ float sh[8], sh2[8];
    float ws = warpsum(s), wq = warpsum(sq);
    if ((tid & 31) == 0) { sh[tid >> 5] = ws; sh2[tid >> 5] = wq; }
    __syncthreads();
    if (tid < 32) {
        float a  = (tid < 8) ? sh[tid]  : 0.f;
        float b2 = (tid < 8) ? sh2[tid] : 0.f;
        a = warpsum(a); b2 = warpsum(b2);
        if (tid == 0) { sh[0] = a; sh2[0] = b2; }
    }
    __syncthreads();
    float mu  = sh[0] * (1.0f / DIM);
    float var = sh2[0] * (1.0f / DIM) - mu * mu;
    float inv = rsqrtf(var + 1e-5f);
    float4 gg = ((const float4*)g)[tid], bb = ((const float4*)bta)[tid];
    float4 o;
    o.x = (v.x - mu) * inv * gg.x + bb.x;
    o.y = (v.y - mu) * inv * gg.y + bb.y;
    o.z = (v.z - mu) * inv * gg.z + bb.z;
    o.w = (v.w - mu) * inv * gg.w + bb.w;
    ((float4*)(out + (size_t)t * DIM))[tid] = o;
}

// ---------------- attention ----------------
__global__ __launch_bounds__(256) void attn_scores(
    const float* __restrict__ qkv, float* __restrict__ S)
{
    int kt = blockIdx.x, qt = blockIdx.y, bh = blockIdx.z;
    int b = bh >> 4, h = bh & 15;
    int q0 = qt * 64, k0 = kt * 64;
    __shared__ float Qs[64][65];
    __shared__ float Ks[64][65];
    int tid = threadIdx.x;
    #pragma unroll
    for (int i = 0; i < 4; i++) {
        int lin = tid + i * 256;
        int row = lin >> 4;
        int c4  = (lin & 15) * 4;
        float4 qv = *(const float4*)(qkv + (size_t)(b * NSEQ + q0 + row) * 3 * DIM + h * HDIM + c4);
        Qs[row][c4] = qv.x; Qs[row][c4 + 1] = qv.y; Qs[row][c4 + 2] = qv.z; Qs[row][c4 + 3] = qv.w;
        float4 kv = *(const float4*)(qkv + (size_t)(b * NSEQ + k0 + row) * 3 * DIM + DIM + h * HDIM + c4);
        Ks[row][c4] = kv.x; Ks[row][c4 + 1] = kv.y; Ks[row][c4 + 2] = kv.z; Ks[row][c4 + 3] = kv.w;
    }
    __syncthreads();
    int ty = tid >> 4, tx = tid & 15;
    float acc[4][4];
    #pragma unroll
    for (int i = 0; i < 4; i++)
        #pragma unroll
        for (int j = 0; j < 4; j++) acc[i][j] = 0.f;
    #pragma unroll 16
    for (int kk = 0; kk < 64; kk++) {
        float a[4], bv[4];
        #pragma unroll
        for (int i = 0; i < 4; i++) a[i]  = Qs[ty * 4 + i][kk];
        #pragma unroll
        for (int j = 0; j < 4; j++) bv[j] = Ks[tx * 4 + j][kk];
        #pragma unroll
        for (int i = 0; i < 4; i++)
            #pragma unroll
            for (int j = 0; j < 4; j++) acc[i][j] += a[i] * bv[j];
    }
    float* Sp = S + (size_t)bh * NSEQ * NSEQ;
    #pragma unroll
    for (int i = 0; i < 4; i++) {
        float4 v = make_float4(acc[i][0] * 0.125f, acc[i][1] * 0.125f,
                               acc[i][2] * 0.125f, acc[i][3] * 0.125f);
        *(float4*)(Sp + (size_t)(q0 + ty * 4 + i) * NSEQ + k0 + tx * 4) = v;
    }
}

__global__ __launch_bounds__(128) void softmax_kernel(float* __restrict__ S) {
    size_t row = (size_t)blockIdx.x * 4 + (threadIdx.x >> 5);
    int lane = threadIdx.x & 31;
    float* p = S + row * NSEQ;
    float v[8];
    float m = -1e30f;
    #pragma unroll
    for (int i = 0; i < 8; i++) { v[i] = p[lane + i * 32]; m = fmaxf(m, v[i]); }
    m = warpmax(m);
    float s = 0.f;
    #pragma unroll
    for (int i = 0; i < 8; i++) { v[i] = expf(v[i] - m); s += v[i]; }
    s = warpsum(s);
    float inv = 1.0f / s;
    #pragma unroll
    for (int i = 0; i < 8; i++) p[lane + i * 32] = v[i] * inv;
}

__global__ __launch_bounds__(256) void attn_av(
    const float* __restrict__ qkv, const float* __restrict__ S, float* __restrict__ o)
{
    int qt = blockIdx.x, bh = blockIdx.y;
    int b = bh >> 4, h = bh & 15;
    int q0 = qt * 64;
    __shared__ float Ps[64][17];
    __shared__ float Vs[16][64];
    int tid = threadIdx.x;
    int ty = tid >> 4, tx = tid & 15;
    float acc[4][4];
    #pragma unroll
    for (int i = 0; i < 4; i++)
        #pragma unroll
        for (int j = 0; j < 4; j++) acc[i][j] = 0.f;
    const float* Sp = S + (size_t)bh * NSEQ * NSEQ;
    for (int k0 = 0; k0 < NSEQ; k0 += 16) {
        {
            int row = tid >> 2, c = (tid & 3) * 4;
            float4 pv = *(const float4*)(Sp + (size_t)(q0 + row) * NSEQ + k0 + c);
            Ps[row][c] = pv.x; Ps[row][c + 1] = pv.y; Ps[row][c + 2] = pv.z; Ps[row][c + 3] = pv.w;
        }
        {
            int kr = tid >> 4, c = (tid & 15) * 4;
            float4 vv = *(const float4*)(qkv + (size_t)(b * NSEQ + k0 + kr) * 3 * DIM + 2 * DIM + h * HDIM + c);
            *(float4*)&Vs[kr][c] = vv;
        }
        __syncthreads();
        #pragma unroll
        for (int kk = 0; kk < 16; kk++) {
            float a[4], bv[4];
            #pragma unroll
            for (int i = 0; i < 4; i++) a[i]  = Ps[ty * 4 + i][kk];
            #pragma unroll
            for (int j = 0; j < 4; j++) bv[j] = Vs[kk][tx * 4 + j];
            #pragma unroll
            for (int i = 0; i < 4; i++)
                #pragma unroll
                for (int j = 0; j < 4; j++) acc[i][j] += a[i] * bv[j];
        }
        __syncthreads();
    }
    #pragma unroll
    for (int i = 0; i < 4; i++) {
        float4 v = make_float4(acc[i][0], acc[i][1], acc[i][2], acc[i][3]);
        *(float4*)(o + (size_t)(b * NSEQ + q0 + ty * 4 + i) * DIM + h * HDIM + tx * 4) = v;
    }
}

// ---------------- router ----------------
__global__ __launch_bounds__(128) void router_kernel(
    const float* __restrict__ gh, const float* __restrict__ W, const float* __restrict__ bias)
{
    int t = blockIdx.x;
    int wid = threadIdx.x >> 5, lane = threadIdx.x & 31;
    const float* row = gh + (size_t)t * RHC;
    float s = 0.f;
    for (int k = lane; k < RHC; k += 32) s += row[k] * W[k * NE + wid];
    s = warpsum(s);
    __shared__ float logits[NE];
    if (lane == 0) logits[wid] = s + bias[wid];
    __syncthreads();
    if (threadIdx.x == 0) {
        float l[NE], m = -1e30f;
        #pragma unroll
        for (int e = 0; e < NE; e++) { l[e] = logits[e]; m = fmaxf(m, l[e]); }
        float ssum = 0.f;
        #pragma unroll
        for (int e = 0; e < NE; e++) { l[e] = expf(l[e] - m); ssum += l[e]; }
        float p[NE];
        #pragma unroll
        for (int e = 0; e < NE; e++)
            p[e] = fminf(fmaxf(l[e] / ssum, 1e-9f), 1.0f - 1e-9f);
        int i1 = 0;
        #pragma unroll
        for (int e = 1; e < NE; e++) if (p[e] > p[i1]) i1 = e;
        int i2 = -1;
        #pragma unroll
        for (int e = 0; e < NE; e++) {
            if (e == i1) continue;
            if (i2 < 0 || p[e] > p[i2]) i2 = e;
        }
        float wsum = p[i1] + p[i2];
        int pos = atomicAdd(&g_cnt[i1], 1);
        g_idx[i1 * TT + pos] = t; g_wgt[i1 * TT + pos] = p[i1] / wsum;
        pos = atomicAdd(&g_cnt[i2], 1);
        g_idx[i2 * TT + pos] = t; g_wgt[i2 * TT + pos] = p[i2] / wsum;
    }
}

__global__ void zero_cnt_kernel() {
    if (threadIdx.x < NE) g_cnt[threadIdx.x] = 0;
}

__global__ __launch_bounds__(256) void copy_kernel(const float* __restrict__ a, float* __restrict__ b) {
    size_t i = (size_t)blockIdx.x * blockDim.x + threadIdx.x;
    ((float4*)b)[i] = ((const float4*)a)[i];
}

// ---------------- host launcher ----------------
static void* symaddr(const void* s) {
    void* p = nullptr;
    cudaGetSymbolAddress(&p, s);
    return p;
}

extern "C" void kernel_launch(void* const* d_in, const int* in_sizes, int n_in,
                              void* d_out, int out_size) {
    const float* x       = (const float*)d_in[0];
    const float* cond    = (const float*)d_in[1];
    const float* ln1_g   = (const float*)d_in[2];
    const float* ln1_b   = (const float*)d_in[3];
    const float* qkv_w   = (const float*)d_in[4];
    const float* proj_w  = (const float*)d_in[5];
    const float* proj_b  = (const float*)d_in[6];
    const float* ln2_g   = (const float*)d_in[7];
    const float* ln2_b   = (const float*)d_in[8];
    const float* r_fc1_w = (const float*)d_in[9];
    const float* r_fc1_b = (const float*)d_in[10];
    const float* r_fc2_w = (const float*)d_in[11];
    const float* r_fc2_b = (const float*)d_in[12];
    const float* e_w1    = (const float*)d_in[13];
    const float* e_b1    = (const float*)d_in[14];
    const float* e_w2    = (const float*)d_in[15];
    const float* e_b2    = (const float*)d_in[16];
    float* out = (float*)d_out;

    float* h1    = (float*)symaddr(g_h1);
    float* qkv   = (float*)symaddr(g_qkv);
    float* S     = (float*)symaddr(g_S);
    float* o     = (float*)symaddr(g_o);
    float* x1    = (float*)symaddr(g_x1);
    float* h2    = (float*)symaddr(g_h2);
    float* condc = (float*)symaddr(g_condc);
    float* gh    = (float*)symaddr(g_gh);
    float* hid   = (float*)symaddr(g_hid);
    int*   cnt   = (int*)symaddr(g_cnt);
    int*   idx   = (int*)symaddr(g_idx);
    float* wgt   = (float*)symaddr(g_wgt);
    __nv_bfloat16* wqkv_h = (__nv_bfloat16*)symaddr(g_wqkv_h);
    __nv_bfloat16* wqkv_l = (__nv_bfloat16*)symaddr(g_wqkv_l);
    __nv_bfloat16* wproj_h = (__nv_bfloat16*)symaddr(g_wproj_h);
    __nv_bfloat16* wproj_l = (__nv_bfloat16*)symaddr(g_wproj_l);
    __nv_bfloat16* wfc1_h = (__nv_bfloat16*)symaddr(g_wfc1_h);
    __nv_bfloat16* wfc1_l = (__nv_bfloat16*)symaddr(g_wfc1_l);
    __nv_bfloat16* we1_h = (__nv_bfloat16*)symaddr(g_we1_h);
    __nv_bfloat16* we1_l = (__nv_bfloat16*)symaddr(g_we1_l);
    __nv_bfloat16* we2_h = (__nv_bfloat16*)symaddr(g_we2_h);
    __nv_bfloat16* we2_l = (__nv_bfloat16*)symaddr(g_we2_l);

    cudaFuncSetAttribute(gemm_tc2<false,false,false,false,false,false>,
                         cudaFuncAttributeMaxDynamicSharedMemorySize, G_SMEM);
    cudaFuncSetAttribute(gemm_tc2<false,false,true,false,true,false>,
                         cudaFuncAttributeMaxDynamicSharedMemorySize, G_SMEM);
    cudaFuncSetAttribute(gemm_tc2<false,false,true,true,false,true>,
                         cudaFuncAttributeMaxDynamicSharedMemorySize, G_SMEM);
    cudaFuncSetAttribute(gemm_tc2<true,false,true,true,false,false>,
                         cudaFuncAttributeMaxDynamicSharedMemorySize, G_SMEM);
    cudaFuncSetAttribute(gemm_tc2<false,true,true,false,false,false>,
                         cudaFuncAttributeMaxDynamicSharedMemorySize, G_SMEM);

    zero_cnt_kernel<<<1, 32>>>();

    // pre-split weights (K-major bf16 hi/lo)
    wsplit_kernel<<<dim3(3 * DIM / 32, DIM / 32, 1), 256>>>(qkv_w, wqkv_h, wqkv_l, DIM, 3 * DIM, 3 * DIM, 0, 0);
    wsplit_kernel<<<dim3(DIM / 32, DIM / 32, 1), 256>>>(proj_w, wproj_h, wproj_l, DIM, DIM, DIM, 0, 0);
    wsplit_kernel<<<dim3(RHC / 32, DIM / 32, 1), 256>>>(r_fc1_w, wfc1_h, wfc1_l, DIM, RHC, RHC, 0, 0);
    wsplit_kernel<<<dim3(DFFC / 32, DIM / 32, NE), 256>>>(e_w1, we1_h, we1_l, DIM, DFFC, DFFC,
                                                          (size_t)DIM * DFFC, (size_t)DFFC * DIM);
    wsplit_kernel<<<dim3(DIM / 32, DFFC / 32, NE), 256>>>(e_w2, we2_h, we2_l, DFFC, DIM, DIM,
                                                          (size_t)DFFC * DIM, (size_t)DIM * DFFC);

    // LN1
    ln_kernel<<<TT, 256>>>(x, ln1_g, ln1_b, h1);

    // QKV = h1 @ qkv_w
    gemm_tc2<false,false,false,false,false,false>
        <<<dim3(3 * DIM / 128, TT / 128), 256, G_SMEM>>>(h1, wqkv_h, wqkv_l, qkv, TT, 3 * DIM, DIM,
            nullptr, nullptr, nullptr, nullptr, nullptr, nullptr);

    // attention
    attn_scores<<<dim3(4, 4, BB * NH), 256>>>(qkv, S);
    softmax_kernel<<<BB * NH * NSEQ / 4, 128>>>(S);
    attn_av<<<dim3(4, BB * NH), 256>>>(qkv, S, o);

    // x1 = x + o @ proj_w + proj_b
    gemm_tc2<false,false,true,false,true,false>
        <<<dim3(DIM / 128, TT / 128), 256, G_SMEM>>>(o, wproj_h, wproj_l, x1, TT, DIM, DIM,
            proj_b, x, nullptr, nullptr, nullptr, nullptr);

    // LN2
    ln_kernel<<<TT, 256>>>(x1, ln2_g, ln2_b, h2);

    // condc[b] = cond[b] @ r_fc1_w[D:, :]  (tiny; legacy kernel)
    gemm_tc_plain<<<dim3(RHC / 128, 1), 256>>>(cond, r_fc1_w + (size_t)DIM * RHC, condc, BB, RHC, CDIM);

    // gh = gelu(h2 @ r_fc1_w[:D] + condc[b] + b1)
    gemm_tc2<false,false,true,true,false,true>
        <<<dim3(RHC / 128, TT / 128), 256, G_SMEM>>>(h2, wfc1_h, wfc1_l, gh, TT, RHC, DIM,
            r_fc1_b, nullptr, condc, nullptr, nullptr, nullptr);

    // router
    router_kernel<<<TT, 128>>>(gh, r_fc2_w, r_fc2_b);

    // out = x1
    copy_kernel<<<TT * DIM / 4 / 256, 256>>>(x1, out);

    // experts
    for (int e = 0; e < NE; e++) {
        gemm_tc2<true,false,true,true,false,false>
            <<<dim3(DFFC / 128, TT / 128), 256, G_SMEM>>>(h2,
                we1_h + (size_t)e * DFFC * DIM, we1_l + (size_t)e * DFFC * DIM, hid,
                TT, DFFC, DIM, e_b1 + e * DFFC, nullptr, nullptr,
                idx + e * TT, nullptr, cnt + e);
        gemm_tc2<false,true,true,false,false,false>
            <<<dim3(DIM / 128, TT / 128), 256, G_SMEM>>>(hid,
                we2_h + (size_t)e * DIM * DFFC, we2_l + (size_t)e * DIM * DFFC, out,
                TT, DIM, DFFC, e_b2 + e * DIM, nullptr, nullptr,
                idx + e * TT, wgt + e * TT, cnt + e);
    }
}

// round 10
// speedup vs baseline: 2.9573x; 1.1268x over previous
#include <cuda_runtime.h>
#include <cuda_bf16.h>
#include <cuda_fp16.h>
#include <math.h>
#include <stdint.h>

// ---------------- problem constants ----------------
constexpr int BB   = 32;
constexpr int NSEQ = 256;
constexpr int DIM  = 1024;
constexpr int NH   = 16;
constexpr int HDIM = 64;
constexpr int CDIM = 1024;
constexpr int NE   = 4;
constexpr int DFFC = 4096;
constexpr int RHC  = 2048;
constexpr int TT   = BB * NSEQ;   // 8192 tokens

// ---------------- scratch (device globals; no allocation allowed) ----------------
__device__ float g_h1[TT * DIM];
__device__ float g_qkv[TT * 3 * DIM];
__device__ float g_S[(size_t)BB * NH * NSEQ * NSEQ];
__device__ float g_o[TT * DIM];
__device__ float g_x1[TT * DIM];
__device__ float g_h2[TT * DIM];
__device__ float g_condc[BB * RHC];
__device__ float g_gh[(size_t)TT * RHC];
__device__ float g_hid[(size_t)NE * TT * DFFC];    // per-expert hidden
__device__ float g_eout[(size_t)NE * TT * DIM];    // per-expert output (token-addressed)
__device__ int   g_cnt[NE];
__device__ int   g_idx[NE * TT];
__device__ int2   g_te[TT];
__device__ float2 g_tw[TT];

// pre-split K-major weights: [N][K] fp16 hi/lo
__device__ __half g_wqkv_h[(size_t)3 * DIM * DIM];
__device__ __half g_wqkv_l[(size_t)3 * DIM * DIM];
__device__ __half g_wproj_h[(size_t)DIM * DIM];
__device__ __half g_wproj_l[(size_t)DIM * DIM];
__device__ __half g_wfc1_h[(size_t)RHC * DIM];
__device__ __half g_wfc1_l[(size_t)RHC * DIM];
__device__ __half g_we1_h[(size_t)NE * DFFC * DIM];
__device__ __half g_we1_l[(size_t)NE * DFFC * DIM];
__device__ __half g_we2_h[(size_t)NE * DIM * DFFC];
__device__ __half g_we2_l[(size_t)NE * DIM * DFFC];

// ---------------- helpers ----------------
__device__ __forceinline__ float warpsum(float v) {
    #pragma unroll
    for (int o = 16; o; o >>= 1) v += __shfl_xor_sync(0xFFFFFFFFu, v, o);
    return v;
}
__device__ __forceinline__ float warpmax(float v) {
    #pragma unroll
    for (int o = 16; o; o >>= 1) v = fmaxf(v, __shfl_xor_sync(0xFFFFFFFFu, v, o));
    return v;
}
__device__ __forceinline__ float gelu_f(float x) {
    return 0.5f * x * (1.0f + erff(x * 0.70710678118654752f));
}
// fp16 hi/lo split (11+11 bits)
__device__ __forceinline__ void hsplit2(float x0, float x1, uint32_t& hi, uint32_t& lo) {
    __half2 h = __floats2half2_rn(x0, x1);
    float r0 = x0 - __half2float(__low2half(h));
    float r1 = x1 - __half2float(__high2half(h));
    __half2 l = __floats2half2_rn(r0, r1);
    hi = *reinterpret_cast<uint32_t*>(&h);
    lo = *reinterpret_cast<uint32_t*>(&l);
}
// bf16 split (kept for tiny condc kernel)
__device__ __forceinline__ void bfsplit2(float x0, float x1, uint32_t& hi, uint32_t& lo) {
    __nv_bfloat162 h = __floats2bfloat162_rn(x0, x1);
    float r0 = x0 - __bfloat162float(h.x);
    float r1 = x1 - __bfloat162float(h.y);
    __nv_bfloat162 l = __floats2bfloat162_rn(r0, r1);
    hi = *reinterpret_cast<uint32_t*>(&h);
    lo = *reinterpret_cast<uint32_t*>(&l);
}
__device__ __forceinline__ void mma16bf(float* c, const uint32_t* a, const uint32_t* b) {
    asm("mma.sync.aligned.m16n8k16.row.col.f32.bf16.bf16.f32 "
        "{%0,%1,%2,%3}, {%4,%5,%6,%7}, {%8,%9}, {%0,%1,%2,%3};"
        : "+f"(c[0]), "+f"(c[1]), "+f"(c[2]), "+f"(c[3])
        : "r"(a[0]), "r"(a[1]), "r"(a[2]), "r"(a[3]), "r"(b[0]), "r"(b[1]));
}
// fp16 inputs, fp32 accum
__device__ __forceinline__ void mma16f(float* c, const uint32_t* a, const uint32_t* b) {
    asm("mma.sync.aligned.m16n8k16.row.col.f32.f16.f16.f32 "
        "{%0,%1,%2,%3}, {%4,%5,%6,%7}, {%8,%9}, {%0,%1,%2,%3};"
        : "+f"(c[0]), "+f"(c[1]), "+f"(c[2]), "+f"(c[3])
        : "r"(a[0]), "r"(a[1]), "r"(a[2]), "r"(a[3]), "r"(b[0]), "r"(b[1]));
}
// fp16 inputs, fp16 accum (2 packed regs)
__device__ __forceinline__ void mma16h(uint32_t* c, const uint32_t* a, const uint32_t* b) {
    asm("mma.sync.aligned.m16n8k16.row.col.f16.f16.f16.f16 "
        "{%0,%1}, {%2,%3,%4,%5}, {%6,%7}, {%0,%1};"
        : "+r"(c[0]), "+r"(c[1])
        : "r"(a[0]), "r"(a[1]), "r"(a[2]), "r"(a[3]), "r"(b[0]), "r"(b[1]));
}
__device__ __forceinline__ void ldmx4(uint32_t* r, uint32_t a) {
    asm volatile("ldmatrix.sync.aligned.m8n8.x4.shared.b16 {%0,%1,%2,%3}, [%4];"
        : "=r"(r[0]), "=r"(r[1]), "=r"(r[2]), "=r"(r[3]) : "r"(a));
}
__device__ __forceinline__ void ldmx2(uint32_t* r, uint32_t a) {
    asm volatile("ldmatrix.sync.aligned.m8n8.x2.shared.b16 {%0,%1}, [%2];"
        : "=r"(r[0]), "=r"(r[1]) : "r"(a));
}
__device__ __forceinline__ uint32_t smem_u32(const void* p) {
    uint32_t a;
    asm("{ .reg .u64 t; cvta.to.shared.u64 t, %1; cvt.u32.u64 %0, t; }" : "=r"(a) : "l"(p));
    return a;
}
__device__ __forceinline__ void cp16(uint32_t dst, const void* src) {
    asm volatile("cp.async.ca.shared.global [%0], [%1], 16;" :: "r"(dst), "l"(src));
}
__device__ __forceinline__ void cp_commit() { asm volatile("cp.async.commit_group;" ::: "memory"); }
__device__ __forceinline__ void cp_wait0()  { asm volatile("cp.async.wait_group 0;" ::: "memory"); }

// ---------------- weight transpose + split: W[K,N] -> Wh/Wl[N,K] fp16 ----------------
__global__ __launch_bounds__(256) void wsplit_kernel(
    const float* __restrict__ W, __half* __restrict__ Wh, __half* __restrict__ Wl,
    int K, int Nn, int ld, size_t wz, size_t oz)
{
    __shared__ float ts[32][33];
    int z = blockIdx.z;
    const float* Wp = W + (size_t)z * wz;
    int n0 = blockIdx.x * 32, k0 = blockIdx.y * 32;
    int tx = threadIdx.x & 31, ty = threadIdx.x >> 5;
    #pragma unroll
    for (int i = 0; i < 4; i++)
        ts[ty + i * 8][tx] = Wp[(size_t)(k0 + ty + i * 8) * ld + n0 + tx];
    __syncthreads();
    #pragma unroll
    for (int i = 0; i < 4; i++) {
        int n = n0 + ty + i * 8, k = k0 + tx;
        float v = ts[tx][ty + i * 8];
        __half h = __float2half(v);
        __half l = __float2half(v - __half2float(h));
        Wh[(size_t)z * oz + (size_t)n * K + k] = h;
        Wl[(size_t)z * oz + (size_t)n * K + k] = l;
    }
}

// ---------------- fp16 3-term split GEMM (lo terms fp16-accum), K32 stages ----------
// C[M,Nn] = A[M,K](fp32) @ W(pre-split fp16 [Nn][K]); CTA 128x128, 8 warps 2m x 4n.
constexpr int G_AH = 0;
constexpr int G_AL = 10240;
constexpr int G_BH = 20480;
constexpr int G_BL = 30720;
constexpr int G_STG = 40960;
constexpr int G_SMEM = 2 * G_STG;     // 81920

// GATHER: A row = gidx[ez*TT + r] (compacted tile rows), C row = ez*czoff + r
// SCATTER: A row = r (plus azoff per-z base), C row = ez*czoff + gidx[ez*TT + r]; plain store
template<bool GATHER, bool SCATTER, bool BIAS, bool GELU, bool RESID, bool CONDC>
__global__ __launch_bounds__(256) void gemm_tc2(
    const float* __restrict__ A,
    const __half* __restrict__ Bh, const __half* __restrict__ Bl,
    float* __restrict__ C, int M, int Nn, int K,
    const float* __restrict__ bias, int biasz,
    const float* __restrict__ res, const float* __restrict__ condc,
    const int* __restrict__ gidx, const int* __restrict__ cntp,
    size_t wz, size_t azoff, int czoff)
{
    extern __shared__ char sm[];
    int ez = blockIdx.z;
    if (cntp) M = cntp[ez];
    int row0 = blockIdx.y * 128;
    if (row0 >= M) return;
    int col0 = blockIdx.x * 128;

    A  += (size_t)ez * azoff;
    Bh += (size_t)ez * wz;
    Bl += (size_t)ez * wz;
    const int* gz = (GATHER || SCATTER) ? (gidx + ez * TT) : nullptr;
    size_t crow_base = (size_t)ez * (size_t)czoff;

    uint32_t sb = smem_u32(sm);
    int tid = threadIdx.x, lane = tid & 31, warp = tid >> 5;
    int m_base = (warp >> 2) * 64, n_base = (warp & 3) * 32;

    // ---- loader mapping ----
    int l_row  = tid >> 1;
    int l_half = tid & 1;
    int gar = row0 + l_row;
    bool gav = gar < M;
    int garow = gav ? (GATHER ? gz[gar] : gar) : 0;
    const float* ap = A + (size_t)garow * K;
    const char* bhp = (const char*)(Bh + (size_t)(col0 + l_row) * K);
    const char* blp = (const char*)(Bl + (size_t)(col0 + l_row) * K);
    uint32_t a_sts = sb + (uint32_t)(l_row * 20 + l_half * 8) * 4;
    uint32_t b_sts = sb + (uint32_t)(l_row * 20 + l_half * 8) * 4;

    // ---- ldmatrix per-thread addresses ----
    uint32_t a_lrow = (uint32_t)(m_base + (lane & 7) + ((lane >> 3) & 1) * 8);
    uint32_t a_lcol = (uint32_t)((lane >> 4) * 4);
    int bl15 = lane & 15;
    uint32_t b_lrow = (uint32_t)(n_base + (bl15 & 7));
    uint32_t b_lcol = (uint32_t)(((bl15 >> 3) & 1) * 4);

    float acc[4][4][4];
    uint32_t accl[4][4][2];
    #pragma unroll
    for (int i = 0; i < 4; i++)
        #pragma unroll
        for (int j = 0; j < 4; j++) {
            #pragma unroll
            for (int q = 0; q < 4; q++) acc[i][j][q] = 0.f;
            accl[i][j][0] = 0u; accl[i][j][1] = 0u;
        }

    int nt = K >> 5;
    float4 pa[4];

    auto ldgA = [&](int kt) {
        const float* p = ap + kt * 32 + l_half * 16;
        if (gav) {
            pa[0] = *(const float4*)(p);
            pa[1] = *(const float4*)(p + 4);
            pa[2] = *(const float4*)(p + 8);
            pa[3] = *(const float4*)(p + 12);
        } else {
            pa[0] = pa[1] = pa[2] = pa[3] = make_float4(0.f, 0.f, 0.f, 0.f);
        }
    };
    auto cpB = [&](int kt, int buf) {
        uint32_t d = b_sts + buf * G_STG;
        const char* sh = bhp + (size_t)kt * 64 + l_half * 32;
        const char* sl = blp + (size_t)kt * 64 + l_half * 32;
        cp16(d + G_BH,      sh);
        cp16(d + G_BH + 16, sh + 16);
        cp16(d + G_BL,      sl);
        cp16(d + G_BL + 16, sl + 16);
        cp_commit();
    };
    auto stsA = [&](int buf) {
        uint32_t h[8], l[8];
        hsplit2(pa[0].x, pa[0].y, h[0], l[0]); hsplit2(pa[0].z, pa[0].w, h[1], l[1]);
        hsplit2(pa[1].x, pa[1].y, h[2], l[2]); hsplit2(pa[1].z, pa[1].w, h[3], l[3]);
        hsplit2(pa[2].x, pa[2].y, h[4], l[4]); hsplit2(pa[2].z, pa[2].w, h[5], l[5]);
        hsplit2(pa[3].x, pa[3].y, h[6], l[6]); hsplit2(pa[3].z, pa[3].w, h[7], l[7]);
        uint32_t d = a_sts + buf * G_STG;
        *(uint4*)(sm + (d - sb) + G_AH)      = *(uint4*)(h);
        *(uint4*)(sm + (d - sb) + G_AH + 16) = *(uint4*)(h + 4);
        *(uint4*)(sm + (d - sb) + G_AL)      = *(uint4*)(l);
        *(uint4*)(sm + (d - sb) + G_AL + 16) = *(uint4*)(l + 4);
    };

    // prologue
    ldgA(0); cpB(0, 0); stsA(0);
    cp_wait0();
    __syncthreads();

    for (int t = 0; t < nt; t++) {
        int cur = t & 1;
        if (t + 1 < nt) { ldgA(t + 1); cpB(t + 1, cur ^ 1); }
        uint32_t stage = sb + cur * G_STG;
        #pragma unroll
        for (int j = 0; j < 2; j++) {
            uint32_t a_h[4][4], a_l[4][4], b_h[4][2], b_l[4][2];
            #pragma unroll
            for (int mi = 0; mi < 4; mi++) {
                uint32_t ad = stage + ((a_lrow + mi * 16) * 20 + j * 8 + a_lcol) * 4;
                ldmx4(a_h[mi], ad + G_AH);
                ldmx4(a_l[mi], ad + G_AL);
            }
            #pragma unroll
            for (int ni = 0; ni < 4; ni++) {
                uint32_t bd = stage + ((b_lrow + ni * 8) * 20 + j * 8 + b_lcol) * 4;
                ldmx2(b_h[ni], bd + G_BH);
                ldmx2(b_l[ni], bd + G_BL);
            }
            #pragma unroll
            for (int mi = 0; mi < 4; mi++)
                #pragma unroll
                for (int ni = 0; ni < 4; ni++) {
                    mma16f(acc[mi][ni],  a_h[mi], b_h[ni]);   // hi*hi, fp32 accum
                    mma16h(accl[mi][ni], a_h[mi], b_l[ni]);   // hi*lo, fp16 accum
                    mma16h(accl[mi][ni], a_l[mi], b_h[ni]);   // lo*hi, fp16 accum
                }
        }
        if (t + 1 < nt) {
            stsA(cur ^ 1);
            cp_wait0();
            __syncthreads();
        }
    }

    // ---------------- epilogue ----------------
    int grp = lane >> 2, qid = lane & 3;
    #pragma unroll
    for (int mi = 0; mi < 4; mi++) {
        int r0 = row0 + m_base + mi * 16 + grp;
        int r1 = r0 + 8;
        bool v0 = r0 < M, v1 = r1 < M;
        size_t cr0 = 0, cr1 = 0;
        if (v0) cr0 = crow_base + (SCATTER ? (size_t)gz[r0] : (size_t)r0);
        if (v1) cr1 = crow_base + (SCATTER ? (size_t)gz[r1] : (size_t)r1);
        #pragma unroll
        for (int ni = 0; ni < 4; ni++) {
            int cb = col0 + n_base + ni * 8 + qid * 2;
            float2 f01 = __half22float2(*(__half2*)&accl[mi][ni][0]);
            float2 f23 = __half22float2(*(__half2*)&accl[mi][ni][1]);
            #pragma unroll
            for (int hf = 0; hf < 2; hf++) {
                bool valid = hf ? v1 : v0;
                if (!valid) continue;
                int rr = hf ? r1 : r0;
                size_t cr = hf ? cr1 : cr0;
                float e0 = acc[mi][ni][hf * 2 + 0] + (hf ? f23.x : f01.x);
                float e1 = acc[mi][ni][hf * 2 + 1] + (hf ? f23.y : f01.y);
                if (BIAS)  { e0 += bias[biasz * ez + cb]; e1 += bias[biasz * ez + cb + 1]; }
                if (CONDC) {
                    const float* cc = condc + (size_t)(rr >> 8) * Nn + cb;
                    e0 += cc[0]; e1 += cc[1];
                }
                if (GELU)  { e0 = gelu_f(e0); e1 = gelu_f(e1); }
                if (RESID) {
                    const float* rp = res + (size_t)rr * Nn + cb;
                    e0 += rp[0]; e1 += rp[1];
                }
                *(float2*)(C + cr * Nn + cb) = make_float2(e0, e1);
            }
        }
    }
}

// ---------------- legacy bf16-split GEMM (tiny condc only) ----------------
__global__ __launch_bounds__(256) void gemm_tc_plain(
    const float* __restrict__ A, const float* __restrict__ Bm, float* __restrict__ C,
    int M, int Nn, int K)
{
    int row0 = blockIdx.y * 128;
    if (row0 >= M) return;
    int col0 = blockIdx.x * 128;
    __shared__ uint32_t Ah[2][128][9];
    __shared__ uint32_t Al[2][128][9];
    __shared__ uint32_t Bh[2][8][132];
    __shared__ uint32_t Bl[2][8][132];
    int tid = threadIdx.x, lane = tid & 31, warp = tid >> 5;
    int grp = lane >> 2, qid = lane & 3;
    int m_base = (warp >> 2) * 64, n_base = (warp & 3) * 32;
    int a_r = tid >> 2, a_k4 = (tid & 3) * 4, a_kp = (tid & 3) * 2;
    int ar1 = row0 + a_r, ar2 = row0 + a_r + 64;
    bool av1 = ar1 < M, av2 = ar2 < M;
    int b_kp = tid >> 5, b_n4 = (tid & 31) * 4;
    float acc[4][4][4];
    #pragma unroll
    for (int i = 0; i < 4; i++)
        #pragma unroll
        for (int j = 0; j < 4; j++)
            #pragma unroll
            for (int q = 0; q < 4; q++) acc[i][j][q] = 0.f;
    int nt = K / 16;
    float4 ra0, ra1, rbE, rbO;
    ra0 = av1 ? *(const float4*)(A + (size_t)ar1 * K + a_k4) : make_float4(0,0,0,0);
    ra1 = av2 ? *(const float4*)(A + (size_t)ar2 * K + a_k4) : make_float4(0,0,0,0);
    rbE = *(const float4*)(Bm + (size_t)(2 * b_kp) * Nn + col0 + b_n4);
    rbO = *(const float4*)(Bm + (size_t)(2 * b_kp + 1) * Nn + col0 + b_n4);
    {
        uint32_t h0, l0, h1, l1;
        bfsplit2(ra0.x, ra0.y, h0, l0); bfsplit2(ra0.z, ra0.w, h1, l1);
        Ah[0][a_r][a_kp] = h0; Ah[0][a_r][a_kp+1] = h1; Al[0][a_r][a_kp] = l0; Al[0][a_r][a_kp+1] = l1;
        bfsplit2(ra1.x, ra1.y, h0, l0); bfsplit2(ra1.z, ra1.w, h1, l1);
        Ah[0][a_r+64][a_kp] = h0; Ah[0][a_r+64][a_kp+1] = h1; Al[0][a_r+64][a_kp] = l0; Al[0][a_r+64][a_kp+1] = l1;
        uint32_t bh4[4], bl4[4];
        bfsplit2(rbE.x, rbO.x, bh4[0], bl4[0]); bfsplit2(rbE.y, rbO.y, bh4[1], bl4[1]);
        bfsplit2(rbE.z, rbO.z, bh4[2], bl4[2]); bfsplit2(rbE.w, rbO.w, bh4[3], bl4[3]);
        *(uint4*)&Bh[0][b_kp][b_n4] = *(uint4*)bh4;
        *(uint4*)&Bl[0][b_kp][b_n4] = *(uint4*)bl4;
    }
    __syncthreads();
    for (int t = 0; t < nt; t++) {
        int cur = t & 1;
        if (t + 1 < nt) {
            int k0 = (t + 1) * 16;
            ra0 = av1 ? *(const float4*)(A + (size_t)ar1 * K + k0 + a_k4) : make_float4(0,0,0,0);
            ra1 = av2 ? *(const float4*)(A + (size_t)ar2 * K + k0 + a_k4) : make_float4(0,0,0,0);
            rbE = *(const float4*)(Bm + (size_t)(k0 + 2 * b_kp) * Nn + col0 + b_n4);
            rbO = *(const float4*)(Bm + (size_t)(k0 + 2 * b_kp + 1) * Nn + col0 + b_n4);
        }
        uint32_t a_h[4][4], a_l[4][4], b_h[4][2], b_l[4][2];
        #pragma unroll
        for (int mi = 0; mi < 4; mi++) {
            int rm = m_base + mi * 16 + grp;
            a_h[mi][0] = Ah[cur][rm][qid];         a_l[mi][0] = Al[cur][rm][qid];
            a_h[mi][1] = Ah[cur][rm + 8][qid];     a_l[mi][1] = Al[cur][rm + 8][qid];
            a_h[mi][2] = Ah[cur][rm][qid + 4];     a_l[mi][2] = Al[cur][rm][qid + 4];
            a_h[mi][3] = Ah[cur][rm + 8][qid + 4]; a_l[mi][3] = Al[cur][rm + 8][qid + 4];
        }
        #pragma unroll
        for (int ni = 0; ni < 4; ni++) {
            int cn = n_base + ni * 8 + grp;
            b_h[ni][0] = Bh[cur][qid][cn];     b_l[ni][0] = Bl[cur][qid][cn];
            b_h[ni][1] = Bh[cur][qid + 4][cn]; b_l[ni][1] = Bl[cur][qid + 4][cn];
        }
        #pragma unroll
        for (int mi = 0; mi < 4; mi++)
            #pragma unroll
            for (int ni = 0; ni < 4; ni++) {
                mma16bf(acc[mi][ni], a_h[mi], b_l[ni]);
                mma16bf(acc[mi][ni], a_l[mi], b_h[ni]);
                mma16bf(acc[mi][ni], a_h[mi], b_h[ni]);
            }
        if (t + 1 < nt) {
            int nxt = (t + 1) & 1;
            uint32_t h0, l0, h1, l1;
            bfsplit2(ra0.x, ra0.y, h0, l0); bfsplit2(ra0.z, ra0.w, h1, l1);
            Ah[nxt][a_r][a_kp] = h0; Ah[nxt][a_r][a_kp+1] = h1; Al[nxt][a_r][a_kp] = l0; Al[nxt][a_r][a_kp+1] = l1;
            bfsplit2(ra1.x, ra1.y, h0, l0); bfsplit2(ra1.z, ra1.w, h1, l1);
            Ah[nxt][a_r+64][a_kp] = h0; Ah[nxt][a_r+64][a_kp+1] = h1; Al[nxt][a_r+64][a_kp] = l0; Al[nxt][a_r+64][a_kp+1] = l1;
            uint32_t bh4[4], bl4[4];
            bfsplit2(rbE.x, rbO.x, bh4[0], bl4[0]); bfsplit2(rbE.y, rbO.y, bh4[1], bl4[1]);
            bfsplit2(rbE.z, rbO.z, bh4[2], bl4[2]); bfsplit2(rbE.w, rbO.w, bh4[3], bl4[3]);
            *(uint4*)&Bh[nxt][b_kp][b_n4] = *(uint4*)bh4;
            *(uint4*)&Bl[nxt][b_kp][b_n4] = *(uint4*)bl4;
            __syncthreads();
        }
    }
    #pragma unroll
    for (int mi = 0; mi < 4; mi++) {
        int r0 = row0 + m_base + mi * 16 + grp;
        int r1 = r0 + 8;
        #pragma unroll
        for (int ni = 0; ni < 4; ni++) {
            int cb = col0 + n_base + ni * 8 + qid * 2;
            if (r0 < M) *(float2*)(C + (size_t)r0 * Nn + cb) = make_float2(acc[mi][ni][0], acc[mi][ni][1]);
            if (r1 < M) *(float2*)(C + (size_t)r1 * Nn + cb) = make_float2(acc[mi][ni][2], acc[mi][ni][3]);
        }
    }
}

// ---------------- LayerNorm ----------------
__global__ __launch_bounds__(256) void ln_kernel(
    const float* __restrict__ x, const float* __restrict__ g,
    const float* __restrict__ bta, float* __restrict__ out)
{
    int t = blockIdx.x, tid = threadIdx.x;
    float4 v = ((const float4*)(x + (size_t)t * DIM))[tid];
    float s  = v.x + v.y + v.z + v.w;
    float sq = v.x * v.x + v.y * v.y + v.z * v.z + v.w * v.w;
    __shared__ float sh[8], sh2[8];
    float ws = warpsum(s), wq = warpsum(sq);
    if ((tid & 31) == 0) { sh[tid >> 5] = ws; sh2[tid >> 5] = wq; }
    __syncthreads();
    if (tid < 32) {
        float a  = (tid < 8) ? sh[tid]  : 0.f;
        float b2 = (tid < 8) ? sh2[tid] : 0.f;
        a = warpsum(a); b2 = warpsum(b2);
        if (tid == 0) { sh[0] = a; sh2[0] = b2; }
    }
    __syncthreads();
    float mu  = sh[0] * (1.0f / DIM);
    float var = sh2[0] * (1.0f / DIM) - mu * mu;
    float inv = rsqrtf(var + 1e-5f);
    float4 gg = ((const float4*)g)[tid], bb = ((const float4*)bta)[tid];
    float4 o;
    o.x = (v.x - mu) * inv * gg.x + bb.x;
    o.y = (v.y - mu) * inv * gg.y + bb.y;
    o.z = (v.z - mu) * inv * gg.z + bb.z;
    o.w = (v.w - mu) * inv * gg.w + bb.w;
    ((float4*)(out + (size_t)t * DIM))[tid] = o;
}

// ---------------- attention ----------------
__global__ __launch_bounds__(256) void attn_scores(
    const float* __restrict__ qkv, float* __restrict__ S)
{
    int kt = blockIdx.x, qt = blockIdx.y, bh = blockIdx.z;
    int b = bh >> 4, h = bh & 15;
    int q0 = qt * 64, k0 = kt * 64;
    __shared__ float Qs[64][65];
    __shared__ float Ks[64][65];
    int tid = threadIdx.x;
    #pragma unroll
    for (int i = 0; i < 4; i++) {
        int lin = tid + i * 256;
        int row = lin >> 4;
        int c4  = (lin & 15) * 4;
        float4 qv = *(const float4*)(qkv + (size_t)(b * NSEQ + q0 + row) * 3 * DIM + h * HDIM + c4);
        Qs[row][c4] = qv.x; Qs[row][c4 + 1] = qv.y; Qs[row][c4 + 2] = qv.z; Qs[row][c4 + 3] = qv.w;
        float4 kv = *(const float4*)(qkv + (size_t)(b * NSEQ + k0 + row) * 3 * DIM + DIM + h * HDIM + c4);
        Ks[row][c4] = kv.x; Ks[row][c4 + 1] = kv.y; Ks[row][c4 + 2] = kv.z; Ks[row][c4 + 3] = kv.w;
    }
    __syncthreads();
    int ty = tid >> 4, tx = tid & 15;
    float acc[4][4];
    #pragma unroll
    for (int i = 0; i < 4; i++)
        #pragma unroll
        for (int j = 0; j < 4; j++) acc[i][j] = 0.f;
    #pragma unroll 16
    for (int kk = 0; kk < 64; kk++) {
        float a[4], bv[4];
        #pragma unroll
        for (int i = 0; i < 4; i++) a[i]  = Qs[ty * 4 + i][kk];
        #pragma unroll
        for (int j = 0; j < 4; j++) bv[j] = Ks[tx * 4 + j][kk];
        #pragma unroll
        for (int i = 0; i < 4; i++)
            #pragma unroll
            for (int j = 0; j < 4; j++) acc[i][j] += a[i] * bv[j];
    }
    float* Sp = S + (size_t)bh * NSEQ * NSEQ;
    #pragma unroll
    for (int i = 0; i < 4; i++) {
        float4 v = make_float4(acc[i][0] * 0.125f, acc[i][1] * 0.125f,
                               acc[i][2] * 0.125f, acc[i][3] * 0.125f);
        *(float4*)(Sp + (size_t)(q0 + ty * 4 + i) * NSEQ + k0 + tx * 4) = v;
    }
}

__global__ __launch_bounds__(128) void softmax_kernel(float* __restrict__ S) {
    size_t row = (size_t)blockIdx.x * 4 + (threadIdx.x >> 5);
    int lane = threadIdx.x & 31;
    float* p = S + row * NSEQ;
    float v[8];
    float m = -1e30f;
    #pragma unroll
    for (int i = 0; i < 8; i++) { v[i] = p[lane + i * 32]; m = fmaxf(m, v[i]); }
    m = warpmax(m);
    float s = 0.f;
    #pragma unroll
    for (int i = 0; i < 8; i++) { v[i] = expf(v[i] - m); s += v[i]; }
    s = warpsum(s);
    float inv = 1.0f / s;
    #pragma unroll
    for (int i = 0; i < 8; i++) p[lane + i * 32] = v[i] * inv;
}

__global__ __launch_bounds__(256) void attn_av(
    const float* __restrict__ qkv, const float* __restrict__ S, float* __restrict__ o)
{
    int qt = blockIdx.x, bh = blockIdx.y;
    int b = bh >> 4, h = bh & 15;
    int q0 = qt * 64;
    __shared__ float Ps[64][17];
    __shared__ float Vs[16][64];
    int tid = threadIdx.x;
    int ty = tid >> 4, tx = tid & 15;
    float acc[4][4];
    #pragma unroll
    for (int i = 0; i < 4; i++)
        #pragma unroll
        for (int j = 0; j < 4; j++) acc[i][j] = 0.f;
    const float* Sp = S + (size_t)bh * NSEQ * NSEQ;
    for (int k0 = 0; k0 < NSEQ; k0 += 16) {
        {
            int row = tid >> 2, c = (tid & 3) * 4;
            float4 pv = *(const float4*)(Sp + (size_t)(q0 + row) * NSEQ + k0 + c);
            Ps[row][c] = pv.x; Ps[row][c + 1] = pv.y; Ps[row][c + 2] = pv.z; Ps[row][c + 3] = pv.w;
        }
        {
            int kr = tid >> 4, c = (tid & 15) * 4;
            float4 vv = *(const float4*)(qkv + (size_t)(b * NSEQ + k0 + kr) * 3 * DIM + 2 * DIM + h * HDIM + c);
            *(float4*)&Vs[kr][c] = vv;
        }
        __syncthreads();
        #pragma unroll
        for (int kk = 0; kk < 16; kk++) {
            float a[4], bv[4];
            #pragma unroll
            for (int i = 0; i < 4; i++) a[i]  = Ps[ty * 4 + i][kk];
            #pragma unroll
            for (int j = 0; j < 4; j++) bv[j] = Vs[kk][tx * 4 + j];
            #pragma unroll
            for (int i = 0; i < 4; i++)
                #pragma unroll
                for (int j = 0; j < 4; j++) acc[i][j] += a[i] * bv[j];
        }
        __syncthreads();
    }
    #pragma unroll
    for (int i = 0; i < 4; i++) {
        float4 v = make_float4(acc[i][0], acc[i][1], acc[i][2], acc[i][3]);
        *(float4*)(o + (size_t)(b * NSEQ + q0 + ty * 4 + i) * DIM + h * HDIM + tx * 4) = v;
    }
}

// ---------------- router: fc2 + softmax + top2; lists + per-token (e,w) ----------------
__global__ __launch_bounds__(128) void router_kernel(
    const float* __restrict__ gh, const float* __restrict__ W, const float* __restrict__ bias)
{
    int t = blockIdx.x;
    int wid = threadIdx.x >> 5, lane = threadIdx.x & 31;
    const float* row = gh + (size_t)t * RHC;
    float s = 0.f;
    for (int k = lane; k < RHC; k += 32) s += row[k] * W[k * NE + wid];
    s = warpsum(s);
    __shared__ float logits[NE];
    if (lane == 0) logits[wid] = s + bias[wid];
    __syncthreads();
    if (threadIdx.x == 0) {
        float l[NE], m = -1e30f;
        #pragma unroll
        for (int e = 0; e < NE; e++) { l[e] = logits[e]; m = fmaxf(m, l[e]); }
        float ssum = 0.f;
        #pragma unroll
        for (int e = 0; e < NE; e++) { l[e] = expf(l[e] - m); ssum += l[e]; }
        float p[NE];
        #pragma unroll
        for (int e = 0; e < NE; e++)
            p[e] = fminf(fmaxf(l[e] / ssum, 1e-9f), 1.0f - 1e-9f);
        int i1 = 0;
        #pragma unroll
        for (int e = 1; e < NE; e++) if (p[e] > p[i1]) i1 = e;
        int i2 = -1;
        #pragma unroll
        for (int e = 0; e < NE; e++) {
            if (e == i1) continue;
            if (i2 < 0 || p[e] > p[i2]) i2 = e;
        }
        float wsum = p[i1] + p[i2];
        int pos = atomicAdd(&g_cnt[i1], 1);
        g_idx[i1 * TT + pos] = t;
        pos = atomicAdd(&g_cnt[i2], 1);
        g_idx[i2 * TT + pos] = t;
        g_te[t] = make_int2(i1, i2);
        g_tw[t] = make_float2(p[i1] / wsum, p[i2] / wsum);
    }
}

__global__ void zero_cnt_kernel() {
    if (threadIdx.x < NE) g_cnt[threadIdx.x] = 0;
}

// out[t] = x1[t] + w1*eout[e1][t] + w2*eout[e2][t]
__global__ __launch_bounds__(256) void combine_kernel(
    const float* __restrict__ x1, const float* __restrict__ eout, float* __restrict__ out)
{
    int t = blockIdx.x, c = threadIdx.x;
    int2 e = g_te[t];
    float2 w = g_tw[t];
    float4 a  = ((const float4*)(x1 + (size_t)t * DIM))[c];
    float4 v1 = ((const float4*)(eout + ((size_t)e.x * TT + t) * DIM))[c];
    float4 v2 = ((const float4*)(eout + ((size_t)e.y * TT + t) * DIM))[c];
    float4 r;
    r.x = a.x + w.x * v1.x + w.y * v2.x;
    r.y = a.y + w.x * v1.y + w.y * v2.y;
    r.z = a.z + w.x * v1.z + w.y * v2.z;
    r.w = a.w + w.x * v1.w + w.y * v2.w;
    ((float4*)(out + (size_t)t * DIM))[c] = r;
}

// ---------------- host launcher ----------------
static void* symaddr(const void* s) {
    void* p = nullptr;
    cudaGetSymbolAddress(&p, s);
    return p;
}

extern "C" void kernel_launch(void* const* d_in, const int* in_sizes, int n_in,
                              void* d_out, int out_size) {
    const float* x       = (const float*)d_in[0];
    const float* cond    = (const float*)d_in[1];
    const float* ln1_g   = (const float*)d_in[2];
    const float* ln1_b   = (const float*)d_in[3];
    const float* qkv_w   = (const float*)d_in[4];
    const float* proj_w  = (const float*)d_in[5];
    const float* proj_b  = (const float*)d_in[6];
    const float* ln2_g   = (const float*)d_in[7];
    const float* ln2_b   = (const float*)d_in[8];
    const float* r_fc1_w = (const float*)d_in[9];
    const float* r_fc1_b = (const float*)d_in[10];
    const float* r_fc2_w = (const float*)d_in[11];
    const float* r_fc2_b = (const float*)d_in[12];
    const float* e_w1    = (const float*)d_in[13];
    const float* e_b1    = (const float*)d_in[14];
    const float* e_w2    = (const float*)d_in[15];
    const float* e_b2    = (const float*)d_in[16];
    float* out = (float*)d_out;

    float* h1    = (float*)symaddr(g_h1);
    float* qkv   = (float*)symaddr(g_qkv);
    float* S     = (float*)symaddr(g_S);
    float* o     = (float*)symaddr(g_o);
    float* x1    = (float*)symaddr(g_x1);
    float* h2    = (float*)symaddr(g_h2);
    float* condc = (float*)symaddr(g_condc);
    float* gh    = (float*)symaddr(g_gh);
    float* hid   = (float*)symaddr(g_hid);
    float* eout  = (float*)symaddr(g_eout);
    int*   cnt   = (int*)symaddr(g_cnt);
    int*   idx   = (int*)symaddr(g_idx);
    __half* wqkv_h  = (__half*)symaddr(g_wqkv_h);
    __half* wqkv_l  = (__half*)symaddr(g_wqkv_l);
    __half* wproj_h = (__half*)symaddr(g_wproj_h);
    __half* wproj_l = (__half*)symaddr(g_wproj_l);
    __half* wfc1_h  = (__half*)symaddr(g_wfc1_h);
    __half* wfc1_l  = (__half*)symaddr(g_wfc1_l);
    __half* we1_h   = (__half*)symaddr(g_we1_h);
    __half* we1_l   = (__half*)symaddr(g_we1_l);
    __half* we2_h   = (__half*)symaddr(g_we2_h);
    __half* we2_l   = (__half*)symaddr(g_we2_l);

    cudaFuncSetAttribute(gemm_tc2<false,false,false,false,false,false>,
                         cudaFuncAttributeMaxDynamicSharedMemorySize, G_SMEM);
    cudaFuncSetAttribute(gemm_tc2<false,false,true,false,true,false>,
                         cudaFuncAttributeMaxDynamicSharedMemorySize, G_SMEM);
    cudaFuncSetAttribute(gemm_tc2<false,false,true,true,false,true>,
                         cudaFuncAttributeMaxDynamicSharedMemorySize, G_SMEM);
    cudaFuncSetAttribute(gemm_tc2<true,false,true,true,false,false>,
                         cudaFuncAttributeMaxDynamicSharedMemorySize, G_SMEM);
    cudaFuncSetAttribute(gemm_tc2<false,true,true,false,false,false>,
                         cudaFuncAttributeMaxDynamicSharedMemorySize, G_SMEM);

    zero_cnt_kernel<<<1, 32>>>();

    // pre-split weights (K-major fp16 hi/lo)
    wsplit_kernel<<<dim3(3 * DIM / 32, DIM / 32, 1), 256>>>(qkv_w, wqkv_h, wqkv_l, DIM, 3 * DIM, 3 * DIM, 0, 0);
    wsplit_kernel<<<dim3(DIM / 32, DIM / 32, 1), 256>>>(proj_w, wproj_h, wproj_l, DIM, DIM, DIM, 0, 0);
    wsplit_kernel<<<dim3(RHC / 32, DIM / 32, 1), 256>>>(r_fc1_w, wfc1_h, wfc1_l, DIM, RHC, RHC, 0, 0);
    wsplit_kernel<<<dim3(DFFC / 32, DIM / 32, NE), 256>>>(e_w1, we1_h, we1_l, DIM, DFFC, DFFC,
                                                          (size_t)DIM * DFFC, (size_t)DFFC * DIM);
    wsplit_kernel<<<dim3(DIM / 32, DFFC / 32, NE), 256>>>(e_w2, we2_h, we2_l, DFFC, DIM, DIM,
                                                          (size_t)DFFC * DIM, (size_t)DIM * DFFC);

    // LN1
    ln_kernel<<<TT, 256>>>(x, ln1_g, ln1_b, h1);

    // QKV = h1 @ qkv_w
    gemm_tc2<false,false,false,false,false,false>
        <<<dim3(3 * DIM / 128, TT / 128, 1), 256, G_SMEM>>>(h1, wqkv_h, wqkv_l, qkv, TT, 3 * DIM, DIM,
            nullptr, 0, nullptr, nullptr, nullptr, nullptr, 0, 0, 0);

    // attention
    attn_scores<<<dim3(4, 4, BB * NH), 256>>>(qkv, S);
    softmax_kernel<<<BB * NH * NSEQ / 4, 128>>>(S);
    attn_av<<<dim3(4, BB * NH), 256>>>(qkv, S, o);

    // x1 = x + o @ proj_w + proj_b
    gemm_tc2<false,false,true,false,true,false>
        <<<dim3(DIM / 128, TT / 128, 1), 256, G_SMEM>>>(o, wproj_h, wproj_l, x1, TT, DIM, DIM,
            proj_b, 0, x, nullptr, nullptr, nullptr, 0, 0, 0);

    // LN2
    ln_kernel<<<TT, 256>>>(x1, ln2_g, ln2_b, h2);

    // condc[b] = cond[b] @ r_fc1_w[D:, :]  (tiny; legacy bf16 kernel)
    gemm_tc_plain<<<dim3(RHC / 128, 1), 256>>>(cond, r_fc1_w + (size_t)DIM * RHC, condc, BB, RHC, CDIM);

    // gh = gelu(h2 @ r_fc1_w[:D] + condc[b] + b1)
    gemm_tc2<false,false,true,true,false,true>
        <<<dim3(RHC / 128, TT / 128, 1), 256, G_SMEM>>>(h2, wfc1_h, wfc1_l, gh, TT, RHC, DIM,
            r_fc1_b, 0, nullptr, condc, nullptr, nullptr, 0, 0, 0);

    // router: logits, top2, per-expert lists + per-token (e,w)
    router_kernel<<<TT, 128>>>(gh, r_fc2_w, r_fc2_b);

    // experts, merged across NE via blockIdx.z:
    // hid[ez][r] = gelu(h2[idx[ez][r]] @ w1[ez] + b1[ez])
    gemm_tc2<true,false,true,true,false,false>
        <<<dim3(DFFC / 128, TT / 128, NE), 256, G_SMEM>>>(h2, we1_h, we1_l, hid,
            TT, DFFC, DIM, e_b1, DFFC, nullptr, nullptr,
            idx, cnt, (size_t)DFFC * DIM, 0, TT);
    // eout[ez][idx[ez][r]] = hid[ez][r] @ w2[ez] + b2[ez]
    gemm_tc2<false,true,true,false,false,false>
        <<<dim3(DIM / 128, TT / 128, NE), 256, G_SMEM>>>(hid, we2_h, we2_l, eout,
            TT, DIM, DFFC, e_b2, DIM, nullptr, nullptr,
            idx, cnt, (size_t)DIM * DFFC, (size_t)TT * DFFC, TT);

    // out = x1 + w1*eout[e1] + w2*eout[e2]
    combine_kernel<<<TT, 256>>>(x1, eout, out);
}

// round 11
// speedup vs baseline: 3.4419x; 1.1639x over previous
#include <cuda_runtime.h>
#include <cuda_bf16.h>
#include <cuda_fp16.h>
#include <math.h>
#include <stdint.h>

// ---------------- problem constants ----------------
constexpr int BB   = 32;
constexpr int NSEQ = 256;
constexpr int DIM  = 1024;
constexpr int NH   = 16;
constexpr int HDIM = 64;
constexpr int CDIM = 1024;
constexpr int NE   = 4;
constexpr int DFFC = 4096;
constexpr int RHC  = 2048;
constexpr int TT   = BB * NSEQ;   // 8192 tokens

// ---------------- scratch (device globals; no allocation allowed) ----------------
__device__ float g_h1[TT * DIM];
__device__ float g_qkv[TT * 3 * DIM];
__device__ float g_S[(size_t)BB * NH * NSEQ * NSEQ];
__device__ float g_o[TT * DIM];
__device__ float g_x1[TT * DIM];
__device__ float g_h2[TT * DIM];
__device__ float g_condc[BB * RHC];
__device__ float g_gh[(size_t)TT * RHC];
__device__ float g_hid[(size_t)NE * TT * DFFC];    // per-expert hidden
__device__ float g_eout[(size_t)NE * TT * DIM];    // per-expert output (token-addressed)
__device__ int   g_cnt[NE];
__device__ int   g_idx[NE * TT];
__device__ int2   g_te[TT];
__device__ float2 g_tw[TT];

// pre-split K-major weights: [N][K] fp16 hi/lo (experts: hi only)
__device__ __half g_wqkv_h[(size_t)3 * DIM * DIM];
__device__ __half g_wqkv_l[(size_t)3 * DIM * DIM];
__device__ __half g_wproj_h[(size_t)DIM * DIM];
__device__ __half g_wproj_l[(size_t)DIM * DIM];
__device__ __half g_wfc1_h[(size_t)RHC * DIM];
__device__ __half g_wfc1_l[(size_t)RHC * DIM];
__device__ __half g_we1_h[(size_t)NE * DFFC * DIM];
__device__ __half g_we2_h[(size_t)NE * DIM * DFFC];

// ---------------- helpers ----------------
__device__ __forceinline__ float warpsum(float v) {
    #pragma unroll
    for (int o = 16; o; o >>= 1) v += __shfl_xor_sync(0xFFFFFFFFu, v, o);
    return v;
}
__device__ __forceinline__ float warpmax(float v) {
    #pragma unroll
    for (int o = 16; o; o >>= 1) v = fmaxf(v, __shfl_xor_sync(0xFFFFFFFFu, v, o));
    return v;
}
__device__ __forceinline__ float gelu_f(float x) {
    return 0.5f * x * (1.0f + erff(x * 0.70710678118654752f));
}
// fp16 hi/lo split (11+11 bits)
__device__ __forceinline__ void hsplit2(float x0, float x1, uint32_t& hi, uint32_t& lo) {
    __half2 h = __floats2half2_rn(x0, x1);
    float r0 = x0 - __half2float(__low2half(h));
    float r1 = x1 - __half2float(__high2half(h));
    __half2 l = __floats2half2_rn(r0, r1);
    hi = *reinterpret_cast<uint32_t*>(&h);
    lo = *reinterpret_cast<uint32_t*>(&l);
}
// bf16 split (tiny condc kernel)
__device__ __forceinline__ void bfsplit2(float x0, float x1, uint32_t& hi, uint32_t& lo) {
    __nv_bfloat162 h = __floats2bfloat162_rn(x0, x1);
    float r0 = x0 - __bfloat162float(h.x);
    float r1 = x1 - __bfloat162float(h.y);
    __nv_bfloat162 l = __floats2bfloat162_rn(r0, r1);
    hi = *reinterpret_cast<uint32_t*>(&h);
    lo = *reinterpret_cast<uint32_t*>(&l);
}
__device__ __forceinline__ void mma16bf(float* c, const uint32_t* a, const uint32_t* b) {
    asm("mma.sync.aligned.m16n8k16.row.col.f32.bf16.bf16.f32 "
        "{%0,%1,%2,%3}, {%4,%5,%6,%7}, {%8,%9}, {%0,%1,%2,%3};"
        : "+f"(c[0]), "+f"(c[1]), "+f"(c[2]), "+f"(c[3])
        : "r"(a[0]), "r"(a[1]), "r"(a[2]), "r"(a[3]), "r"(b[0]), "r"(b[1]));
}
__device__ __forceinline__ void mma16f(float* c, const uint32_t* a, const uint32_t* b) {
    asm("mma.sync.aligned.m16n8k16.row.col.f32.f16.f16.f32 "
        "{%0,%1,%2,%3}, {%4,%5,%6,%7}, {%8,%9}, {%0,%1,%2,%3};"
        : "+f"(c[0]), "+f"(c[1]), "+f"(c[2]), "+f"(c[3])
        : "r"(a[0]), "r"(a[1]), "r"(a[2]), "r"(a[3]), "r"(b[0]), "r"(b[1]));
}
__device__ __forceinline__ void mma16h(uint32_t* c, const uint32_t* a, const uint32_t* b) {
    asm("mma.sync.aligned.m16n8k16.row.col.f16.f16.f16.f16 "
        "{%0,%1}, {%2,%3,%4,%5}, {%6,%7}, {%0,%1};"
        : "+r"(c[0]), "+r"(c[1])
        : "r"(a[0]), "r"(a[1]), "r"(a[2]), "r"(a[3]), "r"(b[0]), "r"(b[1]));
}
__device__ __forceinline__ void ldmx4(uint32_t* r, uint32_t a) {
    asm volatile("ldmatrix.sync.aligned.m8n8.x4.shared.b16 {%0,%1,%2,%3}, [%4];"
        : "=r"(r[0]), "=r"(r[1]), "=r"(r[2]), "=r"(r[3]) : "r"(a));
}
__device__ __forceinline__ void ldmx2(uint32_t* r, uint32_t a) {
    asm volatile("ldmatrix.sync.aligned.m8n8.x2.shared.b16 {%0,%1}, [%2];"
        : "=r"(r[0]), "=r"(r[1]) : "r"(a));
}
__device__ __forceinline__ uint32_t smem_u32(const void* p) {
    uint32_t a;
    asm("{ .reg .u64 t; cvta.to.shared.u64 t, %1; cvt.u32.u64 %0, t; }" : "=r"(a) : "l"(p));
    return a;
}
__device__ __forceinline__ void cp16(uint32_t dst, const void* src) {
    asm volatile("cp.async.ca.shared.global [%0], [%1], 16;" :: "r"(dst), "l"(src));
}
__device__ __forceinline__ void cp_commit() { asm volatile("cp.async.commit_group;" ::: "memory"); }
__device__ __forceinline__ void cp_wait0()  { asm volatile("cp.async.wait_group 0;" ::: "memory"); }

// ---------------- weight transpose + split: W[K,N] -> Wh(/Wl)[N,K] fp16 ----------------
__global__ __launch_bounds__(256) void wsplit_kernel(
    const float* __restrict__ W, __half* __restrict__ Wh, __half* __restrict__ Wl,
    int K, int Nn, int ld, size_t wz, size_t oz)
{
    __shared__ float ts[32][33];
    int z = blockIdx.z;
    const float* Wp = W + (size_t)z * wz;
    int n0 = blockIdx.x * 32, k0 = blockIdx.y * 32;
    int tx = threadIdx.x & 31, ty = threadIdx.x >> 5;
    #pragma unroll
    for (int i = 0; i < 4; i++)
        ts[ty + i * 8][tx] = Wp[(size_t)(k0 + ty + i * 8) * ld + n0 + tx];
    __syncthreads();
    #pragma unroll
    for (int i = 0; i < 4; i++) {
        int n = n0 + ty + i * 8, k = k0 + tx;
        float v = ts[tx][ty + i * 8];
        __half h = __float2half(v);
        Wh[(size_t)z * oz + (size_t)n * K + k] = h;
        if (Wl) Wl[(size_t)z * oz + (size_t)n * K + k] = __float2half(v - __half2float(h));
    }
}

// ---------------- fp16 split GEMM (TERMS=3: AhBh+AhBl+AlBh; TERMS=2: AhBh+AlBh) ------
// C[M,Nn] = A[M,K](fp32) @ W(pre-split fp16 [Nn][K]); CTA 128x128, 8 warps 2m x 4n.
constexpr int G_AH = 0;
constexpr int G_AL = 10240;
constexpr int G_BH = 20480;
constexpr int G_BL = 30720;
constexpr int G_STG = 40960;
constexpr int G_SMEM = 2 * G_STG;     // 81920

template<int TERMS, bool GATHER, bool SCATTER, bool BIAS, bool GELU, bool RESID, bool CONDC>
__global__ __launch_bounds__(256) void gemm_tc2(
    const float* __restrict__ A,
    const __half* __restrict__ Bh, const __half* __restrict__ Bl,
    float* __restrict__ C, int M, int Nn, int K,
    const float* __restrict__ bias, int biasz,
    const float* __restrict__ res, const float* __restrict__ condc,
    const int* __restrict__ gidx, const int* __restrict__ cntp,
    size_t wz, size_t azoff, int czoff)
{
    extern __shared__ char sm[];
    int ez = blockIdx.z;
    if (cntp) M = cntp[ez];
    int row0 = blockIdx.y * 128;
    if (row0 >= M) return;
    int col0 = blockIdx.x * 128;

    A  += (size_t)ez * azoff;
    Bh += (size_t)ez * wz;
    if (TERMS == 3) Bl += (size_t)ez * wz;
    const int* gz = (GATHER || SCATTER) ? (gidx + ez * TT) : nullptr;
    size_t crow_base = (size_t)ez * (size_t)czoff;

    uint32_t sb = smem_u32(sm);
    int tid = threadIdx.x, lane = tid & 31, warp = tid >> 5;
    int m_base = (warp >> 2) * 64, n_base = (warp & 3) * 32;

    // ---- loader mapping ----
    int l_row  = tid >> 1;
    int l_half = tid & 1;
    int gar = row0 + l_row;
    bool gav = gar < M;
    int garow = gav ? (GATHER ? gz[gar] : gar) : 0;
    const float* ap = A + (size_t)garow * K;
    const char* bhp = (const char*)(Bh + (size_t)(col0 + l_row) * K);
    const char* blp = (TERMS == 3) ? (const char*)(Bl + (size_t)(col0 + l_row) * K) : nullptr;
    uint32_t a_sts = sb + (uint32_t)(l_row * 20 + l_half * 8) * 4;
    uint32_t b_sts = sb + (uint32_t)(l_row * 20 + l_half * 8) * 4;

    // ---- ldmatrix per-thread addresses ----
    uint32_t a_lrow = (uint32_t)(m_base + (lane & 7) + ((lane >> 3) & 1) * 8);
    uint32_t a_lcol = (uint32_t)((lane >> 4) * 4);
    int bl15 = lane & 15;
    uint32_t b_lrow = (uint32_t)(n_base + (bl15 & 7));
    uint32_t b_lcol = (uint32_t)(((bl15 >> 3) & 1) * 4);

    float acc[4][4][4];
    uint32_t accl[4][4][2];
    #pragma unroll
    for (int i = 0; i < 4; i++)
        #pragma unroll
        for (int j = 0; j < 4; j++) {
            #pragma unroll
            for (int q = 0; q < 4; q++) acc[i][j][q] = 0.f;
            accl[i][j][0] = 0u; accl[i][j][1] = 0u;
        }

    int nt = K >> 5;
    float4 pa[4];

    auto ldgA = [&](int kt) {
        const float* p = ap + kt * 32 + l_half * 16;
        if (gav) {
            pa[0] = *(const float4*)(p);
            pa[1] = *(const float4*)(p + 4);
            pa[2] = *(const float4*)(p + 8);
            pa[3] = *(const float4*)(p + 12);
        } else {
            pa[0] = pa[1] = pa[2] = pa[3] = make_float4(0.f, 0.f, 0.f, 0.f);
        }
    };
    auto cpB = [&](int kt, int buf) {
        uint32_t d = b_sts + buf * G_STG;
        const char* sh = bhp + (size_t)kt * 64 + l_half * 32;
        cp16(d + G_BH,      sh);
        cp16(d + G_BH + 16, sh + 16);
        if (TERMS == 3) {
            const char* sl = blp + (size_t)kt * 64 + l_half * 32;
            cp16(d + G_BL,      sl);
            cp16(d + G_BL + 16, sl + 16);
        }
        cp_commit();
    };
    auto stsA = [&](int buf) {
        uint32_t h[8], l[8];
        hsplit2(pa[0].x, pa[0].y, h[0], l[0]); hsplit2(pa[0].z, pa[0].w, h[1], l[1]);
        hsplit2(pa[1].x, pa[1].y, h[2], l[2]); hsplit2(pa[1].z, pa[1].w, h[3], l[3]);
        hsplit2(pa[2].x, pa[2].y, h[4], l[4]); hsplit2(pa[2].z, pa[2].w, h[5], l[5]);
        hsplit2(pa[3].x, pa[3].y, h[6], l[6]); hsplit2(pa[3].z, pa[3].w, h[7], l[7]);
        uint32_t d = a_sts + buf * G_STG;
        *(uint4*)(sm + (d - sb) + G_AH)      = *(uint4*)(h);
        *(uint4*)(sm + (d - sb) + G_AH + 16) = *(uint4*)(h + 4);
        *(uint4*)(sm + (d - sb) + G_AL)      = *(uint4*)(l);
        *(uint4*)(sm + (d - sb) + G_AL + 16) = *(uint4*)(l + 4);
    };

    // prologue
    ldgA(0); cpB(0, 0); stsA(0);
    cp_wait0();
    __syncthreads();

    for (int t = 0; t < nt; t++) {
        int cur = t & 1;
        if (t + 1 < nt) { ldgA(t + 1); cpB(t + 1, cur ^ 1); }
        uint32_t stage = sb + cur * G_STG;
        #pragma unroll
        for (int j = 0; j < 2; j++) {
            uint32_t a_h[4][4], a_l[4][4], b_h[4][2], b_l[4][2];
            #pragma unroll
            for (int mi = 0; mi < 4; mi++) {
                uint32_t ad = stage + ((a_lrow + mi * 16) * 20 + j * 8 + a_lcol) * 4;
                ldmx4(a_h[mi], ad + G_AH);
                ldmx4(a_l[mi], ad + G_AL);
            }
            #pragma unroll
            for (int ni = 0; ni < 4; ni++) {
                uint32_t bd = stage + ((b_lrow + ni * 8) * 20 + j * 8 + b_lcol) * 4;
                ldmx2(b_h[ni], bd + G_BH);
                if (TERMS == 3) ldmx2(b_l[ni], bd + G_BL);
            }
            #pragma unroll
            for (int mi = 0; mi < 4; mi++)
                #pragma unroll
                for (int ni = 0; ni < 4; ni++) {
                    mma16f(acc[mi][ni],  a_h[mi], b_h[ni]);       // hi*hi, fp32 accum
                    mma16h(accl[mi][ni], a_l[mi], b_h[ni]);       // lo*hi, fp16 accum
                    if (TERMS == 3)
                        mma16h(accl[mi][ni], a_h[mi], b_l[ni]);   // hi*lo, fp16 accum
                }
        }
        if (t + 1 < nt) {
            stsA(cur ^ 1);
            cp_wait0();
            __syncthreads();
        }
    }

    // ---------------- epilogue ----------------
    int grp = lane >> 2, qid = lane & 3;
    #pragma unroll
    for (int mi = 0; mi < 4; mi++) {
        int r0 = row0 + m_base + mi * 16 + grp;
        int r1 = r0 + 8;
        bool v0 = r0 < M, v1 = r1 < M;
        size_t cr0 = 0, cr1 = 0;
        if (v0) cr0 = crow_base + (SCATTER ? (size_t)gz[r0] : (size_t)r0);
        if (v1) cr1 = crow_base + (SCATTER ? (size_t)gz[r1] : (size_t)r1);
        #pragma unroll
        for (int ni = 0; ni < 4; ni++) {
            int cb = col0 + n_base + ni * 8 + qid * 2;
            float2 f01 = __half22float2(*(__half2*)&accl[mi][ni][0]);
            float2 f23 = __half22float2(*(__half2*)&accl[mi][ni][1]);
            #pragma unroll
            for (int hf = 0; hf < 2; hf++) {
                bool valid = hf ? v1 : v0;
                if (!valid) continue;
                int rr = hf ? r1 : r0;
                size_t cr = hf ? cr1 : cr0;
                float e0 = acc[mi][ni][hf * 2 + 0] + (hf ? f23.x : f01.x);
                float e1 = acc[mi][ni][hf * 2 + 1] + (hf ? f23.y : f01.y);
                if (BIAS)  { e0 += bias[biasz * ez + cb]; e1 += bias[biasz * ez + cb + 1]; }
                if (CONDC) {
                    const float* cc = condc + (size_t)(rr >> 8) * Nn + cb;
                    e0 += cc[0]; e1 += cc[1];
                }
                if (GELU)  { e0 = gelu_f(e0); e1 = gelu_f(e1); }
                if (RESID) {
                    const float* rp = res + (size_t)rr * Nn + cb;
                    e0 += rp[0]; e1 += rp[1];
                }
                *(float2*)(C + cr * Nn + cb) = make_float2(e0, e1);
            }
        }
    }
}

// ---------------- legacy bf16-split GEMM (tiny condc only) ----------------
__global__ __launch_bounds__(256) void gemm_tc_plain(
    const float* __restrict__ A, const float* __restrict__ Bm, float* __restrict__ C,
    int M, int Nn, int K)
{
    int row0 = blockIdx.y * 128;
    if (row0 >= M) return;
    int col0 = blockIdx.x * 128;
    __shared__ uint32_t Ah[2][128][9];
    __shared__ uint32_t Al[2][128][9];
    __shared__ uint32_t Bh[2][8][132];
    __shared__ uint32_t Bl[2][8][132];
    int tid = threadIdx.x, lane = tid & 31, warp = tid >> 5;
    int grp = lane >> 2, qid = lane & 3;
    int m_base = (warp >> 2) * 64, n_base = (warp & 3) * 32;
    int a_r = tid >> 2, a_k4 = (tid & 3) * 4, a_kp = (tid & 3) * 2;
    int ar1 = row0 + a_r, ar2 = row0 + a_r + 64;
    bool av1 = ar1 < M, av2 = ar2 < M;
    int b_kp = tid >> 5, b_n4 = (tid & 31) * 4;
    float acc[4][4][4];
    #pragma unroll
    for (int i = 0; i < 4; i++)
        #pragma unroll
        for (int j = 0; j < 4; j++)
            #pragma unroll
            for (int q = 0; q < 4; q++) acc[i][j][q] = 0.f;
    int nt = K / 16;
    float4 ra0, ra1, rbE, rbO;
    ra0 = av1 ? *(const float4*)(A + (size_t)ar1 * K + a_k4) : make_float4(0,0,0,0);
    ra1 = av2 ? *(const float4*)(A + (size_t)ar2 * K + a_k4) : make_float4(0,0,0,0);
    rbE = *(const float4*)(Bm + (size_t)(2 * b_kp) * Nn + col0 + b_n4);
    rbO = *(const float4*)(Bm + (size_t)(2 * b_kp + 1) * Nn + col0 + b_n4);
    {
        uint32_t h0, l0, h1, l1;
        bfsplit2(ra0.x, ra0.y, h0, l0); bfsplit2(ra0.z, ra0.w, h1, l1);
        Ah[0][a_r][a_kp] = h0; Ah[0][a_r][a_kp+1] = h1; Al[0][a_r][a_kp] = l0; Al[0][a_r][a_kp+1] = l1;
        bfsplit2(ra1.x, ra1.y, h0, l0); bfsplit2(ra1.z, ra1.w, h1, l1);
        Ah[0][a_r+64][a_kp] = h0; Ah[0][a_r+64][a_kp+1] = h1; Al[0][a_r+64][a_kp] = l0; Al[0][a_r+64][a_kp+1] = l1;
        uint32_t bh4[4], bl4[4];
        bfsplit2(rbE.x, rbO.x, bh4[0], bl4[0]); bfsplit2(rbE.y, rbO.y, bh4[1], bl4[1]);
        bfsplit2(rbE.z, rbO.z, bh4[2], bl4[2]); bfsplit2(rbE.w, rbO.w, bh4[3], bl4[3]);
        *(uint4*)&Bh[0][b_kp][b_n4] = *(uint4*)bh4;
        *(uint4*)&Bl[0][b_kp][b_n4] = *(uint4*)bl4;
    }
    __syncthreads();
    for (int t = 0; t < nt; t++) {
        int cur = t & 1;
        if (t + 1 < nt) {
            int k0 = (t + 1) * 16;
            ra0 = av1 ? *(const float4*)(A + (size_t)ar1 * K + k0 + a_k4) : make_float4(0,0,0,0);
            ra1 = av2 ? *(const float4*)(A + (size_t)ar2 * K + k0 + a_k4) : make_float4(0,0,0,0);
            rbE = *(const float4*)(Bm + (size_t)(k0 + 2 * b_kp) * Nn + col0 + b_n4);
            rbO = *(const float4*)(Bm + (size_t)(k0 + 2 * b_kp + 1) * Nn + col0 + b_n4);
        }
        uint32_t a_h[4][4], a_l[4][4], b_h[4][2], b_l[4][2];
        #pragma unroll
        for (int mi = 0; mi < 4; mi++) {
            int rm = m_base + mi * 16 + grp;
            a_h[mi][0] = Ah[cur][rm][qid];         a_l[mi][0] = Al[cur][rm][qid];
            a_h[mi][1] = Ah[cur][rm + 8][qid];     a_l[mi][1] = Al[cur][rm + 8][qid];
            a_h[mi][2] = Ah[cur][rm][qid + 4];     a_l[mi][2] = Al[cur][rm][qid + 4];
            a_h[mi][3] = Ah[cur][rm + 8][qid + 4]; a_l[mi][3] = Al[cur][rm + 8][qid + 4];
        }
        #pragma unroll
        for (int ni = 0; ni < 4; ni++) {
            int cn = n_base + ni * 8 + grp;
            b_h[ni][0] = Bh[cur][qid][cn];     b_l[ni][0] = Bl[cur][qid][cn];
            b_h[ni][1] = Bh[cur][qid + 4][cn]; b_l[ni][1] = Bl[cur][qid + 4][cn];
        }
        #pragma unroll
        for (int mi = 0; mi < 4; mi++)
            #pragma unroll
            for (int ni = 0; ni < 4; ni++) {
                mma16bf(acc[mi][ni], a_h[mi], b_l[ni]);
                mma16bf(acc[mi][ni], a_l[mi], b_h[ni]);
                mma16bf(acc[mi][ni], a_h[mi], b_h[ni]);
            }
        if (t + 1 < nt) {
            int nxt = (t + 1) & 1;
            uint32_t h0, l0, h1, l1;
            bfsplit2(ra0.x, ra0.y, h0, l0); bfsplit2(ra0.z, ra0.w, h1, l1);
            Ah[nxt][a_r][a_kp] = h0; Ah[nxt][a_r][a_kp+1] = h1; Al[nxt][a_r][a_kp] = l0; Al[nxt][a_r][a_kp+1] = l1;
            bfsplit2(ra1.x, ra1.y, h0, l0); bfsplit2(ra1.z, ra1.w, h1, l1);
            Ah[nxt][a_r+64][a_kp] = h0; Ah[nxt][a_r+64][a_kp+1] = h1; Al[nxt][a_r+64][a_kp] = l0; Al[nxt][a_r+64][a_kp+1] = l1;
            uint32_t bh4[4], bl4[4];
            bfsplit2(rbE.x, rbO.x, bh4[0], bl4[0]); bfsplit2(rbE.y, rbO.y, bh4[1], bl4[1]);
            bfsplit2(rbE.z, rbO.z, bh4[2], bl4[2]); bfsplit2(rbE.w, rbO.w, bh4[3], bl4[3]);
            *(uint4*)&Bh[nxt][b_kp][b_n4] = *(uint4*)bh4;
            *(uint4*)&Bl[nxt][b_kp][b_n4] = *(uint4*)bl4;
            __syncthreads();
        }
    }
    #pragma unroll
    for (int mi = 0; mi < 4; mi++) {
        int r0 = row0 + m_base + mi * 16 + grp;
        int r1 = r0 + 8;
        #pragma unroll
        for (int ni = 0; ni < 4; ni++) {
            int cb = col0 + n_base + ni * 8 + qid * 2;
            if (r0 < M) *(float2*)(C + (size_t)r0 * Nn + cb) = make_float2(acc[mi][ni][0], acc[mi][ni][1]);
            if (r1 < M) *(float2*)(C + (size_t)r1 * Nn + cb) = make_float2(acc[mi][ni][2], acc[mi][ni][3]);
        }
    }
}

// ---------------- LayerNorm ----------------
__global__ __launch_bounds__(256) void ln_kernel(
    const float* __restrict__ x, const float* __restrict__ g,
    const float* __restrict__ bta, float* __restrict__ out)
{
    int t = blockIdx.x, tid = threadIdx.x;
    float4 v = ((const float4*)(x + (size_t)t * DIM))[tid];
    float s  = v.x + v.y + v.z + v.w;
    float sq = v.x * v.x + v.y * v.y + v.z * v.z + v.w * v.w;
    __shared__ float sh[8], sh2[8];
    float ws = warpsum(s), wq = warpsum(sq);
    if ((tid & 31) == 0) { sh[tid >> 5] = ws; sh2[tid >> 5] = wq; }
    __syncthreads();
    if (tid < 32) {
        float a  = (tid < 8) ? sh[tid]  : 0.f;
        float b2 = (tid < 8) ? sh2[tid] : 0.f;
        a = warpsum(a); b2 = warpsum(b2);
        if (tid == 0) { sh[0] = a; sh2[0] = b2; }
    }
    __syncthreads();
    float mu  = sh[0] * (1.0f / DIM);
    float var = sh2[0] * (1.0f / DIM) - mu * mu;
    float inv = rsqrtf(var + 1e-5f);
    float4 gg = ((const float4*)g)[tid], bb = ((const float4*)bta)[tid];
    float4 o;
    o.x = (v.x - mu) * inv * gg.x + bb.x;
    o.y = (v.y - mu) * inv * gg.y + bb.y;
    o.z = (v.z - mu) * inv * gg.z + bb.z;
    o.w = (v.w - mu) * inv * gg.w + bb.w;
    ((float4*)(out + (size_t)t * DIM))[tid] = o;
}

// ---------------- attention ----------------
__global__ __launch_bounds__(256) void attn_scores(
    const float* __restrict__ qkv, float* __restrict__ S)
{
    int kt = blockIdx.x, qt = blockIdx.y, bh = blockIdx.z;
    int b = bh >> 4, h = bh & 15;
    int q0 = qt * 64, k0 = kt * 64;
    __shared__ float Qs[64][65];
    __shared__ float Ks[64][65];
    int tid = threadIdx.x;
    #pragma unroll
    for (int i = 0; i < 4; i++) {
        int lin = tid + i * 256;
        int row = lin >> 4;
        int c4  = (lin & 15) * 4;
        float4 qv = *(const float4*)(qkv + (size_t)(b * NSEQ + q0 + row) * 3 * DIM + h * HDIM + c4);
        Qs[row][c4] = qv.x; Qs[row][c4 + 1] = qv.y; Qs[row][c4 + 2] = qv.z; Qs[row][c4 + 3] = qv.w;
        float4 kv = *(const float4*)(qkv + (size_t)(b * NSEQ + k0 + row) * 3 * DIM + DIM + h * HDIM + c4);
        Ks[row][c4] = kv.x; Ks[row][c4 + 1] = kv.y; Ks[row][c4 + 2] = kv.z; Ks[row][c4 + 3] = kv.w;
    }
    __syncthreads();
    int ty = tid >> 4, tx = tid & 15;
    float acc[4][4];
    #pragma unroll
    for (int i = 0; i < 4; i++)
        #pragma unroll
        for (int j = 0; j < 4; j++) acc[i][j] = 0.f;
    #pragma unroll 16
    for (int kk = 0; kk < 64; kk++) {
        float a[4], bv[4];
        #pragma unroll
        for (int i = 0; i < 4; i++) a[i]  = Qs[ty * 4 + i][kk];
        #pragma unroll
        for (int j = 0; j < 4; j++) bv[j] = Ks[tx * 4 + j][kk];
        #pragma unroll
        for (int i = 0; i < 4; i++)
            #pragma unroll
            for (int j = 0; j < 4; j++) acc[i][j] += a[i] * bv[j];
    }
    float* Sp = S + (size_t)bh * NSEQ * NSEQ;
    #pragma unroll
    for (int i = 0; i < 4; i++) {
        float4 v = make_float4(acc[i][0] * 0.125f, acc[i][1] * 0.125f,
                               acc[i][2] * 0.125f, acc[i][3] * 0.125f);
        *(float4*)(Sp + (size_t)(q0 + ty * 4 + i) * NSEQ + k0 + tx * 4) = v;
    }
}

__global__ __launch_bounds__(128) void softmax_kernel(float* __restrict__ S) {
    size_t row = (size_t)blockIdx.x * 4 + (threadIdx.x >> 5);
    int lane = threadIdx.x & 31;
    float* p = S + row * NSEQ;
    float v[8];
    float m = -1e30f;
    #pragma unroll
    for (int i = 0; i < 8; i++) { v[i] = p[lane + i * 32]; m = fmaxf(m, v[i]); }
    m = warpmax(m);
    float s = 0.f;
    #pragma unroll
    for (int i = 0; i < 8; i++) { v[i] = expf(v[i] - m); s += v[i]; }
    s = warpsum(s);
    float inv = 1.0f / s;
    #pragma unroll
    for (int i = 0; i < 8; i++) p[lane + i * 32] = v[i] * inv;
}

__global__ __launch_bounds__(256) void attn_av(
    const float* __restrict__ qkv, const float* __restrict__ S, float* __restrict__ o)
{
    int qt = blockIdx.x, bh = blockIdx.y;
    int b = bh >> 4, h = bh & 15;
    int q0 = qt * 64;
    __shared__ float Ps[64][17];
    __shared__ float Vs[16][64];
    int tid = threadIdx.x;
    int ty = tid >> 4, tx = tid & 15;
    float acc[4][4];
    #pragma unroll
    for (int i = 0; i < 4; i++)
        #pragma unroll
        for (int j = 0; j < 4; j++) acc[i][j] = 0.f;
    const float* Sp = S + (size_t)bh * NSEQ * NSEQ;
    for (int k0 = 0; k0 < NSEQ; k0 += 16) {
        {
            int row = tid >> 2, c = (tid & 3) * 4;
            float4 pv = *(const float4*)(Sp + (size_t)(q0 + row) * NSEQ + k0 + c);
            Ps[row][c] = pv.x; Ps[row][c + 1] = pv.y; Ps[row][c + 2] = pv.z; Ps[row][c + 3] = pv.w;
        }
        {
            int kr = tid >> 4, c = (tid & 15) * 4;
            float4 vv = *(const float4*)(qkv + (size_t)(b * NSEQ + k0 + kr) * 3 * DIM + 2 * DIM + h * HDIM + c);
            *(float4*)&Vs[kr][c] = vv;
        }
        __syncthreads();
        #pragma unroll
        for (int kk = 0; kk < 16; kk++) {
            float a[4], bv[4];
            #pragma unroll
            for (int i = 0; i < 4; i++) a[i]  = Ps[ty * 4 + i][kk];
            #pragma unroll
            for (int j = 0; j < 4; j++) bv[j] = Vs[kk][tx * 4 + j];
            #pragma unroll
            for (int i = 0; i < 4; i++)
                #pragma unroll
                for (int j = 0; j < 4; j++) acc[i][j] += a[i] * bv[j];
        }
        __syncthreads();
    }
    #pragma unroll
    for (int i = 0; i < 4; i++) {
        float4 v = make_float4(acc[i][0], acc[i][1], acc[i][2], acc[i][3]);
        *(float4*)(o + (size_t)(b * NSEQ + q0 + ty * 4 + i) * DIM + h * HDIM + tx * 4) = v;
    }
}

// ---------------- router: fc2 + softmax + top2; lists + per-token (e,w) ----------------
__global__ __launch_bounds__(128) void router_kernel(
    const float* __restrict__ gh, const float* __restrict__ W, const float* __restrict__ bias)
{
    int t = blockIdx.x;
    int wid = threadIdx.x >> 5, lane = threadIdx.x & 31;
    const float* row = gh + (size_t)t * RHC;
    float s = 0.f;
    for (int k = lane; k < RHC; k += 32) s += row[k] * W[k * NE + wid];
    s = warpsum(s);
    __shared__ float logits[NE];
    if (lane == 0) logits[wid] = s + bias[wid];
    __syncthreads();
    if (threadIdx.x == 0) {
        float l[NE], m = -1e30f;
        #pragma unroll
        for (int e = 0; e < NE; e++) { l[e] = logits[e]; m = fmaxf(m, l[e]); }
        float ssum = 0.f;
        #pragma unroll
        for (int e = 0; e < NE; e++) { l[e] = expf(l[e] - m); ssum += l[e]; }
        float p[NE];
        #pragma unroll
        for (int e = 0; e < NE; e++)
            p[e] = fminf(fmaxf(l[e] / ssum, 1e-9f), 1.0f - 1e-9f);
        int i1 = 0;
        #pragma unroll
        for (int e = 1; e < NE; e++) if (p[e] > p[i1]) i1 = e;
        int i2 = -1;
        #pragma unroll
        for (int e = 0; e < NE; e++) {
            if (e == i1) continue;
            if (i2 < 0 || p[e] > p[i2]) i2 = e;
        }
        float wsum = p[i1] + p[i2];
        int pos = atomicAdd(&g_cnt[i1], 1);
        g_idx[i1 * TT + pos] = t;
        pos = atomicAdd(&g_cnt[i2], 1);
        g_idx[i2 * TT + pos] = t;
        g_te[t] = make_int2(i1, i2);
        g_tw[t] = make_float2(p[i1] / wsum, p[i2] / wsum);
    }
}

__global__ void zero_cnt_kernel() {
    if (threadIdx.x < NE) g_cnt[threadIdx.x] = 0;
}

// out[t] = x1[t] + w1*eout[e1][t] + w2*eout[e2][t]
__global__ __launch_bounds__(256) void combine_kernel(
    const float* __restrict__ x1, const float* __restrict__ eout, float* __restrict__ out)
{
    int t = blockIdx.x, c = threadIdx.x;
    int2 e = g_te[t];
    float2 w = g_tw[t];
    float4 a  = ((const float4*)(x1 + (size_t)t * DIM))[c];
    float4 v1 = ((const float4*)(eout + ((size_t)e.x * TT + t) * DIM))[c];
    float4 v2 = ((const float4*)(eout + ((size_t)e.y * TT + t) * DIM))[c];
    float4 r;
    r.x = a.x + w.x * v1.x + w.y * v2.x;
    r.y = a.y + w.x * v1.y + w.y * v2.y;
    r.z = a.z + w.x * v1.z + w.y * v2.z;
    r.w = a.w + w.x * v1.w + w.y * v2.w;
    ((float4*)(out + (size_t)t * DIM))[c] = r;
}

// ---------------- host launcher ----------------
static void* symaddr(const void* s) {
    void* p = nullptr;
    cudaGetSymbolAddress(&p, s);
    return p;
}

extern "C" void kernel_launch(void* const* d_in, const int* in_sizes, int n_in,
                              void* d_out, int out_size) {
    const float* x       = (const float*)d_in[0];
    const float* cond    = (const float*)d_in[1];
    const float* ln1_g   = (const float*)d_in[2];
    const float* ln1_b   = (const float*)d_in[3];
    const float* qkv_w   = (const float*)d_in[4];
    const float* proj_w  = (const float*)d_in[5];
    const float* proj_b  = (const float*)d_in[6];
    const float* ln2_g   = (const float*)d_in[7];
    const float* ln2_b   = (const float*)d_in[8];
    const float* r_fc1_w = (const float*)d_in[9];
    const float* r_fc1_b = (const float*)d_in[10];
    const float* r_fc2_w = (const float*)d_in[11];
    const float* r_fc2_b = (const float*)d_in[12];
    const float* e_w1    = (const float*)d_in[13];
    const float* e_b1    = (const float*)d_in[14];
    const float* e_w2    = (const float*)d_in[15];
    const float* e_b2    = (const float*)d_in[16];
    float* out = (float*)d_out;

    float* h1    = (float*)symaddr(g_h1);
    float* qkv   = (float*)symaddr(g_qkv);
    float* S     = (float*)symaddr(g_S);
    float* o     = (float*)symaddr(g_o);
    float* x1    = (float*)symaddr(g_x1);
    float* h2    = (float*)symaddr(g_h2);
    float* condc = (float*)symaddr(g_condc);
    float* gh    = (float*)symaddr(g_gh);
    float* hid   = (float*)symaddr(g_hid);
    float* eout  = (float*)symaddr(g_eout);
    int*   cnt   = (int*)symaddr(g_cnt);
    int*   idx   = (int*)symaddr(g_idx);
    __half* wqkv_h  = (__half*)symaddr(g_wqkv_h);
    __half* wqkv_l  = (__half*)symaddr(g_wqkv_l);
    __half* wproj_h = (__half*)symaddr(g_wproj_h);
    __half* wproj_l = (__half*)symaddr(g_wproj_l);
    __half* wfc1_h  = (__half*)symaddr(g_wfc1_h);
    __half* wfc1_l  = (__half*)symaddr(g_wfc1_l);
    __half* we1_h   = (__half*)symaddr(g_we1_h);
    __half* we2_h   = (__half*)symaddr(g_we2_h);

    cudaFuncSetAttribute(gemm_tc2<3,false,false,false,false,false,false>,
                         cudaFuncAttributeMaxDynamicSharedMemorySize, G_SMEM);
    cudaFuncSetAttribute(gemm_tc2<3,false,false,true,false,true,false>,
                         cudaFuncAttributeMaxDynamicSharedMemorySize, G_SMEM);
    cudaFuncSetAttribute(gemm_tc2<3,false,false,true,true,false,true>,
                         cudaFuncAttributeMaxDynamicSharedMemorySize, G_SMEM);
    cudaFuncSetAttribute(gemm_tc2<2,true,false,true,true,false,false>,
                         cudaFuncAttributeMaxDynamicSharedMemorySize, G_SMEM);
    cudaFuncSetAttribute(gemm_tc2<2,false,true,true,false,false,false>,
                         cudaFuncAttributeMaxDynamicSharedMemorySize, G_SMEM);

    zero_cnt_kernel<<<1, 32>>>();

    // pre-split weights (K-major fp16 hi/lo; experts hi-only)
    wsplit_kernel<<<dim3(3 * DIM / 32, DIM / 32, 1), 256>>>(qkv_w, wqkv_h, wqkv_l, DIM, 3 * DIM, 3 * DIM, 0, 0);
    wsplit_kernel<<<dim3(DIM / 32, DIM / 32, 1), 256>>>(proj_w, wproj_h, wproj_l, DIM, DIM, DIM, 0, 0);
    wsplit_kernel<<<dim3(RHC / 32, DIM / 32, 1), 256>>>(r_fc1_w, wfc1_h, wfc1_l, DIM, RHC, RHC, 0, 0);
    wsplit_kernel<<<dim3(DFFC / 32, DIM / 32, NE), 256>>>(e_w1, we1_h, nullptr, DIM, DFFC, DFFC,
                                                          (size_t)DIM * DFFC, (size_t)DFFC * DIM);
    wsplit_kernel<<<dim3(DIM / 32, DFFC / 32, NE), 256>>>(e_w2, we2_h, nullptr, DFFC, DIM, DIM,
                                                          (size_t)DFFC * DIM, (size_t)DIM * DFFC);

    // LN1
    ln_kernel<<<TT, 256>>>(x, ln1_g, ln1_b, h1);

    // QKV = h1 @ qkv_w (3-term)
    gemm_tc2<3,false,false,false,false,false,false>
        <<<dim3(3 * DIM / 128, TT / 128, 1), 256, G_SMEM>>>(h1, wqkv_h, wqkv_l, qkv, TT, 3 * DIM, DIM,
            nullptr, 0, nullptr, nullptr, nullptr, nullptr, 0, 0, 0);

    // attention
    attn_scores<<<dim3(4, 4, BB * NH), 256>>>(qkv, S);
    softmax_kernel<<<BB * NH * NSEQ / 4, 128>>>(S);
    attn_av<<<dim3(4, BB * NH), 256>>>(qkv, S, o);

    // x1 = x + o @ proj_w + proj_b (3-term)
    gemm_tc2<3,false,false,true,false,true,false>
        <<<dim3(DIM / 128, TT / 128, 1), 256, G_SMEM>>>(o, wproj_h, wproj_l, x1, TT, DIM, DIM,
            proj_b, 0, x, nullptr, nullptr, nullptr, 0, 0, 0);

    // LN2
    ln_kernel<<<TT, 256>>>(x1, ln2_g, ln2_b, h2);

    // condc[b] = cond[b] @ r_fc1_w[D:, :]  (tiny; legacy bf16 kernel)
    gemm_tc_plain<<<dim3(RHC / 128, 1), 256>>>(cond, r_fc1_w + (size_t)DIM * RHC, condc, BB, RHC, CDIM);

    // gh = gelu(h2 @ r_fc1_w[:D] + condc[b] + b1) (3-term)
    gemm_tc2<3,false,false,true,true,false,true>
        <<<dim3(RHC / 128, TT / 128, 1), 256, G_SMEM>>>(h2, wfc1_h, wfc1_l, gh, TT, RHC, DIM,
            r_fc1_b, 0, nullptr, condc, nullptr, nullptr, 0, 0, 0);

    // router: logits, top2, per-expert lists + per-token (e,w)
    router_kernel<<<TT, 128>>>(gh, r_fc2_w, r_fc2_b);

    // experts (2-term: activations split, weights fp16-rounded), merged across NE:
    // hid[ez][r] = gelu(h2[idx[ez][r]] @ w1[ez] + b1[ez])
    gemm_tc2<2,true,false,true,true,false,false>
        <<<dim3(DFFC / 128, TT / 128, NE), 256, G_SMEM>>>(h2, we1_h, nullptr, hid,
            TT, DFFC, DIM, e_b1, DFFC, nullptr, nullptr,
            idx, cnt, (size_t)DFFC * DIM, 0, TT);
    // eout[ez][idx[ez][r]] = hid[ez][r] @ w2[ez] + b2[ez]
    gemm_tc2<2,false,true,true,false,false,false>
        <<<dim3(DIM / 128, TT / 128, NE), 256, G_SMEM>>>(hid, we2_h, nullptr, eout,
            TT, DIM, DFFC, e_b2, DIM, nullptr, nullptr,
            idx, cnt, (size_t)DIM * DFFC, (size_t)TT * DFFC, TT);

    // out = x1 + w1*eout[e1] + w2*eout[e2]
    combine_kernel<<<TT, 256>>>(x1, eout, out);
}

// round 12
// speedup vs baseline: 4.2464x; 1.2337x over previous
#include <cuda_runtime.h>
#include <cuda_bf16.h>
#include <cuda_fp16.h>
#include <math.h>
#include <stdint.h>

// ---------------- problem constants ----------------
constexpr int BB   = 32;
constexpr int NSEQ = 256;
constexpr int DIM  = 1024;
constexpr int NH   = 16;
constexpr int HDIM = 64;
constexpr int CDIM = 1024;
constexpr int NE   = 4;
constexpr int DFFC = 4096;
constexpr int RHC  = 2048;
constexpr int TT   = BB * NSEQ;   // 8192 tokens

// ---------------- scratch (device globals; no allocation allowed) ----------------
__device__ float g_h1[TT * DIM];
__device__ float g_qkv[TT * 3 * DIM];
__device__ float g_S[(size_t)BB * NH * NSEQ * NSEQ];
__device__ float g_o[TT * DIM];
__device__ float g_x1[TT * DIM];
__device__ float g_h2[TT * DIM];
__device__ float g_condc[BB * RHC];
__device__ float g_gh[(size_t)TT * RHC];
__device__ float g_hid[(size_t)NE * TT * DFFC];    // per-expert hidden
__device__ float g_eout[(size_t)NE * TT * DIM];    // per-expert output (token-addressed)
__device__ int   g_cnt[NE];
__device__ int   g_idx[NE * TT];
__device__ int2   g_te[TT];
__device__ float2 g_tw[TT];

// pre-split K-major weights: [N][K] fp16 hi/lo (experts: hi only)
__device__ __half g_wqkv_h[(size_t)3 * DIM * DIM];
__device__ __half g_wqkv_l[(size_t)3 * DIM * DIM];
__device__ __half g_wproj_h[(size_t)DIM * DIM];
__device__ __half g_wproj_l[(size_t)DIM * DIM];
__device__ __half g_wfc1_h[(size_t)RHC * DIM];
__device__ __half g_wfc1_l[(size_t)RHC * DIM];
__device__ __half g_we1_h[(size_t)NE * DFFC * DIM];
__device__ __half g_we2_h[(size_t)NE * DIM * DFFC];

// ---------------- helpers ----------------
__device__ __forceinline__ float warpsum(float v) {
    #pragma unroll
    for (int o = 16; o; o >>= 1) v += __shfl_xor_sync(0xFFFFFFFFu, v, o);
    return v;
}
__device__ __forceinline__ float warpmax(float v) {
    #pragma unroll
    for (int o = 16; o; o >>= 1) v = fmaxf(v, __shfl_xor_sync(0xFFFFFFFFu, v, o));
    return v;
}
__device__ __forceinline__ float gelu_f(float x) {
    return 0.5f * x * (1.0f + erff(x * 0.70710678118654752f));
}
// fp16 hi/lo split (11+11 bits)
__device__ __forceinline__ void hsplit2(float x0, float x1, uint32_t& hi, uint32_t& lo) {
    __half2 h = __floats2half2_rn(x0, x1);
    float r0 = x0 - __half2float(__low2half(h));
    float r1 = x1 - __half2float(__high2half(h));
    __half2 l = __floats2half2_rn(r0, r1);
    hi = *reinterpret_cast<uint32_t*>(&h);
    lo = *reinterpret_cast<uint32_t*>(&l);
}
__device__ __forceinline__ uint32_t hpack2(float x0, float x1) {
    __half2 h = __floats2half2_rn(x0, x1);
    return *reinterpret_cast<uint32_t*>(&h);
}
// bf16 split (tiny condc kernel)
__device__ __forceinline__ void bfsplit2(float x0, float x1, uint32_t& hi, uint32_t& lo) {
    __nv_bfloat162 h = __floats2bfloat162_rn(x0, x1);
    float r0 = x0 - __bfloat162float(h.x);
    float r1 = x1 - __bfloat162float(h.y);
    __nv_bfloat162 l = __floats2bfloat162_rn(r0, r1);
    hi = *reinterpret_cast<uint32_t*>(&h);
    lo = *reinterpret_cast<uint32_t*>(&l);
}
__device__ __forceinline__ void mma16bf(float* c, const uint32_t* a, const uint32_t* b) {
    asm("mma.sync.aligned.m16n8k16.row.col.f32.bf16.bf16.f32 "
        "{%0,%1,%2,%3}, {%4,%5,%6,%7}, {%8,%9}, {%0,%1,%2,%3};"
        : "+f"(c[0]), "+f"(c[1]), "+f"(c[2]), "+f"(c[3])
        : "r"(a[0]), "r"(a[1]), "r"(a[2]), "r"(a[3]), "r"(b[0]), "r"(b[1]));
}
__device__ __forceinline__ void mma16f(float* c, const uint32_t* a, const uint32_t* b) {
    asm("mma.sync.aligned.m16n8k16.row.col.f32.f16.f16.f32 "
        "{%0,%1,%2,%3}, {%4,%5,%6,%7}, {%8,%9}, {%0,%1,%2,%3};"
        : "+f"(c[0]), "+f"(c[1]), "+f"(c[2]), "+f"(c[3])
        : "r"(a[0]), "r"(a[1]), "r"(a[2]), "r"(a[3]), "r"(b[0]), "r"(b[1]));
}
__device__ __forceinline__ void mma16h(uint32_t* c, const uint32_t* a, const uint32_t* b) {
    asm("mma.sync.aligned.m16n8k16.row.col.f16.f16.f16.f16 "
        "{%0,%1}, {%2,%3,%4,%5}, {%6,%7}, {%0,%1};"
        : "+r"(c[0]), "+r"(c[1])
        : "r"(a[0]), "r"(a[1]), "r"(a[2]), "r"(a[3]), "r"(b[0]), "r"(b[1]));
}
__device__ __forceinline__ void ldmx4(uint32_t* r, uint32_t a) {
    asm volatile("ldmatrix.sync.aligned.m8n8.x4.shared.b16 {%0,%1,%2,%3}, [%4];"
        : "=r"(r[0]), "=r"(r[1]), "=r"(r[2]), "=r"(r[3]) : "r"(a));
}
__device__ __forceinline__ void ldmx2(uint32_t* r, uint32_t a) {
    asm volatile("ldmatrix.sync.aligned.m8n8.x2.shared.b16 {%0,%1}, [%2];"
        : "=r"(r[0]), "=r"(r[1]) : "r"(a));
}
__device__ __forceinline__ uint32_t smem_u32(const void* p) {
    uint32_t a;
    asm("{ .reg .u64 t; cvta.to.shared.u64 t, %1; cvt.u32.u64 %0, t; }" : "=r"(a) : "l"(p));
    return a;
}
__device__ __forceinline__ void cp16(uint32_t dst, const void* src) {
    asm volatile("cp.async.ca.shared.global [%0], [%1], 16;" :: "r"(dst), "l"(src));
}
__device__ __forceinline__ void cp_commit() { asm volatile("cp.async.commit_group;" ::: "memory"); }
__device__ __forceinline__ void cp_wait0()  { asm volatile("cp.async.wait_group 0;" ::: "memory"); }

// ---------------- weight transpose + split: W[K,N] -> Wh(/Wl)[N,K] fp16 ----------------
__global__ __launch_bounds__(256) void wsplit_kernel(
    const float* __restrict__ W, __half* __restrict__ Wh, __half* __restrict__ Wl,
    int K, int Nn, int ld, size_t wz, size_t oz)
{
    __shared__ float ts[32][33];
    int z = blockIdx.z;
    const float* Wp = W + (size_t)z * wz;
    int n0 = blockIdx.x * 32, k0 = blockIdx.y * 32;
    int tx = threadIdx.x & 31, ty = threadIdx.x >> 5;
    #pragma unroll
    for (int i = 0; i < 4; i++)
        ts[ty + i * 8][tx] = Wp[(size_t)(k0 + ty + i * 8) * ld + n0 + tx];
    __syncthreads();
    #pragma unroll
    for (int i = 0; i < 4; i++) {
        int n = n0 + ty + i * 8, k = k0 + tx;
        float v = ts[tx][ty + i * 8];
        __half h = __float2half(v);
        Wh[(size_t)z * oz + (size_t)n * K + k] = h;
        if (Wl) Wl[(size_t)z * oz + (size_t)n * K + k] = __float2half(v - __half2float(h));
    }
}

// ---------------- fp16 split GEMM (TERMS=3 / 2 / 1) ------
// TERMS=3: AhBh(f32) + AhBl(f16) + AlBh(f16); TERMS=2: AhBh + AlBh; TERMS=1: AhBh only.
// C[M,Nn] = A[M,K](fp32) @ W(pre-split fp16 [Nn][K]); CTA 128x128, 8 warps 2m x 4n.
constexpr int G_AH = 0;
constexpr int G_AL = 10240;
constexpr int G_BH = 20480;
constexpr int G_BL = 30720;
constexpr int G_STG = 40960;
constexpr int G_SMEM = 2 * G_STG;     // 81920

template<int TERMS, bool GATHER, bool SCATTER, bool BIAS, bool GELU, bool RESID, bool CONDC>
__global__ __launch_bounds__(256) void gemm_tc2(
    const float* __restrict__ A,
    const __half* __restrict__ Bh, const __half* __restrict__ Bl,
    float* __restrict__ C, int M, int Nn, int K,
    const float* __restrict__ bias, int biasz,
    const float* __restrict__ res, const float* __restrict__ condc,
    const int* __restrict__ gidx, const int* __restrict__ cntp,
    size_t wz, size_t azoff, int czoff)
{
    extern __shared__ char sm[];
    int ez = blockIdx.z;
    if (cntp) M = cntp[ez];
    int row0 = blockIdx.y * 128;
    if (row0 >= M) return;
    int col0 = blockIdx.x * 128;

    A  += (size_t)ez * azoff;
    Bh += (size_t)ez * wz;
    if (TERMS == 3) Bl += (size_t)ez * wz;
    const int* gz = (GATHER || SCATTER) ? (gidx + ez * TT) : nullptr;
    size_t crow_base = (size_t)ez * (size_t)czoff;

    uint32_t sb = smem_u32(sm);
    int tid = threadIdx.x, lane = tid & 31, warp = tid >> 5;
    int m_base = (warp >> 2) * 64, n_base = (warp & 3) * 32;

    // ---- loader mapping ----
    int l_row  = tid >> 1;
    int l_half = tid & 1;
    int gar = row0 + l_row;
    bool gav = gar < M;
    int garow = gav ? (GATHER ? gz[gar] : gar) : 0;
    const float* ap = A + (size_t)garow * K;
    const char* bhp = (const char*)(Bh + (size_t)(col0 + l_row) * K);
    const char* blp = (TERMS == 3) ? (const char*)(Bl + (size_t)(col0 + l_row) * K) : nullptr;
    uint32_t a_sts = sb + (uint32_t)(l_row * 20 + l_half * 8) * 4;
    uint32_t b_sts = sb + (uint32_t)(l_row * 20 + l_half * 8) * 4;

    // ---- ldmatrix per-thread addresses ----
    uint32_t a_lrow = (uint32_t)(m_base + (lane & 7) + ((lane >> 3) & 1) * 8);
    uint32_t a_lcol = (uint32_t)((lane >> 4) * 4);
    int bl15 = lane & 15;
    uint32_t b_lrow = (uint32_t)(n_base + (bl15 & 7));
    uint32_t b_lcol = (uint32_t)(((bl15 >> 3) & 1) * 4);

    float acc[4][4][4];
    uint32_t accl[4][4][2];
    #pragma unroll
    for (int i = 0; i < 4; i++)
        #pragma unroll
        for (int j = 0; j < 4; j++) {
            #pragma unroll
            for (int q = 0; q < 4; q++) acc[i][j][q] = 0.f;
            accl[i][j][0] = 0u; accl[i][j][1] = 0u;
        }

    int nt = K >> 5;
    float4 pa[4];

    auto ldgA = [&](int kt) {
        const float* p = ap + kt * 32 + l_half * 16;
        if (gav) {
            pa[0] = *(const float4*)(p);
            pa[1] = *(const float4*)(p + 4);
            pa[2] = *(const float4*)(p + 8);
            pa[3] = *(const float4*)(p + 12);
        } else {
            pa[0] = pa[1] = pa[2] = pa[3] = make_float4(0.f, 0.f, 0.f, 0.f);
        }
    };
    auto cpB = [&](int kt, int buf) {
        uint32_t d = b_sts + buf * G_STG;
        const char* sh = bhp + (size_t)kt * 64 + l_half * 32;
        cp16(d + G_BH,      sh);
        cp16(d + G_BH + 16, sh + 16);
        if (TERMS == 3) {
            const char* sl = blp + (size_t)kt * 64 + l_half * 32;
            cp16(d + G_BL,      sl);
            cp16(d + G_BL + 16, sl + 16);
        }
        cp_commit();
    };
    auto stsA = [&](int buf) {
        uint32_t d = a_sts + buf * G_STG;
        if (TERMS >= 2) {
            uint32_t h[8], l[8];
            hsplit2(pa[0].x, pa[0].y, h[0], l[0]); hsplit2(pa[0].z, pa[0].w, h[1], l[1]);
            hsplit2(pa[1].x, pa[1].y, h[2], l[2]); hsplit2(pa[1].z, pa[1].w, h[3], l[3]);
            hsplit2(pa[2].x, pa[2].y, h[4], l[4]); hsplit2(pa[2].z, pa[2].w, h[5], l[5]);
            hsplit2(pa[3].x, pa[3].y, h[6], l[6]); hsplit2(pa[3].z, pa[3].w, h[7], l[7]);
            *(uint4*)(sm + (d - sb) + G_AH)      = *(uint4*)(h);
            *(uint4*)(sm + (d - sb) + G_AH + 16) = *(uint4*)(h + 4);
            *(uint4*)(sm + (d - sb) + G_AL)      = *(uint4*)(l);
            *(uint4*)(sm + (d - sb) + G_AL + 16) = *(uint4*)(l + 4);
        } else {
            uint32_t h[8];
            h[0] = hpack2(pa[0].x, pa[0].y); h[1] = hpack2(pa[0].z, pa[0].w);
            h[2] = hpack2(pa[1].x, pa[1].y); h[3] = hpack2(pa[1].z, pa[1].w);
            h[4] = hpack2(pa[2].x, pa[2].y); h[5] = hpack2(pa[2].z, pa[2].w);
            h[6] = hpack2(pa[3].x, pa[3].y); h[7] = hpack2(pa[3].z, pa[3].w);
            *(uint4*)(sm + (d - sb) + G_AH)      = *(uint4*)(h);
            *(uint4*)(sm + (d - sb) + G_AH + 16) = *(uint4*)(h + 4);
        }
    };

    // prologue
    ldgA(0); cpB(0, 0); stsA(0);
    cp_wait0();
    __syncthreads();

    for (int t = 0; t < nt; t++) {
        int cur = t & 1;
        if (t + 1 < nt) { ldgA(t + 1); cpB(t + 1, cur ^ 1); }
        uint32_t stage = sb + cur * G_STG;
        #pragma unroll
        for (int j = 0; j < 2; j++) {
            uint32_t a_h[4][4], a_l[4][4], b_h[4][2], b_l[4][2];
            #pragma unroll
            for (int mi = 0; mi < 4; mi++) {
                uint32_t ad = stage + ((a_lrow + mi * 16) * 20 + j * 8 + a_lcol) * 4;
                ldmx4(a_h[mi], ad + G_AH);
                if (TERMS >= 2) ldmx4(a_l[mi], ad + G_AL);
            }
            #pragma unroll
            for (int ni = 0; ni < 4; ni++) {
                uint32_t bd = stage + ((b_lrow + ni * 8) * 20 + j * 8 + b_lcol) * 4;
                ldmx2(b_h[ni], bd + G_BH);
                if (TERMS == 3) ldmx2(b_l[ni], bd + G_BL);
            }
            #pragma unroll
            for (int mi = 0; mi < 4; mi++)
                #pragma unroll
                for (int ni = 0; ni < 4; ni++) {
                    mma16f(acc[mi][ni],  a_h[mi], b_h[ni]);       // hi*hi, fp32 accum
                    if (TERMS >= 2)
                        mma16h(accl[mi][ni], a_l[mi], b_h[ni]);   // lo*hi, fp16 accum
                    if (TERMS == 3)
                        mma16h(accl[mi][ni], a_h[mi], b_l[ni]);   // hi*lo, fp16 accum
                }
        }
        if (t + 1 < nt) {
            stsA(cur ^ 1);
            cp_wait0();
            __syncthreads();
        }
    }

    // ---------------- epilogue ----------------
    int grp = lane >> 2, qid = lane & 3;
    #pragma unroll
    for (int mi = 0; mi < 4; mi++) {
        int r0 = row0 + m_base + mi * 16 + grp;
        int r1 = r0 + 8;
        bool v0 = r0 < M, v1 = r1 < M;
        size_t cr0 = 0, cr1 = 0;
        if (v0) cr0 = crow_base + (SCATTER ? (size_t)gz[r0] : (size_t)r0);
        if (v1) cr1 = crow_base + (SCATTER ? (size_t)gz[r1] : (size_t)r1);
        #pragma unroll
        for (int ni = 0; ni < 4; ni++) {
            int cb = col0 + n_base + ni * 8 + qid * 2;
            float2 f01 = make_float2(0.f, 0.f), f23 = make_float2(0.f, 0.f);
            if (TERMS >= 2) {
                f01 = __half22float2(*(__half2*)&accl[mi][ni][0]);
                f23 = __half22float2(*(__half2*)&accl[mi][ni][1]);
            }
            #pragma unroll
            for (int hf = 0; hf < 2; hf++) {
                bool valid = hf ? v1 : v0;
                if (!valid) continue;
                int rr = hf ? r1 : r0;
                size_t cr = hf ? cr1 : cr0;
                float e0 = acc[mi][ni][hf * 2 + 0] + (hf ? f23.x : f01.x);
                float e1 = acc[mi][ni][hf * 2 + 1] + (hf ? f23.y : f01.y);
                if (BIAS)  { e0 += bias[biasz * ez + cb]; e1 += bias[biasz * ez + cb + 1]; }
                if (CONDC) {
                    const float* cc = condc + (size_t)(rr >> 8) * Nn + cb;
                    e0 += cc[0]; e1 += cc[1];
                }
                if (GELU)  { e0 = gelu_f(e0); e1 = gelu_f(e1); }
                if (RESID) {
                    const float* rp = res + (size_t)rr * Nn + cb;
                    e0 += rp[0]; e1 += rp[1];
                }
                *(float2*)(C + cr * Nn + cb) = make_float2(e0, e1);
            }
        }
    }
}

// ---------------- legacy bf16-split GEMM (tiny condc only) ----------------
__global__ __launch_bounds__(256) void gemm_tc_plain(
    const float* __restrict__ A, const float* __restrict__ Bm, float* __restrict__ C,
    int M, int Nn, int K)
{
    int row0 = blockIdx.y * 128;
    if (row0 >= M) return;
    int col0 = blockIdx.x * 128;
    __shared__ uint32_t Ah[2][128][9];
    __shared__ uint32_t Al[2][128][9];
    __shared__ uint32_t Bh[2][8][132];
    __shared__ uint32_t Bl[2][8][132];
    int tid = threadIdx.x, lane = tid & 31, warp = tid >> 5;
    int grp = lane >> 2, qid = lane & 3;
    int m_base = (warp >> 2) * 64, n_base = (warp & 3) * 32;
    int a_r = tid >> 2, a_k4 = (tid & 3) * 4, a_kp = (tid & 3) * 2;
    int ar1 = row0 + a_r, ar2 = row0 + a_r + 64;
    bool av1 = ar1 < M, av2 = ar2 < M;
    int b_kp = tid >> 5, b_n4 = (tid & 31) * 4;
    float acc[4][4][4];
    #pragma unroll
    for (int i = 0; i < 4; i++)
        #pragma unroll
        for (int j = 0; j < 4; j++)
            #pragma unroll
            for (int q = 0; q < 4; q++) acc[i][j][q] = 0.f;
    int nt = K / 16;
    float4 ra0, ra1, rbE, rbO;
    ra0 = av1 ? *(const float4*)(A + (size_t)ar1 * K + a_k4) : make_float4(0,0,0,0);
    ra1 = av2 ? *(const float4*)(A + (size_t)ar2 * K + a_k4) : make_float4(0,0,0,0);
    rbE = *(const float4*)(Bm + (size_t)(2 * b_kp) * Nn + col0 + b_n4);
    rbO = *(const float4*)(Bm + (size_t)(2 * b_kp + 1) * Nn + col0 + b_n4);
    {
        uint32_t h0, l0, h1, l1;
        bfsplit2(ra0.x, ra0.y, h0, l0); bfsplit2(ra0.z, ra0.w, h1, l1);
        Ah[0][a_r][a_kp] = h0; Ah[0][a_r][a_kp+1] = h1; Al[0][a_r][a_kp] = l0; Al[0][a_r][a_kp+1] = l1;
        bfsplit2(ra1.x, ra1.y, h0, l0); bfsplit2(ra1.z, ra1.w, h1, l1);
        Ah[0][a_r+64][a_kp] = h0; Ah[0][a_r+64][a_kp+1] = h1; Al[0][a_r+64][a_kp] = l0; Al[0][a_r+64][a_kp+1] = l1;
        uint32_t bh4[4], bl4[4];
        bfsplit2(rbE.x, rbO.x, bh4[0], bl4[0]); bfsplit2(rbE.y, rbO.y, bh4[1], bl4[1]);
        bfsplit2(rbE.z, rbO.z, bh4[2], bl4[2]); bfsplit2(rbE.w, rbO.w, bh4[3], bl4[3]);
        *(uint4*)&Bh[0][b_kp][b_n4] = *(uint4*)bh4;
        *(uint4*)&Bl[0][b_kp][b_n4] = *(uint4*)bl4;
    }
    __syncthreads();
    for (int t = 0; t < nt; t++) {
        int cur = t & 1;
        if (t + 1 < nt) {
            int k0 = (t + 1) * 16;
            ra0 = av1 ? *(const float4*)(A + (size_t)ar1 * K + k0 + a_k4) : make_float4(0,0,0,0);
            ra1 = av2 ? *(const float4*)(A + (size_t)ar2 * K + k0 + a_k4) : make_float4(0,0,0,0);
            rbE = *(const float4*)(Bm + (size_t)(k0 + 2 * b_kp) * Nn + col0 + b_n4);
            rbO = *(const float4*)(Bm + (size_t)(k0 + 2 * b_kp + 1) * Nn + col0 + b_n4);
        }
        uint32_t a_h[4][4], a_l[4][4], b_h[4][2], b_l[4][2];
        #pragma unroll
        for (int mi = 0; mi < 4; mi++) {
            int rm = m_base + mi * 16 + grp;
            a_h[mi][0] = Ah[cur][rm][qid];         a_l[mi][0] = Al[cur][rm][qid];
            a_h[mi][1] = Ah[cur][rm + 8][qid];     a_l[mi][1] = Al[cur][rm + 8][qid];
            a_h[mi][2] = Ah[cur][rm][qid + 4];     a_l[mi][2] = Al[cur][rm][qid + 4];
            a_h[mi][3] = Ah[cur][rm + 8][qid + 4]; a_l[mi][3] = Al[cur][rm + 8][qid + 4];
        }
        #pragma unroll
        for (int ni = 0; ni < 4; ni++) {
            int cn = n_base + ni * 8 + grp;
            b_h[ni][0] = Bh[cur][qid][cn];     b_l[ni][0] = Bl[cur][qid][cn];
            b_h[ni][1] = Bh[cur][qid + 4][cn]; b_l[ni][1] = Bl[cur][qid + 4][cn];
        }
        #pragma unroll
        for (int mi = 0; mi < 4; mi++)
            #pragma unroll
            for (int ni = 0; ni < 4; ni++) {
                mma16bf(acc[mi][ni], a_h[mi], b_l[ni]);
                mma16bf(acc[mi][ni], a_l[mi], b_h[ni]);
                mma16bf(acc[mi][ni], a_h[mi], b_h[ni]);
            }
        if (t + 1 < nt) {
            int nxt = (t + 1) & 1;
            uint32_t h0, l0, h1, l1;
            bfsplit2(ra0.x, ra0.y, h0, l0); bfsplit2(ra0.z, ra0.w, h1, l1);
            Ah[nxt][a_r][a_kp] = h0; Ah[nxt][a_r][a_kp+1] = h1; Al[nxt][a_r][a_kp] = l0; Al[nxt][a_r][a_kp+1] = l1;
            bfsplit2(ra1.x, ra1.y, h0, l0); bfsplit2(ra1.z, ra1.w, h1, l1);
            Ah[nxt][a_r+64][a_kp] = h0; Ah[nxt][a_r+64][a_kp+1] = h1; Al[nxt][a_r+64][a_kp] = l0; Al[nxt][a_r+64][a_kp+1] = l1;
            uint32_t bh4[4], bl4[4];
            bfsplit2(rbE.x, rbO.x, bh4[0], bl4[0]); bfsplit2(rbE.y, rbO.y, bh4[1], bl4[1]);
            bfsplit2(rbE.z, rbO.z, bh4[2], bl4[2]); bfsplit2(rbE.w, rbO.w, bh4[3], bl4[3]);
            *(uint4*)&Bh[nxt][b_kp][b_n4] = *(uint4*)bh4;
            *(uint4*)&Bl[nxt][b_kp][b_n4] = *(uint4*)bl4;
            __syncthreads();
        }
    }
    #pragma unroll
    for (int mi = 0; mi < 4; mi++) {
        int r0 = row0 + m_base + mi * 16 + grp;
        int r1 = r0 + 8;
        #pragma unroll
        for (int ni = 0; ni < 4; ni++) {
            int cb = col0 + n_base + ni * 8 + qid * 2;
            if (r0 < M) *(float2*)(C + (size_t)r0 * Nn + cb) = make_float2(acc[mi][ni][0], acc[mi][ni][1]);
            if (r1 < M) *(float2*)(C + (size_t)r1 * Nn + cb) = make_float2(acc[mi][ni][2], acc[mi][ni][3]);
        }
    }
}

// ---------------- LayerNorm ----------------
__global__ __launch_bounds__(256) void ln_kernel(
    const float* __restrict__ x, const float* __restrict__ g,
    const float* __restrict__ bta, float* __restrict__ out)
{
    int t = blockIdx.x, tid = threadIdx.x;
    float4 v = ((const float4*)(x + (size_t)t * DIM))[tid];
    float s  = v.x + v.y + v.z + v.w;
    float sq = v.x * v.x + v.y * v.y + v.z * v.z + v.w * v.w;
    __shared__ float sh[8], sh2[8];
    float ws = warpsum(s), wq = warpsum(sq);
    if ((tid & 31) == 0) { sh[tid >> 5] = ws; sh2[tid >> 5] = wq; }
    __syncthreads();
    if (tid < 32) {
        float a  = (tid < 8) ? sh[tid]  : 0.f;
        float b2 = (tid < 8) ? sh2[tid] : 0.f;
        a = warpsum(a); b2 = warpsum(b2);
        if (tid == 0) { sh[0] = a; sh2[0] = b2; }
    }
    __syncthreads();
    float mu  = sh[0] * (1.0f / DIM);
    float var = sh2[0] * (1.0f / DIM) - mu * mu;
    float inv = rsqrtf(var + 1e-5f);
    float4 gg = ((const float4*)g)[tid], bb = ((const float4*)bta)[tid];
    float4 o;
    o.x = (v.x - mu) * inv * gg.x + bb.x;
    o.y = (v.y - mu) * inv * gg.y + bb.y;
    o.z = (v.z - mu) * inv * gg.z + bb.z;
    o.w = (v.w - mu) * inv * gg.w + bb.w;
    ((float4*)(out + (size_t)t * DIM))[tid] = o;
}

// ---------------- attention ----------------
__global__ __launch_bounds__(256) void attn_scores(
    const float* __restrict__ qkv, float* __restrict__ S)
{
    int kt = blockIdx.x, qt = blockIdx.y, bh = blockIdx.z;
    int b = bh >> 4, h = bh & 15;
    int q0 = qt * 64, k0 = kt * 64;
    __shared__ float Qs[64][65];
    __shared__ float Ks[64][65];
    int tid = threadIdx.x;
    #pragma unroll
    for (int i = 0; i < 4; i++) {
        int lin = tid + i * 256;
        int row = lin >> 4;
        int c4  = (lin & 15) * 4;
        float4 qv = *(const float4*)(qkv + (size_t)(b * NSEQ + q0 + row) * 3 * DIM + h * HDIM + c4);
        Qs[row][c4] = qv.x; Qs[row][c4 + 1] = qv.y; Qs[row][c4 + 2] = qv.z; Qs[row][c4 + 3] = qv.w;
        float4 kv = *(const float4*)(qkv + (size_t)(b * NSEQ + k0 + row) * 3 * DIM + DIM + h * HDIM + c4);
        Ks[row][c4] = kv.x; Ks[row][c4 + 1] = kv.y; Ks[row][c4 + 2] = kv.z; Ks[row][c4 + 3] = kv.w;
    }
    __syncthreads();
    int ty = tid >> 4, tx = tid & 15;
    float acc[4][4];
    #pragma unroll
    for (int i = 0; i < 4; i++)
        #pragma unroll
        for (int j = 0; j < 4; j++) acc[i][j] = 0.f;
    #pragma unroll 16
    for (int kk = 0; kk < 64; kk++) {
        float a[4], bv[4];
        #pragma unroll
        for (int i = 0; i < 4; i++) a[i]  = Qs[ty * 4 + i][kk];
        #pragma unroll
        for (int j = 0; j < 4; j++) bv[j] = Ks[tx * 4 + j][kk];
        #pragma unroll
        for (int i = 0; i < 4; i++)
            #pragma unroll
            for (int j = 0; j < 4; j++) acc[i][j] += a[i] * bv[j];
    }
    float* Sp = S + (size_t)bh * NSEQ * NSEQ;
    #pragma unroll
    for (int i = 0; i < 4; i++) {
        float4 v = make_float4(acc[i][0] * 0.125f, acc[i][1] * 0.125f,
                               acc[i][2] * 0.125f, acc[i][3] * 0.125f);
        *(float4*)(Sp + (size_t)(q0 + ty * 4 + i) * NSEQ + k0 + tx * 4) = v;
    }
}

__global__ __launch_bounds__(128) void softmax_kernel(float* __restrict__ S) {
    size_t row = (size_t)blockIdx.x * 4 + (threadIdx.x >> 5);
    int lane = threadIdx.x & 31;
    float* p = S + row * NSEQ;
    float v[8];
    float m = -1e30f;
    #pragma unroll
    for (int i = 0; i < 8; i++) { v[i] = p[lane + i * 32]; m = fmaxf(m, v[i]); }
    m = warpmax(m);
    float s = 0.f;
    #pragma unroll
    for (int i = 0; i < 8; i++) { v[i] = expf(v[i] - m); s += v[i]; }
    s = warpsum(s);
    float inv = 1.0f / s;
    #pragma unroll
    for (int i = 0; i < 8; i++) p[lane + i * 32] = v[i] * inv;
}

__global__ __launch_bounds__(256) void attn_av(
    const float* __restrict__ qkv, const float* __restrict__ S, float* __restrict__ o)
{
    int qt = blockIdx.x, bh = blockIdx.y;
    int b = bh >> 4, h = bh & 15;
    int q0 = qt * 64;
    __shared__ float Ps[64][17];
    __shared__ float Vs[16][64];
    int tid = threadIdx.x;
    int ty = tid >> 4, tx = tid & 15;
    float acc[4][4];
    #pragma unroll
    for (int i = 0; i < 4; i++)
        #pragma unroll
        for (int j = 0; j < 4; j++) acc[i][j] = 0.f;
    const float* Sp = S + (size_t)bh * NSEQ * NSEQ;
    for (int k0 = 0; k0 < NSEQ; k0 += 16) {
        {
            int row = tid >> 2, c = (tid & 3) * 4;
            float4 pv = *(const float4*)(Sp + (size_t)(q0 + row) * NSEQ + k0 + c);
            Ps[row][c] = pv.x; Ps[row][c + 1] = pv.y; Ps[row][c + 2] = pv.z; Ps[row][c + 3] = pv.w;
        }
        {
            int kr = tid >> 4, c = (tid & 15) * 4;
            float4 vv = *(const float4*)(qkv + (size_t)(b * NSEQ + k0 + kr) * 3 * DIM + 2 * DIM + h * HDIM + c);
            *(float4*)&Vs[kr][c] = vv;
        }
        __syncthreads();
        #pragma unroll
        for (int kk = 0; kk < 16; kk++) {
            float a[4], bv[4];
            #pragma unroll
            for (int i = 0; i < 4; i++) a[i]  = Ps[ty * 4 + i][kk];
            #pragma unroll
            for (int j = 0; j < 4; j++) bv[j] = Vs[kk][tx * 4 + j];
            #pragma unroll
            for (int i = 0; i < 4; i++)
                #pragma unroll
                for (int j = 0; j < 4; j++) acc[i][j] += a[i] * bv[j];
        }
        __syncthreads();
    }
    #pragma unroll
    for (int i = 0; i < 4; i++) {
        float4 v = make_float4(acc[i][0], acc[i][1], acc[i][2], acc[i][3]);
        *(float4*)(o + (size_t)(b * NSEQ + q0 + ty * 4 + i) * DIM + h * HDIM + tx * 4) = v;
    }
}

// ---------------- router: fc2 + softmax + top2; lists + per-token (e,w) ----------------
__global__ __launch_bounds__(128) void router_kernel(
    const float* __restrict__ gh, const float* __restrict__ W, const float* __restrict__ bias)
{
    int t = blockIdx.x;
    int wid = threadIdx.x >> 5, lane = threadIdx.x & 31;
    const float* row = gh + (size_t)t * RHC;
    float s = 0.f;
    for (int k = lane; k < RHC; k += 32) s += row[k] * W[k * NE + wid];
    s = warpsum(s);
    __shared__ float logits[NE];
    if (lane == 0) logits[wid] = s + bias[wid];
    __syncthreads();
    if (threadIdx.x == 0) {
        float l[NE], m = -1e30f;
        #pragma unroll
        for (int e = 0; e < NE; e++) { l[e] = logits[e]; m = fmaxf(m, l[e]); }
        float ssum = 0.f;
        #pragma unroll
        for (int e = 0; e < NE; e++) { l[e] = expf(l[e] - m); ssum += l[e]; }
        float p[NE];
        #pragma unroll
        for (int e = 0; e < NE; e++)
            p[e] = fminf(fmaxf(l[e] / ssum, 1e-9f), 1.0f - 1e-9f);
        int i1 = 0;
        #pragma unroll
        for (int e = 1; e < NE; e++) if (p[e] > p[i1]) i1 = e;
        int i2 = -1;
        #pragma unroll
        for (int e = 0; e < NE; e++) {
            if (e == i1) continue;
            if (i2 < 0 || p[e] > p[i2]) i2 = e;
        }
        float wsum = p[i1] + p[i2];
        int pos = atomicAdd(&g_cnt[i1], 1);
        g_idx[i1 * TT + pos] = t;
        pos = atomicAdd(&g_cnt[i2], 1);
        g_idx[i2 * TT + pos] = t;
        g_te[t] = make_int2(i1, i2);
        g_tw[t] = make_float2(p[i1] / wsum, p[i2] / wsum);
    }
}

__global__ void zero_cnt_kernel() {
    if (threadIdx.x < NE) g_cnt[threadIdx.x] = 0;
}

// out[t] = x1[t] + w1*eout[e1][t] + w2*eout[e2][t]
__global__ __launch_bounds__(256) void combine_kernel(
    const float* __restrict__ x1, const float* __restrict__ eout, float* __restrict__ out)
{
    int t = blockIdx.x, c = threadIdx.x;
    int2 e = g_te[t];
    float2 w = g_tw[t];
    float4 a  = ((const float4*)(x1 + (size_t)t * DIM))[c];
    float4 v1 = ((const float4*)(eout + ((size_t)e.x * TT + t) * DIM))[c];
    float4 v2 = ((const float4*)(eout + ((size_t)e.y * TT + t) * DIM))[c];
    float4 r;
    r.x = a.x + w.x * v1.x + w.y * v2.x;
    r.y = a.y + w.x * v1.y + w.y * v2.y;
    r.z = a.z + w.x * v1.z + w.y * v2.z;
    r.w = a.w + w.x * v1.w + w.y * v2.w;
    ((float4*)(out + (size_t)t * DIM))[c] = r;
}

// ---------------- host launcher ----------------
static void* symaddr(const void* s) {
    void* p = nullptr;
    cudaGetSymbolAddress(&p, s);
    return p;
}

extern "C" void kernel_launch(void* const* d_in, const int* in_sizes, int n_in,
                              void* d_out, int out_size) {
    const float* x       = (const float*)d_in[0];
    const float* cond    = (const float*)d_in[1];
    const float* ln1_g   = (const float*)d_in[2];
    const float* ln1_b   = (const float*)d_in[3];
    const float* qkv_w   = (const float*)d_in[4];
    const float* proj_w  = (const float*)d_in[5];
    const float* proj_b  = (const float*)d_in[6];
    const float* ln2_g   = (const float*)d_in[7];
    const float* ln2_b   = (const float*)d_in[8];
    const float* r_fc1_w = (const float*)d_in[9];
    const float* r_fc1_b = (const float*)d_in[10];
    const float* r_fc2_w = (const float*)d_in[11];
    const float* r_fc2_b = (const float*)d_in[12];
    const float* e_w1    = (const float*)d_in[13];
    const float* e_b1    = (const float*)d_in[14];
    const float* e_w2    = (const float*)d_in[15];
    const float* e_b2    = (const float*)d_in[16];
    float* out = (float*)d_out;

    float* h1    = (float*)symaddr(g_h1);
    float* qkv   = (float*)symaddr(g_qkv);
    float* S     = (float*)symaddr(g_S);
    float* o     = (float*)symaddr(g_o);
    float* x1    = (float*)symaddr(g_x1);
    float* h2    = (float*)symaddr(g_h2);
    float* condc = (float*)symaddr(g_condc);
    float* gh    = (float*)symaddr(g_gh);
    float* hid   = (float*)symaddr(g_hid);
    float* eout  = (float*)symaddr(g_eout);
    int*   cnt   = (int*)symaddr(g_cnt);
    int*   idx   = (int*)symaddr(g_idx);
    __half* wqkv_h  = (__half*)symaddr(g_wqkv_h);
    __half* wqkv_l  = (__half*)symaddr(g_wqkv_l);
    __half* wproj_h = (__half*)symaddr(g_wproj_h);
    __half* wproj_l = (__half*)symaddr(g_wproj_l);
    __half* wfc1_h  = (__half*)symaddr(g_wfc1_h);
    __half* wfc1_l  = (__half*)symaddr(g_wfc1_l);
    __half* we1_h   = (__half*)symaddr(g_we1_h);
    __half* we2_h   = (__half*)symaddr(g_we2_h);

    cudaFuncSetAttribute(gemm_tc2<3,false,false,false,false,false,false>,
                         cudaFuncAttributeMaxDynamicSharedMemorySize, G_SMEM);
    cudaFuncSetAttribute(gemm_tc2<3,false,false,true,false,true,false>,
                         cudaFuncAttributeMaxDynamicSharedMemorySize, G_SMEM);
    cudaFuncSetAttribute(gemm_tc2<3,false,false,true,true,false,true>,
                         cudaFuncAttributeMaxDynamicSharedMemorySize, G_SMEM);
    cudaFuncSetAttribute(gemm_tc2<1,true,false,true,true,false,false>,
                         cudaFuncAttributeMaxDynamicSharedMemorySize, G_SMEM);
    cudaFuncSetAttribute(gemm_tc2<1,false,true,true,false,false,false>,
                         cudaFuncAttributeMaxDynamicSharedMemorySize, G_SMEM);

    zero_cnt_kernel<<<1, 32>>>();

    // pre-split weights (K-major fp16 hi/lo; experts hi-only)
    wsplit_kernel<<<dim3(3 * DIM / 32, DIM / 32, 1), 256>>>(qkv_w, wqkv_h, wqkv_l, DIM, 3 * DIM, 3 * DIM, 0, 0);
    wsplit_kernel<<<dim3(DIM / 32, DIM / 32, 1), 256>>>(proj_w, wproj_h, wproj_l, DIM, DIM, DIM, 0, 0);
    wsplit_kernel<<<dim3(RHC / 32, DIM / 32, 1), 256>>>(r_fc1_w, wfc1_h, wfc1_l, DIM, RHC, RHC, 0, 0);
    wsplit_kernel<<<dim3(DFFC / 32, DIM / 32, NE), 256>>>(e_w1, we1_h, nullptr, DIM, DFFC, DFFC,
                                                          (size_t)DIM * DFFC, (size_t)DFFC * DIM);
    wsplit_kernel<<<dim3(DIM / 32, DFFC / 32, NE), 256>>>(e_w2, we2_h, nullptr, DFFC, DIM, DIM,
                                                          (size_t)DFFC * DIM, (size_t)DIM * DFFC);

    // LN1
    ln_kernel<<<TT, 256>>>(x, ln1_g, ln1_b, h1);

    // QKV = h1 @ qkv_w (3-term)
    gemm_tc2<3,false,false,false,false,false,false>
        <<<dim3(3 * DIM / 128, TT / 128, 1), 256, G_SMEM>>>(h1, wqkv_h, wqkv_l, qkv, TT, 3 * DIM, DIM,
            nullptr, 0, nullptr, nullptr, nullptr, nullptr, 0, 0, 0);

    // attention
    attn_scores<<<dim3(4, 4, BB * NH), 256>>>(qkv, S);
    softmax_kernel<<<BB * NH * NSEQ / 4, 128>>>(S);
    attn_av<<<dim3(4, BB * NH), 256>>>(qkv, S, o);

    // x1 = x + o @ proj_w + proj_b (3-term)
    gemm_tc2<3,false,false,true,false,true,false>
        <<<dim3(DIM / 128, TT / 128, 1), 256, G_SMEM>>>(o, wproj_h, wproj_l, x1, TT, DIM, DIM,
            proj_b, 0, x, nullptr, nullptr, nullptr, 0, 0, 0);

    // LN2
    ln_kernel<<<TT, 256>>>(x1, ln2_g, ln2_b, h2);

    // condc[b] = cond[b] @ r_fc1_w[D:, :]  (tiny; legacy bf16 kernel)
    gemm_tc_plain<<<dim3(RHC / 128, 1), 256>>>(cond, r_fc1_w + (size_t)DIM * RHC, condc, BB, RHC, CDIM);

    // gh = gelu(h2 @ r_fc1_w[:D] + condc[b] + b1) (3-term)
    gemm_tc2<3,false,false,true,true,false,true>
        <<<dim3(RHC / 128, TT / 128, 1), 256, G_SMEM>>>(h2, wfc1_h, wfc1_l, gh, TT, RHC, DIM,
            r_fc1_b, 0, nullptr, condc, nullptr, nullptr, 0, 0, 0);

    // router: logits, top2, per-expert lists + per-token (e,w)
    router_kernel<<<TT, 128>>>(gh, r_fc2_w, r_fc2_b);

    // experts (1-term: pure fp16), merged across NE:
    // hid[ez][r] = gelu(h2[idx[ez][r]] @ w1[ez] + b1[ez])
    gemm_tc2<1,true,false,true,true,false,false>
        <<<dim3(DFFC / 128, TT / 128, NE), 256, G_SMEM>>>(h2, we1_h, nullptr, hid,
            TT, DFFC, DIM, e_b1, DFFC, nullptr, nullptr,
            idx, cnt, (size_t)DFFC * DIM, 0, TT);
    // eout[ez][idx[ez][r]] = hid[ez][r] @ w2[ez] + b2[ez]
    gemm_tc2<1,false,true,true,false,false,false>
        <<<dim3(DIM / 128, TT / 128, NE), 256, G_SMEM>>>(hid, we2_h, nullptr, eout,
            TT, DIM, DFFC, e_b2, DIM, nullptr, nullptr,
            idx, cnt, (size_t)DIM * DFFC, (size_t)TT * DFFC, TT);

    // out = x1 + w1*eout[e1] + w2*eout[e2]
    combine_kernel<<<TT, 256>>>(x1, eout, out);
}

// round 13
// speedup vs baseline: 4.4540x; 1.0489x over previous
#include <cuda_runtime.h>
#include <cuda_bf16.h>
#include <cuda_fp16.h>
#include <math.h>
#include <stdint.h>

// ---------------- problem constants ----------------
constexpr int BB   = 32;
constexpr int NSEQ = 256;
constexpr int DIM  = 1024;
constexpr int NH   = 16;
constexpr int HDIM = 64;
constexpr int CDIM = 1024;
constexpr int NE   = 4;
constexpr int DFFC = 4096;
constexpr int RHC  = 2048;
constexpr int TT   = BB * NSEQ;   // 8192 tokens

// ---------------- scratch (device globals; no allocation allowed) ----------------
__device__ float g_h1[TT * DIM];
__device__ float g_qkv[TT * 3 * DIM];
__device__ float g_S[(size_t)BB * NH * NSEQ * NSEQ];
__device__ __half g_P[(size_t)BB * NH * NSEQ * NSEQ];
__device__ float g_o[TT * DIM];
__device__ float g_x1[TT * DIM];
__device__ float g_h2[TT * DIM];
__device__ float g_condc[BB * RHC];
__device__ float g_gh[(size_t)TT * RHC];
__device__ float g_hid[(size_t)NE * TT * DFFC];
__device__ float g_eout[(size_t)NE * TT * DIM];
__device__ int   g_cnt[NE];
__device__ int   g_idx[NE * TT];
__device__ int2   g_te[TT];
__device__ float2 g_tw[TT];

// pre-split K-major weights: [N][K] fp16 hi/lo (experts: hi only)
__device__ __half g_wqkv_h[(size_t)3 * DIM * DIM];
__device__ __half g_wqkv_l[(size_t)3 * DIM * DIM];
__device__ __half g_wproj_h[(size_t)DIM * DIM];
__device__ __half g_wproj_l[(size_t)DIM * DIM];
__device__ __half g_wfc1_h[(size_t)RHC * DIM];
__device__ __half g_wfc1_l[(size_t)RHC * DIM];
__device__ __half g_we1_h[(size_t)NE * DFFC * DIM];
__device__ __half g_we2_h[(size_t)NE * DIM * DFFC];

// ---------------- helpers ----------------
__device__ __forceinline__ float warpsum(float v) {
    #pragma unroll
    for (int o = 16; o; o >>= 1) v += __shfl_xor_sync(0xFFFFFFFFu, v, o);
    return v;
}
__device__ __forceinline__ float warpmax(float v) {
    #pragma unroll
    for (int o = 16; o; o >>= 1) v = fmaxf(v, __shfl_xor_sync(0xFFFFFFFFu, v, o));
    return v;
}
__device__ __forceinline__ float gelu_f(float x) {
    return 0.5f * x * (1.0f + erff(x * 0.70710678118654752f));
}
__device__ __forceinline__ void hsplit2(float x0, float x1, uint32_t& hi, uint32_t& lo) {
    __half2 h = __floats2half2_rn(x0, x1);
    float r0 = x0 - __half2float(__low2half(h));
    float r1 = x1 - __half2float(__high2half(h));
    __half2 l = __floats2half2_rn(r0, r1);
    hi = *reinterpret_cast<uint32_t*>(&h);
    lo = *reinterpret_cast<uint32_t*>(&l);
}
__device__ __forceinline__ uint32_t hpack2(float x0, float x1) {
    __half2 h = __floats2half2_rn(x0, x1);
    return *reinterpret_cast<uint32_t*>(&h);
}
__device__ __forceinline__ void bfsplit2(float x0, float x1, uint32_t& hi, uint32_t& lo) {
    __nv_bfloat162 h = __floats2bfloat162_rn(x0, x1);
    float r0 = x0 - __bfloat162float(h.x);
    float r1 = x1 - __bfloat162float(h.y);
    __nv_bfloat162 l = __floats2bfloat162_rn(r0, r1);
    hi = *reinterpret_cast<uint32_t*>(&h);
    lo = *reinterpret_cast<uint32_t*>(&l);
}
__device__ __forceinline__ void mma16bf(float* c, const uint32_t* a, const uint32_t* b) {
    asm("mma.sync.aligned.m16n8k16.row.col.f32.bf16.bf16.f32 "
        "{%0,%1,%2,%3}, {%4,%5,%6,%7}, {%8,%9}, {%0,%1,%2,%3};"
        : "+f"(c[0]), "+f"(c[1]), "+f"(c[2]), "+f"(c[3])
        : "r"(a[0]), "r"(a[1]), "r"(a[2]), "r"(a[3]), "r"(b[0]), "r"(b[1]));
}
__device__ __forceinline__ void mma16f(float* c, const uint32_t* a, const uint32_t* b) {
    asm("mma.sync.aligned.m16n8k16.row.col.f32.f16.f16.f32 "
        "{%0,%1,%2,%3}, {%4,%5,%6,%7}, {%8,%9}, {%0,%1,%2,%3};"
        : "+f"(c[0]), "+f"(c[1]), "+f"(c[2]), "+f"(c[3])
        : "r"(a[0]), "r"(a[1]), "r"(a[2]), "r"(a[3]), "r"(b[0]), "r"(b[1]));
}
__device__ __forceinline__ void mma16h(uint32_t* c, const uint32_t* a, const uint32_t* b) {
    asm("mma.sync.aligned.m16n8k16.row.col.f16.f16.f16.f16 "
        "{%0,%1}, {%2,%3,%4,%5}, {%6,%7}, {%0,%1};"
        : "+r"(c[0]), "+r"(c[1])
        : "r"(a[0]), "r"(a[1]), "r"(a[2]), "r"(a[3]), "r"(b[0]), "r"(b[1]));
}
__device__ __forceinline__ void ldmx4(uint32_t* r, uint32_t a) {
    asm volatile("ldmatrix.sync.aligned.m8n8.x4.shared.b16 {%0,%1,%2,%3}, [%4];"
        : "=r"(r[0]), "=r"(r[1]), "=r"(r[2]), "=r"(r[3]) : "r"(a));
}
__device__ __forceinline__ void ldmx2(uint32_t* r, uint32_t a) {
    asm volatile("ldmatrix.sync.aligned.m8n8.x2.shared.b16 {%0,%1}, [%2];"
        : "=r"(r[0]), "=r"(r[1]) : "r"(a));
}
__device__ __forceinline__ void ldmx2t(uint32_t* r, uint32_t a) {
    asm volatile("ldmatrix.sync.aligned.m8n8.x2.trans.shared.b16 {%0,%1}, [%2];"
        : "=r"(r[0]), "=r"(r[1]) : "r"(a));
}
__device__ __forceinline__ uint32_t smem_u32(const void* p) {
    uint32_t a;
    asm("{ .reg .u64 t; cvta.to.shared.u64 t, %1; cvt.u32.u64 %0, t; }" : "=r"(a) : "l"(p));
    return a;
}
__device__ __forceinline__ void cp16(uint32_t dst, const void* src) {
    asm volatile("cp.async.ca.shared.global [%0], [%1], 16;" :: "r"(dst), "l"(src));
}
__device__ __forceinline__ void cp_commit() { asm volatile("cp.async.commit_group;" ::: "memory"); }
__device__ __forceinline__ void cp_wait0()  { asm volatile("cp.async.wait_group 0;" ::: "memory"); }

// ---------------- weight transpose + split ----------------
__global__ __launch_bounds__(256) void wsplit_kernel(
    const float* __restrict__ W, __half* __restrict__ Wh, __half* __restrict__ Wl,
    int K, int Nn, int ld, size_t wz, size_t oz)
{
    __shared__ float ts[32][33];
    int z = blockIdx.z;
    const float* Wp = W + (size_t)z * wz;
    int n0 = blockIdx.x * 32, k0 = blockIdx.y * 32;
    int tx = threadIdx.x & 31, ty = threadIdx.x >> 5;
    #pragma unroll
    for (int i = 0; i < 4; i++)
        ts[ty + i * 8][tx] = Wp[(size_t)(k0 + ty + i * 8) * ld + n0 + tx];
    __syncthreads();
    #pragma unroll
    for (int i = 0; i < 4; i++) {
        int n = n0 + ty + i * 8, k = k0 + tx;
        float v = ts[tx][ty + i * 8];
        __half h = __float2half(v);
        Wh[(size_t)z * oz + (size_t)n * K + k] = h;
        if (Wl) Wl[(size_t)z * oz + (size_t)n * K + k] = __float2half(v - __half2float(h));
    }
}

// ---------------- fp16 split GEMM (TERMS=3 / 1) ----------------
constexpr int G_AH = 0;
constexpr int G_AL = 10240;
constexpr int G_BH = 20480;
constexpr int G_BL = 30720;
constexpr int G_STG = 40960;
constexpr int G_SMEM = 2 * G_STG;     // 81920

template<int TERMS, bool GATHER, bool SCATTER, bool BIAS, bool GELU, bool RESID, bool CONDC>
__global__ __launch_bounds__(256) void gemm_tc2(
    const float* __restrict__ A,
    const __half* __restrict__ Bh, const __half* __restrict__ Bl,
    float* __restrict__ C, int M, int Nn, int K,
    const float* __restrict__ bias, int biasz,
    const float* __restrict__ res, const float* __restrict__ condc,
    const int* __restrict__ gidx, const int* __restrict__ cntp,
    size_t wz, size_t azoff, int czoff)
{
    extern __shared__ char sm[];
    int ez = blockIdx.z;
    if (cntp) M = cntp[ez];
    int row0 = blockIdx.y * 128;
    if (row0 >= M) return;
    int col0 = blockIdx.x * 128;

    A  += (size_t)ez * azoff;
    Bh += (size_t)ez * wz;
    if (TERMS == 3) Bl += (size_t)ez * wz;
    const int* gz = (GATHER || SCATTER) ? (gidx + ez * TT) : nullptr;
    size_t crow_base = (size_t)ez * (size_t)czoff;

    uint32_t sb = smem_u32(sm);
    int tid = threadIdx.x, lane = tid & 31, warp = tid >> 5;
    int m_base = (warp >> 2) * 64, n_base = (warp & 3) * 32;

    int l_row  = tid >> 1;
    int l_half = tid & 1;
    int gar = row0 + l_row;
    bool gav = gar < M;
    int garow = gav ? (GATHER ? gz[gar] : gar) : 0;
    const float* ap = A + (size_t)garow * K;
    const char* bhp = (const char*)(Bh + (size_t)(col0 + l_row) * K);
    const char* blp = (TERMS == 3) ? (const char*)(Bl + (size_t)(col0 + l_row) * K) : nullptr;
    uint32_t a_sts = sb + (uint32_t)(l_row * 20 + l_half * 8) * 4;
    uint32_t b_sts = sb + (uint32_t)(l_row * 20 + l_half * 8) * 4;

    uint32_t a_lrow = (uint32_t)(m_base + (lane & 7) + ((lane >> 3) & 1) * 8);
    uint32_t a_lcol = (uint32_t)((lane >> 4) * 4);
    int bl15 = lane & 15;
    uint32_t b_lrow = (uint32_t)(n_base + (bl15 & 7));
    uint32_t b_lcol = (uint32_t)(((bl15 >> 3) & 1) * 4);

    float acc[4][4][4];
    uint32_t accl[4][4][2];
    #pragma unroll
    for (int i = 0; i < 4; i++)
        #pragma unroll
        for (int j = 0; j < 4; j++) {
            #pragma unroll
            for (int q = 0; q < 4; q++) acc[i][j][q] = 0.f;
            accl[i][j][0] = 0u; accl[i][j][1] = 0u;
        }

    int nt = K >> 5;
    float4 pa[4];

    auto ldgA = [&](int kt) {
        const float* p = ap + kt * 32 + l_half * 16;
        if (gav) {
            pa[0] = *(const float4*)(p);
            pa[1] = *(const float4*)(p + 4);
            pa[2] = *(const float4*)(p + 8);
            pa[3] = *(const float4*)(p + 12);
        } else {
            pa[0] = pa[1] = pa[2] = pa[3] = make_float4(0.f, 0.f, 0.f, 0.f);
        }
    };
    auto cpB = [&](int kt, int buf) {
        uint32_t d = b_sts + buf * G_STG;
        const char* sh = bhp + (size_t)kt * 64 + l_half * 32;
        cp16(d + G_BH,      sh);
        cp16(d + G_BH + 16, sh + 16);
        if (TERMS == 3) {
            const char* sl = blp + (size_t)kt * 64 + l_half * 32;
            cp16(d + G_BL,      sl);
            cp16(d + G_BL + 16, sl + 16);
        }
        cp_commit();
    };
    auto stsA = [&](int buf) {
        uint32_t d = a_sts + buf * G_STG;
        if (TERMS >= 2) {
            uint32_t h[8], l[8];
            hsplit2(pa[0].x, pa[0].y, h[0], l[0]); hsplit2(pa[0].z, pa[0].w, h[1], l[1]);
            hsplit2(pa[1].x, pa[1].y, h[2], l[2]); hsplit2(pa[1].z, pa[1].w, h[3], l[3]);
            hsplit2(pa[2].x, pa[2].y, h[4], l[4]); hsplit2(pa[2].z, pa[2].w, h[5], l[5]);
            hsplit2(pa[3].x, pa[3].y, h[6], l[6]); hsplit2(pa[3].z, pa[3].w, h[7], l[7]);
            *(uint4*)(sm + (d - sb) + G_AH)      = *(uint4*)(h);
            *(uint4*)(sm + (d - sb) + G_AH + 16) = *(uint4*)(h + 4);
            *(uint4*)(sm + (d - sb) + G_AL)      = *(uint4*)(l);
            *(uint4*)(sm + (d - sb) + G_AL + 16) = *(uint4*)(l + 4);
        } else {
            uint32_t h[8];
            h[0] = hpack2(pa[0].x, pa[0].y); h[1] = hpack2(pa[0].z, pa[0].w);
            h[2] = hpack2(pa[1].x, pa[1].y); h[3] = hpack2(pa[1].z, pa[1].w);
            h[4] = hpack2(pa[2].x, pa[2].y); h[5] = hpack2(pa[2].z, pa[2].w);
            h[6] = hpack2(pa[3].x, pa[3].y); h[7] = hpack2(pa[3].z, pa[3].w);
            *(uint4*)(sm + (d - sb) + G_AH)      = *(uint4*)(h);
            *(uint4*)(sm + (d - sb) + G_AH + 16) = *(uint4*)(h + 4);
        }
    };

    ldgA(0); cpB(0, 0); stsA(0);
    cp_wait0();
    __syncthreads();

    for (int t = 0; t < nt; t++) {
        int cur = t & 1;
        if (t + 1 < nt) { ldgA(t + 1); cpB(t + 1, cur ^ 1); }
        uint32_t stage = sb + cur * G_STG;
        #pragma unroll
        for (int j = 0; j < 2; j++) {
            uint32_t a_h[4][4], a_l[4][4], b_h[4][2], b_l[4][2];
            #pragma unroll
            for (int mi = 0; mi < 4; mi++) {
                uint32_t ad = stage + ((a_lrow + mi * 16) * 20 + j * 8 + a_lcol) * 4;
                ldmx4(a_h[mi], ad + G_AH);
                if (TERMS >= 2) ldmx4(a_l[mi], ad + G_AL);
            }
            #pragma unroll
            for (int ni = 0; ni < 4; ni++) {
                uint32_t bd = stage + ((b_lrow + ni * 8) * 20 + j * 8 + b_lcol) * 4;
                ldmx2(b_h[ni], bd + G_BH);
                if (TERMS == 3) ldmx2(b_l[ni], bd + G_BL);
            }
            #pragma unroll
            for (int mi = 0; mi < 4; mi++)
                #pragma unroll
                for (int ni = 0; ni < 4; ni++) {
                    mma16f(acc[mi][ni],  a_h[mi], b_h[ni]);
                    if (TERMS >= 2)
                        mma16h(accl[mi][ni], a_l[mi], b_h[ni]);
                    if (TERMS == 3)
                        mma16h(accl[mi][ni], a_h[mi], b_l[ni]);
                }
        }
        if (t + 1 < nt) {
            stsA(cur ^ 1);
            cp_wait0();
            __syncthreads();
        }
    }

    int grp = lane >> 2, qid = lane & 3;
    #pragma unroll
    for (int mi = 0; mi < 4; mi++) {
        int r0 = row0 + m_base + mi * 16 + grp;
        int r1 = r0 + 8;
        bool v0 = r0 < M, v1 = r1 < M;
        size_t cr0 = 0, cr1 = 0;
        if (v0) cr0 = crow_base + (SCATTER ? (size_t)gz[r0] : (size_t)r0);
        if (v1) cr1 = crow_base + (SCATTER ? (size_t)gz[r1] : (size_t)r1);
        #pragma unroll
        for (int ni = 0; ni < 4; ni++) {
            int cb = col0 + n_base + ni * 8 + qid * 2;
            float2 f01 = make_float2(0.f, 0.f), f23 = make_float2(0.f, 0.f);
            if (TERMS >= 2) {
                f01 = __half22float2(*(__half2*)&accl[mi][ni][0]);
                f23 = __half22float2(*(__half2*)&accl[mi][ni][1]);
            }
            #pragma unroll
            for (int hf = 0; hf < 2; hf++) {
                bool valid = hf ? v1 : v0;
                if (!valid) continue;
                int rr = hf ? r1 : r0;
                size_t cr = hf ? cr1 : cr0;
                float e0 = acc[mi][ni][hf * 2 + 0] + (hf ? f23.x : f01.x);
                float e1 = acc[mi][ni][hf * 2 + 1] + (hf ? f23.y : f01.y);
                if (BIAS)  { e0 += bias[biasz * ez + cb]; e1 += bias[biasz * ez + cb + 1]; }
                if (CONDC) {
                    const float* cc = condc + (size_t)(rr >> 8) * Nn + cb;
                    e0 += cc[0]; e1 += cc[1];
                }
                if (GELU)  { e0 = gelu_f(e0); e1 = gelu_f(e1); }
                if (RESID) {
                    const float* rp = res + (size_t)rr * Nn + cb;
                    e0 += rp[0]; e1 += rp[1];
                }
                *(float2*)(C + cr * Nn + cb) = make_float2(e0, e1);
            }
        }
    }
}

// ---------------- legacy bf16-split GEMM (tiny condc only) ----------------
__global__ __launch_bounds__(256) void gemm_tc_plain(
    const float* __restrict__ A, const float* __restrict__ Bm, float* __restrict__ C,
    int M, int Nn, int K)
{
    int row0 = blockIdx.y * 128;
    if (row0 >= M) return;
    int col0 = blockIdx.x * 128;
    __shared__ uint32_t Ah[2][128][9];
    __shared__ uint32_t Al[2][128][9];
    __shared__ uint32_t Bh[2][8][132];
    __shared__ uint32_t Bl[2][8][132];
    int tid = threadIdx.x, lane = tid & 31, warp = tid >> 5;
    int grp = lane >> 2, qid = lane & 3;
    int m_base = (warp >> 2) * 64, n_base = (warp & 3) * 32;
    int a_r = tid >> 2, a_k4 = (tid & 3) * 4, a_kp = (tid & 3) * 2;
    int ar1 = row0 + a_r, ar2 = row0 + a_r + 64;
    bool av1 = ar1 < M, av2 = ar2 < M;
    int b_kp = tid >> 5, b_n4 = (tid & 31) * 4;
    float acc[4][4][4];
    #pragma unroll
    for (int i = 0; i < 4; i++)
        #pragma unroll
        for (int j = 0; j < 4; j++)
            #pragma unroll
            for (int q = 0; q < 4; q++) acc[i][j][q] = 0.f;
    int nt = K / 16;
    float4 ra0, ra1, rbE, rbO;
    ra0 = av1 ? *(const float4*)(A + (size_t)ar1 * K + a_k4) : make_float4(0,0,0,0);
    ra1 = av2 ? *(const float4*)(A + (size_t)ar2 * K + a_k4) : make_float4(0,0,0,0);
    rbE = *(const float4*)(Bm + (size_t)(2 * b_kp) * Nn + col0 + b_n4);
    rbO = *(const float4*)(Bm + (size_t)(2 * b_kp + 1) * Nn + col0 + b_n4);
    {
        uint32_t h0, l0, h1, l1;
        bfsplit2(ra0.x, ra0.y, h0, l0); bfsplit2(ra0.z, ra0.w, h1, l1);
        Ah[0][a_r][a_kp] = h0; Ah[0][a_r][a_kp+1] = h1; Al[0][a_r][a_kp] = l0; Al[0][a_r][a_kp+1] = l1;
        bfsplit2(ra1.x, ra1.y, h0, l0); bfsplit2(ra1.z, ra1.w, h1, l1);
        Ah[0][a_r+64][a_kp] = h0; Ah[0][a_r+64][a_kp+1] = h1; Al[0][a_r+64][a_kp] = l0; Al[0][a_r+64][a_kp+1] = l1;
        uint32_t bh4[4], bl4[4];
        bfsplit2(rbE.x, rbO.x, bh4[0], bl4[0]); bfsplit2(rbE.y, rbO.y, bh4[1], bl4[1]);
        bfsplit2(rbE.z, rbO.z, bh4[2], bl4[2]); bfsplit2(rbE.w, rbO.w, bh4[3], bl4[3]);
        *(uint4*)&Bh[0][b_kp][b_n4] = *(uint4*)bh4;
        *(uint4*)&Bl[0][b_kp][b_n4] = *(uint4*)bl4;
    }
    __syncthreads();
    for (int t = 0; t < nt; t++) {
        int cur = t & 1;
        if (t + 1 < nt) {
            int k0 = (t + 1) * 16;
            ra0 = av1 ? *(const float4*)(A + (size_t)ar1 * K + k0 + a_k4) : make_float4(0,0,0,0);
            ra1 = av2 ? *(const float4*)(A + (size_t)ar2 * K + k0 + a_k4) : make_float4(0,0,0,0);
            rbE = *(const float4*)(Bm + (size_t)(k0 + 2 * b_kp) * Nn + col0 + b_n4);
            rbO = *(const float4*)(Bm + (size_t)(k0 + 2 * b_kp + 1) * Nn + col0 + b_n4);
        }
        uint32_t a_h[4][4], a_l[4][4], b_h[4][2], b_l[4][2];
        #pragma unroll
        for (int mi = 0; mi < 4; mi++) {
            int rm = m_base + mi * 16 + grp;
            a_h[mi][0] = Ah[cur][rm][qid];         a_l[mi][0] = Al[cur][rm][qid];
            a_h[mi][1] = Ah[cur][rm + 8][qid];     a_l[mi][1] = Al[cur][rm + 8][qid];
            a_h[mi][2] = Ah[cur][rm][qid + 4];     a_l[mi][2] = Al[cur][rm][qid + 4];
            a_h[mi][3] = Ah[cur][rm + 8][qid + 4]; a_l[mi][3] = Al[cur][rm + 8][qid + 4];
        }
        #pragma unroll
        for (int ni = 0; ni < 4; ni++) {
            int cn = n_base + ni * 8 + grp;
            b_h[ni][0] = Bh[cur][qid][cn];     b_l[ni][0] = Bl[cur][qid][cn];
            b_h[ni][1] = Bh[cur][qid + 4][cn]; b_l[ni][1] = Bl[cur][qid + 4][cn];
        }
        #pragma unroll
        for (int mi = 0; mi < 4; mi++)
            #pragma unroll
            for (int ni = 0; ni < 4; ni++) {
                mma16bf(acc[mi][ni], a_h[mi], b_l[ni]);
                mma16bf(acc[mi][ni], a_l[mi], b_h[ni]);
                mma16bf(acc[mi][ni], a_h[mi], b_h[ni]);
            }
        if (t + 1 < nt) {
            int nxt = (t + 1) & 1;
            uint32_t h0, l0, h1, l1;
            bfsplit2(ra0.x, ra0.y, h0, l0); bfsplit2(ra0.z, ra0.w, h1, l1);
            Ah[nxt][a_r][a_kp] = h0; Ah[nxt][a_r][a_kp+1] = h1; Al[nxt][a_r][a_kp] = l0; Al[nxt][a_r][a_kp+1] = l1;
            bfsplit2(ra1.x, ra1.y, h0, l0); bfsplit2(ra1.z, ra1.w, h1, l1);
            Ah[nxt][a_r+64][a_kp] = h0; Ah[nxt][a_r+64][a_kp+1] = h1; Al[nxt][a_r+64][a_kp] = l0; Al[nxt][a_r+64][a_kp+1] = l1;
            uint32_t bh4[4], bl4[4];
            bfsplit2(rbE.x, rbO.x, bh4[0], bl4[0]); bfsplit2(rbE.y, rbO.y, bh4[1], bl4[1]);
            bfsplit2(rbE.z, rbO.z, bh4[2], bl4[2]); bfsplit2(rbE.w, rbO.w, bh4[3], bl4[3]);
            *(uint4*)&Bh[nxt][b_kp][b_n4] = *(uint4*)bh4;
            *(uint4*)&Bl[nxt][b_kp][b_n4] = *(uint4*)bl4;
            __syncthreads();
        }
    }
    #pragma unroll
    for (int mi = 0; mi < 4; mi++) {
        int r0 = row0 + m_base + mi * 16 + grp;
        int r1 = r0 + 8;
        #pragma unroll
        for (int ni = 0; ni < 4; ni++) {
            int cb = col0 + n_base + ni * 8 + qid * 2;
            if (r0 < M) *(float2*)(C + (size_t)r0 * Nn + cb) = make_float2(acc[mi][ni][0], acc[mi][ni][1]);
            if (r1 < M) *(float2*)(C + (size_t)r1 * Nn + cb) = make_float2(acc[mi][ni][2], acc[mi][ni][3]);
        }
    }
}

// ---------------- LayerNorm ----------------
__global__ __launch_bounds__(256) void ln_kernel(
    const float* __restrict__ x, const float* __restrict__ g,
    const float* __restrict__ bta, float* __restrict__ out)
{
    int t = blockIdx.x, tid = threadIdx.x;
    float4 v = ((const float4*)(x + (size_t)t * DIM))[tid];
    float s  = v.x + v.y + v.z + v.w;
    float sq = v.x * v.x + v.y * v.y + v.z * v.z + v.w * v.w;
    __shared__ float sh[8], sh2[8];
    float ws = warpsum(s), wq = warpsum(sq);
    if ((tid & 31) == 0) { sh[tid >> 5] = ws; sh2[tid >> 5] = wq; }
    __syncthreads();
    if (tid < 32) {
        float a  = (tid < 8) ? sh[tid]  : 0.f;
        float b2 = (tid < 8) ? sh2[tid] : 0.f;
        a = warpsum(a); b2 = warpsum(b2);
        if (tid == 0) { sh[0] = a; sh2[0] = b2; }
    }
    __syncthreads();
    float mu  = sh[0] * (1.0f / DIM);
    float var = sh2[0] * (1.0f / DIM) - mu * mu;
    float inv = rsqrtf(var + 1e-5f);
    float4 gg = ((const float4*)g)[tid], bb = ((const float4*)bta)[tid];
    float4 o;
    o.x = (v.x - mu) * inv * gg.x + bb.x;
    o.y = (v.y - mu) * inv * gg.y + bb.y;
    o.z = (v.z - mu) * inv * gg.z + bb.z;
    o.w = (v.w - mu) * inv * gg.w + bb.w;
    ((float4*)(out + (size_t)t * DIM))[tid] = o;
}

// ---------------- tensor-core attention ----------------
// S = 0.125 * Q K^T ; one 64x64 tile per CTA; 128 thr (4 warps x 16 q-rows)
__global__ __launch_bounds__(128) void attn_scores_tc(
    const float* __restrict__ qkv, float* __restrict__ S)
{
    int kt = blockIdx.x, qt = blockIdx.y, bh = blockIdx.z;
    int b = bh >> 4, h = bh & 15;
    __shared__ uint32_t Qs[64][36];
    __shared__ uint32_t Ks[64][36];
    int tid = threadIdx.x, lane = tid & 31, warp = tid >> 5;
    int l_row = tid >> 1, l_half = tid & 1;
    {
        const float* qp = qkv + (size_t)(b * NSEQ + qt * 64 + l_row) * 3 * DIM + h * HDIM + l_half * 32;
        const float* kp = qkv + (size_t)(b * NSEQ + kt * 64 + l_row) * 3 * DIM + DIM + h * HDIM + l_half * 32;
        uint32_t hq[16], hk[16];
        #pragma unroll
        for (int i = 0; i < 8; i++) {
            float4 q4 = *(const float4*)(qp + i * 4);
            float4 k4 = *(const float4*)(kp + i * 4);
            hq[i * 2]     = hpack2(q4.x, q4.y);
            hq[i * 2 + 1] = hpack2(q4.z, q4.w);
            hk[i * 2]     = hpack2(k4.x, k4.y);
            hk[i * 2 + 1] = hpack2(k4.z, k4.w);
        }
        #pragma unroll
        for (int i = 0; i < 4; i++) {
            *(uint4*)&Qs[l_row][l_half * 16 + i * 4] = *(uint4*)(hq + i * 4);
            *(uint4*)&Ks[l_row][l_half * 16 + i * 4] = *(uint4*)(hk + i * 4);
        }
    }
    __syncthreads();
    int m_base = warp * 16;
    uint32_t a_lrow = (uint32_t)(m_base + (lane & 7) + ((lane >> 3) & 1) * 8);
    uint32_t a_lcol = (uint32_t)((lane >> 4) * 4);
    int bl15 = lane & 15;
    float acc[8][4];
    #pragma unroll
    for (int i = 0; i < 8; i++)
        #pragma unroll
        for (int q = 0; q < 4; q++) acc[i][q] = 0.f;
    uint32_t qbase = smem_u32(Qs), kbase = smem_u32(Ks);
    #pragma unroll
    for (int j = 0; j < 4; j++) {
        uint32_t af[4];
        ldmx4(af, qbase + (a_lrow * 36 + j * 8 + a_lcol) * 4);
        #pragma unroll
        for (int ni = 0; ni < 8; ni++) {
            uint32_t bf[2];
            ldmx2(bf, kbase + ((uint32_t)(ni * 8 + (bl15 & 7)) * 36 + j * 8 + ((bl15 >> 3) & 1) * 4) * 4);
            mma16f(acc[ni], af, bf);
        }
    }
    int grp = lane >> 2, qid = lane & 3;
    float* Sp = S + (size_t)bh * NSEQ * NSEQ;
    int r0 = qt * 64 + m_base + grp;
    #pragma unroll
    for (int ni = 0; ni < 8; ni++) {
        int col = kt * 64 + ni * 8 + qid * 2;
        *(float2*)(Sp + (size_t)r0 * NSEQ + col)       = make_float2(acc[ni][0] * 0.125f, acc[ni][1] * 0.125f);
        *(float2*)(Sp + (size_t)(r0 + 8) * NSEQ + col) = make_float2(acc[ni][2] * 0.125f, acc[ni][3] * 0.125f);
    }
}

// softmax: S fp32 -> P fp16
__global__ __launch_bounds__(128) void softmax_kernel(
    const float* __restrict__ S, __half* __restrict__ P)
{
    size_t row = (size_t)blockIdx.x * 4 + (threadIdx.x >> 5);
    int lane = threadIdx.x & 31;
    const float* p = S + row * NSEQ;
    __half* pp = P + row * NSEQ;
    float v[8];
    float m = -1e30f;
    #pragma unroll
    for (int i = 0; i < 8; i++) { v[i] = p[lane + i * 32]; m = fmaxf(m, v[i]); }
    m = warpmax(m);
    float s = 0.f;
    #pragma unroll
    for (int i = 0; i < 8; i++) { v[i] = expf(v[i] - m); s += v[i]; }
    s = warpsum(s);
    float inv = 1.0f / s;
    #pragma unroll
    for (int i = 0; i < 8; i++) pp[lane + i * 32] = __float2half(v[i] * inv);
}

// O = P V : one 64q x 64d tile per CTA; V fed via ldmatrix.trans
__global__ __launch_bounds__(128) void attn_av_tc(
    const float* __restrict__ qkv, const __half* __restrict__ P, float* __restrict__ o)
{
    int qt = blockIdx.x, bh = blockIdx.y;
    int b = bh >> 4, h = bh & 15;
    __shared__ uint32_t Ps[64][36];
    __shared__ uint32_t Vs[64][36];
    int tid = threadIdx.x, lane = tid & 31, warp = tid >> 5;
    int l_row = tid >> 1, l_half = tid & 1;
    int m_base = warp * 16;
    uint32_t a_lrow = (uint32_t)(m_base + (lane & 7) + ((lane >> 3) & 1) * 8);
    uint32_t a_lcol = (uint32_t)((lane >> 4) * 4);
    int bl15 = lane & 15;
    float acc[8][4];
    #pragma unroll
    for (int i = 0; i < 8; i++)
        #pragma unroll
        for (int q = 0; q < 4; q++) acc[i][q] = 0.f;
    uint32_t pbase = smem_u32(Ps), vbase = smem_u32(Vs);
    const __half* Pp = P + (size_t)bh * NSEQ * NSEQ + (size_t)(qt * 64 + l_row) * NSEQ + l_half * 32;

    for (int c = 0; c < 4; c++) {
        // P chunk 64q x 64k fp16
        #pragma unroll
        for (int i = 0; i < 4; i++)
            *(uint4*)&Ps[l_row][l_half * 16 + i * 4] =
                *(const uint4*)((const char*)(Pp + c * 64) + i * 16);
        // V chunk [k=64][d=64], convert fp32 -> fp16
        {
            const float* vp = qkv + (size_t)(b * NSEQ + c * 64 + l_row) * 3 * DIM + 2 * DIM + h * HDIM + l_half * 32;
            uint32_t hv[16];
            #pragma unroll
            for (int i = 0; i < 8; i++) {
                float4 v4 = *(const float4*)(vp + i * 4);
                hv[i * 2]     = hpack2(v4.x, v4.y);
                hv[i * 2 + 1] = hpack2(v4.z, v4.w);
            }
            #pragma unroll
            for (int i = 0; i < 4; i++)
                *(uint4*)&Vs[l_row][l_half * 16 + i * 4] = *(uint4*)(hv + i * 4);
        }
        __syncthreads();
        #pragma unroll
        for (int j = 0; j < 4; j++) {
            uint32_t af[4];
            ldmx4(af, pbase + (a_lrow * 36 + j * 8 + a_lcol) * 4);
            #pragma unroll
            for (int ni = 0; ni < 8; ni++) {
                uint32_t bf[2];
                ldmx2t(bf, vbase + ((uint32_t)(j * 16 + bl15) * 36 + ni * 4) * 4);
                mma16f(acc[ni], af, bf);
            }
        }
        __syncthreads();
    }
    int grp = lane >> 2, qid = lane & 3;
    int r0 = qt * 64 + m_base + grp;
    #pragma unroll
    for (int ni = 0; ni < 8; ni++) {
        int d = ni * 8 + qid * 2;
        *(float2*)(o + (size_t)(b * NSEQ + r0) * DIM + h * HDIM + d)       = make_float2(acc[ni][0], acc[ni][1]);
        *(float2*)(o + (size_t)(b * NSEQ + r0 + 8) * DIM + h * HDIM + d)   = make_float2(acc[ni][2], acc[ni][3]);
    }
}

// ---------------- router ----------------
__global__ __launch_bounds__(128) void router_kernel(
    const float* __restrict__ gh, const float* __restrict__ W, const float* __restrict__ bias)
{
    int t = blockIdx.x;
    int wid = threadIdx.x >> 5, lane = threadIdx.x & 31;
    const float* row = gh + (size_t)t * RHC;
    float s = 0.f;
    for (int k = lane; k < RHC; k += 32) s += row[k] * W[k * NE + wid];
    s = warpsum(s);
    __shared__ float logits[NE];
    if (lane == 0) logits[wid] = s + bias[wid];
    __syncthreads();
    if (threadIdx.x == 0) {
        float l[NE], m = -1e30f;
        #pragma unroll
        for (int e = 0; e < NE; e++) { l[e] = logits[e]; m = fmaxf(m, l[e]); }
        float ssum = 0.f;
        #pragma unroll
        for (int e = 0; e < NE; e++) { l[e] = expf(l[e] - m); ssum += l[e]; }
        float p[NE];
        #pragma unroll
        for (int e = 0; e < NE; e++)
            p[e] = fminf(fmaxf(l[e] / ssum, 1e-9f), 1.0f - 1e-9f);
        int i1 = 0;
        #pragma unroll
        for (int e = 1; e < NE; e++) if (p[e] > p[i1]) i1 = e;
        int i2 = -1;
        #pragma unroll
        for (int e = 0; e < NE; e++) {
            if (e == i1) continue;
            if (i2 < 0 || p[e] > p[i2]) i2 = e;
        }
        float wsum = p[i1] + p[i2];
        int pos = atomicAdd(&g_cnt[i1], 1);
        g_idx[i1 * TT + pos] = t;
        pos = atomicAdd(&g_cnt[i2], 1);
        g_idx[i2 * TT + pos] = t;
        g_te[t] = make_int2(i1, i2);
        g_tw[t] = make_float2(p[i1] / wsum, p[i2] / wsum);
    }
}

__global__ void zero_cnt_kernel() {
    if (threadIdx.x < NE) g_cnt[threadIdx.x] = 0;
}

__global__ __launch_bounds__(256) void combine_kernel(
    const float* __restrict__ x1, const float* __restrict__ eout, float* __restrict__ out)
{
    int t = blockIdx.x, c = threadIdx.x;
    int2 e = g_te[t];
    float2 w = g_tw[t];
    float4 a  = ((const float4*)(x1 + (size_t)t * DIM))[c];
    float4 v1 = ((const float4*)(eout + ((size_t)e.x * TT + t) * DIM))[c];
    float4 v2 = ((const float4*)(eout + ((size_t)e.y * TT + t) * DIM))[c];
    float4 r;
    r.x = a.x + w.x * v1.x + w.y * v2.x;
    r.y = a.y + w.x * v1.y + w.y * v2.y;
    r.z = a.z + w.x * v1.z + w.y * v2.z;
    r.w = a.w + w.x * v1.w + w.y * v2.w;
    ((float4*)(out + (size_t)t * DIM))[c] = r;
}

// ---------------- host launcher ----------------
static void* symaddr(const void* s) {
    void* p = nullptr;
    cudaGetSymbolAddress(&p, s);
    return p;
}

extern "C" void kernel_launch(void* const* d_in, const int* in_sizes, int n_in,
                              void* d_out, int out_size) {
    const float* x       = (const float*)d_in[0];
    const float* cond    = (const float*)d_in[1];
    const float* ln1_g   = (const float*)d_in[2];
    const float* ln1_b   = (const float*)d_in[3];
    const float* qkv_w   = (const float*)d_in[4];
    const float* proj_w  = (const float*)d_in[5];
    const float* proj_b  = (const float*)d_in[6];
    const float* ln2_g   = (const float*)d_in[7];
    const float* ln2_b   = (const float*)d_in[8];
    const float* r_fc1_w = (const float*)d_in[9];
    const float* r_fc1_b = (const float*)d_in[10];
    const float* r_fc2_w = (const float*)d_in[11];
    const float* r_fc2_b = (const float*)d_in[12];
    const float* e_w1    = (const float*)d_in[13];
    const float* e_b1    = (const float*)d_in[14];
    const float* e_w2    = (const float*)d_in[15];
    const float* e_b2    = (const float*)d_in[16];
    float* out = (float*)d_out;

    float* h1    = (float*)symaddr(g_h1);
    float* qkv   = (float*)symaddr(g_qkv);
    float* S     = (float*)symaddr(g_S);
    __half* P    = (__half*)symaddr(g_P);
    float* o     = (float*)symaddr(g_o);
    float* x1    = (float*)symaddr(g_x1);
    float* h2    = (float*)symaddr(g_h2);
    float* condc = (float*)symaddr(g_condc);
    float* gh    = (float*)symaddr(g_gh);
    float* hid   = (float*)symaddr(g_hid);
    float* eout  = (float*)symaddr(g_eout);
    int*   cnt   = (int*)symaddr(g_cnt);
    int*   idx   = (int*)symaddr(g_idx);
    __half* wqkv_h  = (__half*)symaddr(g_wqkv_h);
    __half* wqkv_l  = (__half*)symaddr(g_wqkv_l);
    __half* wproj_h = (__half*)symaddr(g_wproj_h);
    __half* wproj_l = (__half*)symaddr(g_wproj_l);
    __half* wfc1_h  = (__half*)symaddr(g_wfc1_h);
    __half* wfc1_l  = (__half*)symaddr(g_wfc1_l);
    __half* we1_h   = (__half*)symaddr(g_we1_h);
    __half* we2_h   = (__half*)symaddr(g_we2_h);

    cudaFuncSetAttribute(gemm_tc2<3,false,false,false,false,false,false>,
                         cudaFuncAttributeMaxDynamicSharedMemorySize, G_SMEM);
    cudaFuncSetAttribute(gemm_tc2<3,false,false,true,false,true,false>,
                         cudaFuncAttributeMaxDynamicSharedMemorySize, G_SMEM);
    cudaFuncSetAttribute(gemm_tc2<3,false,false,true,true,false,true>,
                         cudaFuncAttributeMaxDynamicSharedMemorySize, G_SMEM);
    cudaFuncSetAttribute(gemm_tc2<1,true,false,true,true,false,false>,
                         cudaFuncAttributeMaxDynamicSharedMemorySize, G_SMEM);
    cudaFuncSetAttribute(gemm_tc2<1,false,true,true,false,false,false>,
                         cudaFuncAttributeMaxDynamicSharedMemorySize, G_SMEM);

    zero_cnt_kernel<<<1, 32>>>();

    // pre-split weights
    wsplit_kernel<<<dim3(3 * DIM / 32, DIM / 32, 1), 256>>>(qkv_w, wqkv_h, wqkv_l, DIM, 3 * DIM, 3 * DIM, 0, 0);
    wsplit_kernel<<<dim3(DIM / 32, DIM / 32, 1), 256>>>(proj_w, wproj_h, wproj_l, DIM, DIM, DIM, 0, 0);
    wsplit_kernel<<<dim3(RHC / 32, DIM / 32, 1), 256>>>(r_fc1_w, wfc1_h, wfc1_l, DIM, RHC, RHC, 0, 0);
    wsplit_kernel<<<dim3(DFFC / 32, DIM / 32, NE), 256>>>(e_w1, we1_h, nullptr, DIM, DFFC, DFFC,
                                                          (size_t)DIM * DFFC, (size_t)DFFC * DIM);
    wsplit_kernel<<<dim3(DIM / 32, DFFC / 32, NE), 256>>>(e_w2, we2_h, nullptr, DFFC, DIM, DIM,
                                                          (size_t)DFFC * DIM, (size_t)DIM * DFFC);

    // LN1
    ln_kernel<<<TT, 256>>>(x, ln1_g, ln1_b, h1);

    // QKV = h1 @ qkv_w (3-term)
    gemm_tc2<3,false,false,false,false,false,false>
        <<<dim3(3 * DIM / 128, TT / 128, 1), 256, G_SMEM>>>(h1, wqkv_h, wqkv_l, qkv, TT, 3 * DIM, DIM,
            nullptr, 0, nullptr, nullptr, nullptr, nullptr, 0, 0, 0);

    // attention (fp16 tensor cores)
    attn_scores_tc<<<dim3(4, 4, BB * NH), 128>>>(qkv, S);
    softmax_kernel<<<BB * NH * NSEQ / 4, 128>>>(S, P);
    attn_av_tc<<<dim3(4, BB * NH), 128>>>(qkv, P, o);

    // x1 = x + o @ proj_w + proj_b (3-term)
    gemm_tc2<3,false,false,true,false,true,false>
        <<<dim3(DIM / 128, TT / 128, 1), 256, G_SMEM>>>(o, wproj_h, wproj_l, x1, TT, DIM, DIM,
            proj_b, 0, x, nullptr, nullptr, nullptr, 0, 0, 0);

    // LN2
    ln_kernel<<<TT, 256>>>(x1, ln2_g, ln2_b, h2);

    // condc
    gemm_tc_plain<<<dim3(RHC / 128, 1), 256>>>(cond, r_fc1_w + (size_t)DIM * RHC, condc, BB, RHC, CDIM);

    // gh = gelu(h2 @ r_fc1_w[:D] + condc[b] + b1) (3-term)
    gemm_tc2<3,false,false,true,true,false,true>
        <<<dim3(RHC / 128, TT / 128, 1), 256, G_SMEM>>>(h2, wfc1_h, wfc1_l, gh, TT, RHC, DIM,
            r_fc1_b, 0, nullptr, condc, nullptr, nullptr, 0, 0, 0);

    // router
    router_kernel<<<TT, 128>>>(gh, r_fc2_w, r_fc2_b);

    // experts (1-term fp16), merged across NE
    gemm_tc2<1,true,false,true,true,false,false>
        <<<dim3(DFFC / 128, TT / 128, NE), 256, G_SMEM>>>(h2, we1_h, nullptr, hid,
            TT, DFFC, DIM, e_b1, DFFC, nullptr, nullptr,
            idx, cnt, (size_t)DFFC * DIM, 0, TT);
    gemm_tc2<1,false,true,true,false,false,false>
        <<<dim3(DIM / 128, TT / 128, NE), 256, G_SMEM>>>(hid, we2_h, nullptr, eout,
            TT, DIM, DFFC, e_b2, DIM, nullptr, nullptr,
            idx, cnt, (size_t)DIM * DFFC, (size_t)TT * DFFC, TT);

    // out = x1 + w1*eout[e1] + w2*eout[e2]
    combine_kernel<<<TT, 256>>>(x1, eout, out);
}

// round 15
// speedup vs baseline: 4.6927x; 1.0536x over previous
#include <cuda_runtime.h>
#include <cuda_bf16.h>
#include <cuda_fp16.h>
#include <math.h>
#include <stdint.h>

// ---------------- problem constants ----------------
constexpr int BB   = 32;
constexpr int NSEQ = 256;
constexpr int DIM  = 1024;
constexpr int NH   = 16;
constexpr int HDIM = 64;
constexpr int CDIM = 1024;
constexpr int NE   = 4;
constexpr int DFFC = 4096;
constexpr int RHC  = 2048;
constexpr int TT   = BB * NSEQ;   // 8192 tokens

// ---------------- scratch (device globals; no allocation allowed) ----------------
__device__ float g_h1[TT * DIM];
__device__ float g_qkv[TT * 3 * DIM];
__device__ float g_S[(size_t)BB * NH * NSEQ * NSEQ];
__device__ __half g_P[(size_t)BB * NH * NSEQ * NSEQ];
__device__ float g_o[TT * DIM];
__device__ float g_x1[TT * DIM];
__device__ float g_h2[TT * DIM];
__device__ float g_condc[BB * RHC];
__device__ float g_gh[(size_t)TT * RHC];
__device__ float g_hid[(size_t)NE * TT * DFFC];
__device__ float g_eout[(size_t)NE * TT * DIM];
__device__ int   g_cnt[NE];
__device__ int   g_idx[NE * TT];
__device__ int2   g_te[TT];
__device__ float2 g_tw[TT];

// pre-split K-major weights: [N][K] fp16; lo only where needed (fc1)
__device__ __half g_wqkv_h[(size_t)3 * DIM * DIM];
__device__ __half g_wproj_h[(size_t)DIM * DIM];
__device__ __half g_wfc1_h[(size_t)RHC * DIM];
__device__ __half g_wfc1_l[(size_t)RHC * DIM];
__device__ __half g_we1_h[(size_t)NE * DFFC * DIM];
__device__ __half g_we2_h[(size_t)NE * DIM * DFFC];

// ---------------- helpers ----------------
__device__ __forceinline__ float warpsum(float v) {
    #pragma unroll
    for (int o = 16; o; o >>= 1) v += __shfl_xor_sync(0xFFFFFFFFu, v, o);
    return v;
}
__device__ __forceinline__ float warpmax(float v) {
    #pragma unroll
    for (int o = 16; o; o >>= 1) v = fmaxf(v, __shfl_xor_sync(0xFFFFFFFFu, v, o));
    return v;
}
__device__ __forceinline__ float gelu_f(float x) {
    return 0.5f * x * (1.0f + erff(x * 0.70710678118654752f));
}
__device__ __forceinline__ void hsplit2(float x0, float x1, uint32_t& hi, uint32_t& lo) {
    __half2 h = __floats2half2_rn(x0, x1);
    float r0 = x0 - __half2float(__low2half(h));
    float r1 = x1 - __half2float(__high2half(h));
    __half2 l = __floats2half2_rn(r0, r1);
    hi = *reinterpret_cast<uint32_t*>(&h);
    lo = *reinterpret_cast<uint32_t*>(&l);
}
__device__ __forceinline__ uint32_t hpack2(float x0, float x1) {
    __half2 h = __floats2half2_rn(x0, x1);
    return *reinterpret_cast<uint32_t*>(&h);
}
__device__ __forceinline__ void bfsplit2(float x0, float x1, uint32_t& hi, uint32_t& lo) {
    __nv_bfloat162 h = __floats2bfloat162_rn(x0, x1);
    float r0 = x0 - __bfloat162float(h.x);
    float r1 = x1 - __bfloat162float(h.y);
    __nv_bfloat162 l = __floats2bfloat162_rn(r0, r1);
    hi = *reinterpret_cast<uint32_t*>(&h);
    lo = *reinterpret_cast<uint32_t*>(&l);
}
__device__ __forceinline__ void mma16bf(float* c, const uint32_t* a, const uint32_t* b) {
    asm("mma.sync.aligned.m16n8k16.row.col.f32.bf16.bf16.f32 "
        "{%0,%1,%2,%3}, {%4,%5,%6,%7}, {%8,%9}, {%0,%1,%2,%3};"
        : "+f"(c[0]), "+f"(c[1]), "+f"(c[2]), "+f"(c[3])
        : "r"(a[0]), "r"(a[1]), "r"(a[2]), "r"(a[3]), "r"(b[0]), "r"(b[1]));
}
__device__ __forceinline__ void mma16f(float* c, const uint32_t* a, const uint32_t* b) {
    asm("mma.sync.aligned.m16n8k16.row.col.f32.f16.f16.f32 "
        "{%0,%1,%2,%3}, {%4,%5,%6,%7}, {%8,%9}, {%0,%1,%2,%3};"
        : "+f"(c[0]), "+f"(c[1]), "+f"(c[2]), "+f"(c[3])
        : "r"(a[0]), "r"(a[1]), "r"(a[2]), "r"(a[3]), "r"(b[0]), "r"(b[1]));
}
__device__ __forceinline__ void mma16h(uint32_t* c, const uint32_t* a, const uint32_t* b) {
    asm("mma.sync.aligned.m16n8k16.row.col.f16.f16.f16.f16 "
        "{%0,%1}, {%2,%3,%4,%5}, {%6,%7}, {%0,%1};"
        : "+r"(c[0]), "+r"(c[1])
        : "r"(a[0]), "r"(a[1]), "r"(a[2]), "r"(a[3]), "r"(b[0]), "r"(b[1]));
}
__device__ __forceinline__ void ldmx4(uint32_t* r, uint32_t a) {
    asm volatile("ldmatrix.sync.aligned.m8n8.x4.shared.b16 {%0,%1,%2,%3}, [%4];"
        : "=r"(r[0]), "=r"(r[1]), "=r"(r[2]), "=r"(r[3]) : "r"(a));
}
__device__ __forceinline__ void ldmx2(uint32_t* r, uint32_t a) {
    asm volatile("ldmatrix.sync.aligned.m8n8.x2.shared.b16 {%0,%1}, [%2];"
        : "=r"(r[0]), "=r"(r[1]) : "r"(a));
}
__device__ __forceinline__ void ldmx2t(uint32_t* r, uint32_t a) {
    asm volatile("ldmatrix.sync.aligned.m8n8.x2.trans.shared.b16 {%0,%1}, [%2];"
        : "=r"(r[0]), "=r"(r[1]) : "r"(a));
}
__device__ __forceinline__ uint32_t smem_u32(const void* p) {
    uint32_t a;
    asm("{ .reg .u64 t; cvta.to.shared.u64 t, %1; cvt.u32.u64 %0, t; }" : "=r"(a) : "l"(p));
    return a;
}
__device__ __forceinline__ void cp16(uint32_t dst, const void* src) {
    asm volatile("cp.async.ca.shared.global [%0], [%1], 16;" :: "r"(dst), "l"(src));
}
__device__ __forceinline__ void cp_commit() { asm volatile("cp.async.commit_group;" ::: "memory"); }
__device__ __forceinline__ void cp_wait0()  { asm volatile("cp.async.wait_group 0;" ::: "memory"); }

// ---------------- weight transpose + split: W[K,N] -> Wh(/Wl)[N,K] fp16 ----------------
__global__ __launch_bounds__(256) void wsplit_kernel(
    const float* __restrict__ W, __half* __restrict__ Wh, __half* __restrict__ Wl,
    int K, int Nn, int ld, size_t wz, size_t oz)
{
    __shared__ float ts[32][33];
    int z = blockIdx.z;
    const float* Wp = W + (size_t)z * wz;
    int n0 = blockIdx.x * 32, k0 = blockIdx.y * 32;
    int tx = threadIdx.x & 31, ty = threadIdx.x >> 5;
    #pragma unroll
    for (int i = 0; i < 4; i++)
        ts[ty + i * 8][tx] = Wp[(size_t)(k0 + ty + i * 8) * ld + n0 + tx];
    __syncthreads();
    #pragma unroll
    for (int i = 0; i < 4; i++) {
        int n = n0 + ty + i * 8, k = k0 + tx;
        float v = ts[tx][ty + i * 8];
        __half h = __float2half(v);
        Wh[(size_t)z * oz + (size_t)n * K + k] = h;
        if (Wl) Wl[(size_t)z * oz + (size_t)n * K + k] = __float2half(v - __half2float(h));
    }
}

// ---------------- fp16 split GEMM (TERMS=3 / 2 / 1) ----------------
// TERMS=3: AhBh(f32) + AlBh(f16) + AhBl(f16); TERMS=2: AhBh + AlBh; TERMS=1: AhBh.
constexpr int G_AH = 0;
constexpr int G_AL = 10240;
constexpr int G_BH = 20480;
constexpr int G_BL = 30720;
constexpr int G_STG = 40960;
constexpr int G_SMEM = 2 * G_STG;     // 81920

template<int TERMS, bool GATHER, bool SCATTER, bool BIAS, bool GELU, bool RESID, bool CONDC>
__global__ __launch_bounds__(256) void gemm_tc2(
    const float* __restrict__ A,
    const __half* __restrict__ Bh, const __half* __restrict__ Bl,
    float* __restrict__ C, int M, int Nn, int K,
    const float* __restrict__ bias, int biasz,
    const float* __restrict__ res, const float* __restrict__ condc,
    const int* __restrict__ gidx, const int* __restrict__ cntp,
    size_t wz, size_t azoff, int czoff)
{
    extern __shared__ char sm[];
    int ez = blockIdx.z;
    if (cntp) M = cntp[ez];
    int row0 = blockIdx.y * 128;
    if (row0 >= M) return;
    int col0 = blockIdx.x * 128;

    A  += (size_t)ez * azoff;
    Bh += (size_t)ez * wz;
    if (TERMS == 3) Bl += (size_t)ez * wz;
    const int* gz = (GATHER || SCATTER) ? (gidx + ez * TT) : nullptr;
    size_t crow_base = (size_t)ez * (size_t)czoff;

    uint32_t sb = smem_u32(sm);
    int tid = threadIdx.x, lane = tid & 31, warp = tid >> 5;
    int m_base = (warp >> 2) * 64, n_base = (warp & 3) * 32;

    int l_row  = tid >> 1;
    int l_half = tid & 1;
    int gar = row0 + l_row;
    bool gav = gar < M;
    int garow = gav ? (GATHER ? gz[gar] : gar) : 0;
    const float* ap = A + (size_t)garow * K;
    const char* bhp = (const char*)(Bh + (size_t)(col0 + l_row) * K);
    const char* blp = (TERMS == 3) ? (const char*)(Bl + (size_t)(col0 + l_row) * K) : nullptr;
    uint32_t a_sts = sb + (uint32_t)(l_row * 20 + l_half * 8) * 4;
    uint32_t b_sts = sb + (uint32_t)(l_row * 20 + l_half * 8) * 4;

    uint32_t a_lrow = (uint32_t)(m_base + (lane & 7) + ((lane >> 3) & 1) * 8);
    uint32_t a_lcol = (uint32_t)((lane >> 4) * 4);
    int bl15 = lane & 15;
    uint32_t b_lrow = (uint32_t)(n_base + (bl15 & 7));
    uint32_t b_lcol = (uint32_t)(((bl15 >> 3) & 1) * 4);

    float acc[4][4][4];
    uint32_t accl[4][4][2];
    #pragma unroll
    for (int i = 0; i < 4; i++)
        #pragma unroll
        for (int j = 0; j < 4; j++) {
            #pragma unroll
            for (int q = 0; q < 4; q++) acc[i][j][q] = 0.f;
            accl[i][j][0] = 0u; accl[i][j][1] = 0u;
        }

    int nt = K >> 5;
    float4 pa[4];

    auto ldgA = [&](int kt) {
        const float* p = ap + kt * 32 + l_half * 16;
        if (gav) {
            pa[0] = *(const float4*)(p);
            pa[1] = *(const float4*)(p + 4);
            pa[2] = *(const float4*)(p + 8);
            pa[3] = *(const float4*)(p + 12);
        } else {
            pa[0] = pa[1] = pa[2] = pa[3] = make_float4(0.f, 0.f, 0.f, 0.f);
        }
    };
    auto cpB = [&](int kt, int buf) {
        uint32_t d = b_sts + buf * G_STG;
        const char* sh = bhp + (size_t)kt * 64 + l_half * 32;
        cp16(d + G_BH,      sh);
        cp16(d + G_BH + 16, sh + 16);
        if (TERMS == 3) {
            const char* sl = blp + (size_t)kt * 64 + l_half * 32;
            cp16(d + G_BL,      sl);
            cp16(d + G_BL + 16, sl + 16);
        }
        cp_commit();
    };
    auto stsA = [&](int buf) {
        uint32_t d = a_sts + buf * G_STG;
        if (TERMS >= 2) {
            uint32_t h[8], l[8];
            hsplit2(pa[0].x, pa[0].y, h[0], l[0]); hsplit2(pa[0].z, pa[0].w, h[1], l[1]);
            hsplit2(pa[1].x, pa[1].y, h[2], l[2]); hsplit2(pa[1].z, pa[1].w, h[3], l[3]);
            hsplit2(pa[2].x, pa[2].y, h[4], l[4]); hsplit2(pa[2].z, pa[2].w, h[5], l[5]);
            hsplit2(pa[3].x, pa[3].y, h[6], l[6]); hsplit2(pa[3].z, pa[3].w, h[7], l[7]);
            *(uint4*)(sm + (d - sb) + G_AH)      = *(uint4*)(h);
            *(uint4*)(sm + (d - sb) + G_AH + 16) = *(uint4*)(h + 4);
            *(uint4*)(sm + (d - sb) + G_AL)      = *(uint4*)(l);
            *(uint4*)(sm + (d - sb) + G_AL + 16) = *(uint4*)(l + 4);
        } else {
            uint32_t h[8];
            h[0] = hpack2(pa[0].x, pa[0].y); h[1] = hpack2(pa[0].z, pa[0].w);
            h[2] = hpack2(pa[1].x, pa[1].y); h[3] = hpack2(pa[1].z, pa[1].w);
            h[4] = hpack2(pa[2].x, pa[2].y); h[5] = hpack2(pa[2].z, pa[2].w);
            h[6] = hpack2(pa[3].x, pa[3].y); h[7] = hpack2(pa[3].z, pa[3].w);
            *(uint4*)(sm + (d - sb) + G_AH)      = *(uint4*)(h);
            *(uint4*)(sm + (d - sb) + G_AH + 16) = *(uint4*)(h + 4);
        }
    };

    ldgA(0); cpB(0, 0); stsA(0);
    cp_wait0();
    __syncthreads();

    for (int t = 0; t < nt; t++) {
        int cur = t & 1;
        if (t + 1 < nt) { ldgA(t + 1); cpB(t + 1, cur ^ 1); }
        uint32_t stage = sb + cur * G_STG;
        #pragma unroll
        for (int j = 0; j < 2; j++) {
            uint32_t a_h[4][4], a_l[4][4], b_h[4][2], b_l[4][2];
            #pragma unroll
            for (int mi = 0; mi < 4; mi++) {
                uint32_t ad = stage + ((a_lrow + mi * 16) * 20 + j * 8 + a_lcol) * 4;
                ldmx4(a_h[mi], ad + G_AH);
                if (TERMS >= 2) ldmx4(a_l[mi], ad + G_AL);
            }
            #pragma unroll
            for (int ni = 0; ni < 4; ni++) {
                uint32_t bd = stage + ((b_lrow + ni * 8) * 20 + j * 8 + b_lcol) * 4;
                ldmx2(b_h[ni], bd + G_BH);
                if (TERMS == 3) ldmx2(b_l[ni], bd + G_BL);
            }
            #pragma unroll
            for (int mi = 0; mi < 4; mi++)
                #pragma unroll
                for (int ni = 0; ni < 4; ni++) {
                    mma16f(acc[mi][ni],  a_h[mi], b_h[ni]);       // hi*hi, fp32 accum
                    if (TERMS >= 2)
                        mma16h(accl[mi][ni], a_l[mi], b_h[ni]);   // lo*hi, fp16 accum
                    if (TERMS == 3)
                        mma16h(accl[mi][ni], a_h[mi], b_l[ni]);   // hi*lo, fp16 accum
                }
        }
        if (t + 1 < nt) {
            stsA(cur ^ 1);
            cp_wait0();
            __syncthreads();
        }
    }

    int grp = lane >> 2, qid = lane & 3;
    #pragma unroll
    for (int mi = 0; mi < 4; mi++) {
        int r0 = row0 + m_base + mi * 16 + grp;
        int r1 = r0 + 8;
        bool v0 = r0 < M, v1 = r1 < M;
        size_t cr0 = 0, cr1 = 0;
        if (v0) cr0 = crow_base + (SCATTER ? (size_t)gz[r0] : (size_t)r0);
        if (v1) cr1 = crow_base + (SCATTER ? (size_t)gz[r1] : (size_t)r1);
        #pragma unroll
        for (int ni = 0; ni < 4; ni++) {
            int cb = col0 + n_base + ni * 8 + qid * 2;
            float2 f01 = make_float2(0.f, 0.f), f23 = make_float2(0.f, 0.f);
            if (TERMS >= 2) {
                f01 = __half22float2(*(__half2*)&accl[mi][ni][0]);
                f23 = __half22float2(*(__half2*)&accl[mi][ni][1]);
            }
            #pragma unroll
            for (int hf = 0; hf < 2; hf++) {
                bool valid = hf ? v1 : v0;
                if (!valid) continue;
                int rr = hf ? r1 : r0;
                size_t cr = hf ? cr1 : cr0;
                float e0 = acc[mi][ni][hf * 2 + 0] + (hf ? f23.x : f01.x);
                float e1 = acc[mi][ni][hf * 2 + 1] + (hf ? f23.y : f01.y);
                if (BIAS)  { e0 += bias[biasz * ez + cb]; e1 += bias[biasz * ez + cb + 1]; }
                if (CONDC) {
                    const float* cc = condc + (size_t)(rr >> 8) * Nn + cb;
                    e0 += cc[0]; e1 += cc[1];
                }
                if (GELU)  { e0 = gelu_f(e0); e1 = gelu_f(e1); }
                if (RESID) {
                    const float* rp = res + (size_t)rr * Nn + cb;
                    e0 += rp[0]; e1 += rp[1];
                }
                *(float2*)(C + cr * Nn + cb) = make_float2(e0, e1);
            }
        }
    }
}

// ---------------- legacy bf16-split GEMM (tiny condc only) ----------------
__global__ __launch_bounds__(256) void gemm_tc_plain(
    const float* __restrict__ A, const float* __restrict__ Bm, float* __restrict__ C,
    int M, int Nn, int K)
{
    int row0 = blockIdx.y * 128;
    if (row0 >= M) return;
    int col0 = blockIdx.x * 128;
    __shared__ uint32_t Ah[2][128][9];
    __shared__ uint32_t Al[2][128][9];
    __shared__ uint32_t Bh[2][8][132];
    __shared__ uint32_t Bl[2][8][132];
    int tid = threadIdx.x, lane = tid & 31, warp = tid >> 5;
    int grp = lane >> 2, qid = lane & 3;
    int m_base = (warp >> 2) * 64, n_base = (warp & 3) * 32;
    int a_r = tid >> 2, a_k4 = (tid & 3) * 4, a_kp = (tid & 3) * 2;
    int ar1 = row0 + a_r, ar2 = row0 + a_r + 64;
    bool av1 = ar1 < M, av2 = ar2 < M;
    int b_kp = tid >> 5, b_n4 = (tid & 31) * 4;
    float acc[4][4][4];
    #pragma unroll
    for (int i = 0; i < 4; i++)
        #pragma unroll
        for (int j = 0; j < 4; j++)
            #pragma unroll
            for (int q = 0; q < 4; q++) acc[i][j][q] = 0.f;
    int nt = K / 16;
    float4 ra0, ra1, rbE, rbO;
    ra0 = av1 ? *(const float4*)(A + (size_t)ar1 * K + a_k4) : make_float4(0,0,0,0);
    ra1 = av2 ? *(const float4*)(A + (size_t)ar2 * K + a_k4) : make_float4(0,0,0,0);
    rbE = *(const float4*)(Bm + (size_t)(2 * b_kp) * Nn + col0 + b_n4);
    rbO = *(const float4*)(Bm + (size_t)(2 * b_kp + 1) * Nn + col0 + b_n4);
    {
        uint32_t h0, l0, h1, l1;
        bfsplit2(ra0.x, ra0.y, h0, l0); bfsplit2(ra0.z, ra0.w, h1, l1);
        Ah[0][a_r][a_kp] = h0; Ah[0][a_r][a_kp+1] = h1; Al[0][a_r][a_kp] = l0; Al[0][a_r][a_kp+1] = l1;
        bfsplit2(ra1.x, ra1.y, h0, l0); bfsplit2(ra1.z, ra1.w, h1, l1);
        Ah[0][a_r+64][a_kp] = h0; Ah[0][a_r+64][a_kp+1] = h1; Al[0][a_r+64][a_kp] = l0; Al[0][a_r+64][a_kp+1] = l1;
        uint32_t bh4[4], bl4[4];
        bfsplit2(rbE.x, rbO.x, bh4[0], bl4[0]); bfsplit2(rbE.y, rbO.y, bh4[1], bl4[1]);
        bfsplit2(rbE.z, rbO.z, bh4[2], bl4[2]); bfsplit2(rbE.w, rbO.w, bh4[3], bl4[3]);
        *(uint4*)&Bh[0][b_kp][b_n4] = *(uint4*)bh4;
        *(uint4*)&Bl[0][b_kp][b_n4] = *(uint4*)bl4;
    }
    __syncthreads();
    for (int t = 0; t < nt; t++) {
        int cur = t & 1;
        if (t + 1 < nt) {
            int k0 = (t + 1) * 16;
            ra0 = av1 ? *(const float4*)(A + (size_t)ar1 * K + k0 + a_k4) : make_float4(0,0,0,0);
            ra1 = av2 ? *(const float4*)(A + (size_t)ar2 * K + k0 + a_k4) : make_float4(0,0,0,0);
            rbE = *(const float4*)(Bm + (size_t)(k0 + 2 * b_kp) * Nn + col0 + b_n4);
            rbO = *(const float4*)(Bm + (size_t)(k0 + 2 * b_kp + 1) * Nn + col0 + b_n4);
        }
        uint32_t a_h[4][4], a_l[4][4], b_h[4][2], b_l[4][2];
        #pragma unroll
        for (int mi = 0; mi < 4; mi++) {
            int rm = m_base + mi * 16 + grp;
            a_h[mi][0] = Ah[cur][rm][qid];         a_l[mi][0] = Al[cur][rm][qid];
            a_h[mi][1] = Ah[cur][rm + 8][qid];     a_l[mi][1] = Al[cur][rm + 8][qid];
            a_h[mi][2] = Ah[cur][rm][qid + 4];     a_l[mi][2] = Al[cur][rm][qid + 4];
            a_h[mi][3] = Ah[cur][rm + 8][qid + 4]; a_l[mi][3] = Al[cur][rm + 8][qid + 4];
        }
        #pragma unroll
        for (int ni = 0; ni < 4; ni++) {
            int cn = n_base + ni * 8 + grp;
            b_h[ni][0] = Bh[cur][qid][cn];     b_l[ni][0] = Bl[cur][qid][cn];
            b_h[ni][1] = Bh[cur][qid + 4][cn]; b_l[ni][1] = Bl[cur][qid + 4][cn];
        }
        #pragma unroll
        for (int mi = 0; mi < 4; mi++)
            #pragma unroll
            for (int ni = 0; ni < 4; ni++) {
                mma16bf(acc[mi][ni], a_h[mi], b_l[ni]);
                mma16bf(acc[mi][ni], a_l[mi], b_h[ni]);
                mma16bf(acc[mi][ni], a_h[mi], b_h[ni]);
            }
        if (t + 1 < nt) {
            int nxt = (t + 1) & 1;
            uint32_t h0, l0, h1, l1;
            bfsplit2(ra0.x, ra0.y, h0, l0); bfsplit2(ra0.z, ra0.w, h1, l1);
            Ah[nxt][a_r][a_kp] = h0; Ah[nxt][a_r][a_kp+1] = h1; Al[nxt][a_r][a_kp] = l0; Al[nxt][a_r][a_kp+1] = l1;
            bfsplit2(ra1.x, ra1.y, h0, l0); bfsplit2(ra1.z, ra1.w, h1, l1);
            Ah[nxt][a_r+64][a_kp] = h0; Ah[nxt][a_r+64][a_kp+1] = h1; Al[nxt][a_r+64][a_kp] = l0; Al[nxt][a_r+64][a_kp+1] = l1;
            uint32_t bh4[4], bl4[4];
            bfsplit2(rbE.x, rbO.x, bh4[0], bl4[0]); bfsplit2(rbE.y, rbO.y, bh4[1], bl4[1]);
            bfsplit2(rbE.z, rbO.z, bh4[2], bl4[2]); bfsplit2(rbE.w, rbO.w, bh4[3], bl4[3]);
            *(uint4*)&Bh[nxt][b_kp][b_n4] = *(uint4*)bh4;
            *(uint4*)&Bl[nxt][b_kp][b_n4] = *(uint4*)bl4;
            __syncthreads();
        }
    }
    #pragma unroll
    for (int mi = 0; mi < 4; mi++) {
        int r0 = row0 + m_base + mi * 16 + grp;
        int r1 = r0 + 8;
        #pragma unroll
        for (int ni = 0; ni < 4; ni++) {
            int cb = col0 + n_base + ni * 8 + qid * 2;
            if (r0 < M) *(float2*)(C + (size_t)r0 * Nn + cb) = make_float2(acc[mi][ni][0], acc[mi][ni][1]);
            if (r1 < M) *(float2*)(C + (size_t)r1 * Nn + cb) = make_float2(acc[mi][ni][2], acc[mi][ni][3]);
        }
    }
}

// ---------------- LayerNorm ----------------
__global__ __launch_bounds__(256) void ln_kernel(
    const float* __restrict__ x, const float* __restrict__ g,
    const float* __restrict__ bta, float* __restrict__ out)
{
    int t = blockIdx.x, tid = threadIdx.x;
    float4 v = ((const float4*)(x + (size_t)t * DIM))[tid];
    float s  = v.x + v.y + v.z + v.w;
    float sq = v.x * v.x + v.y * v.y + v.z * v.z + v.w * v.w;
    __shared__ float sh[8], sh2[8];
    float ws = warpsum(s), wq = warpsum(sq);
    if ((tid & 31) == 0) { sh[tid >> 5] = ws; sh2[tid >> 5] = wq; }
    __syncthreads();
    if (tid < 32) {
        float a  = (tid < 8) ? sh[tid]  : 0.f;
        float b2 = (tid < 8) ? sh2[tid] : 0.f;
        a = warpsum(a); b2 = warpsum(b2);
        if (tid == 0) { sh[0] = a; sh2[0] = b2; }
    }
    __syncthreads();
    float mu  = sh[0] * (1.0f / DIM);
    float var = sh2[0] * (1.0f / DIM) - mu * mu;
    float inv = rsqrtf(var + 1e-5f);
    float4 gg = ((const float4*)g)[tid], bb = ((const float4*)bta)[tid];
    float4 o;
    o.x = (v.x - mu) * inv * gg.x + bb.x;
    o.y = (v.y - mu) * inv * gg.y + bb.y;
    o.z = (v.z - mu) * inv * gg.z + bb.z;
    o.w = (v.w - mu) * inv * gg.w + bb.w;
    ((float4*)(out + (size_t)t * DIM))[tid] = o;
}

// ---------------- tensor-core attention ----------------
__global__ __launch_bounds__(128) void attn_scores_tc(
    const float* __restrict__ qkv, float* __restrict__ S)
{
    int kt = blockIdx.x, qt = blockIdx.y, bh = blockIdx.z;
    int b = bh >> 4, h = bh & 15;
    __shared__ uint32_t Qs[64][36];
    __shared__ uint32_t Ks[64][36];
    int tid = threadIdx.x, lane = tid & 31, warp = tid >> 5;
    int l_row = tid >> 1, l_half = tid & 1;
    {
        const float* qp = qkv + (size_t)(b * NSEQ + qt * 64 + l_row) * 3 * DIM + h * HDIM + l_half * 32;
        const float* kp = qkv + (size_t)(b * NSEQ + kt * 64 + l_row) * 3 * DIM + DIM + h * HDIM + l_half * 32;
        uint32_t hq[16], hk[16];
        #pragma unroll
        for (int i = 0; i < 8; i++) {
            float4 q4 = *(const float4*)(qp + i * 4);
            float4 k4 = *(const float4*)(kp + i * 4);
            hq[i * 2]     = hpack2(q4.x, q4.y);
            hq[i * 2 + 1] = hpack2(q4.z, q4.w);
            hk[i * 2]     = hpack2(k4.x, k4.y);
            hk[i * 2 + 1] = hpack2(k4.z, k4.w);
        }
        #pragma unroll
        for (int i = 0; i < 4; i++) {
            *(uint4*)&Qs[l_row][l_half * 16 + i * 4] = *(uint4*)(hq + i * 4);
            *(uint4*)&Ks[l_row][l_half * 16 + i * 4] = *(uint4*)(hk + i * 4);
        }
    }
    __syncthreads();
    int m_base = warp * 16;
    uint32_t a_lrow = (uint32_t)(m_base + (lane & 7) + ((lane >> 3) & 1) * 8);
    uint32_t a_lcol = (uint32_t)((lane >> 4) * 4);
    int bl15 = lane & 15;
    float acc[8][4];
    #pragma unroll
    for (int i = 0; i < 8; i++)
        #pragma unroll
        for (int q = 0; q < 4; q++) acc[i][q] = 0.f;
    uint32_t qbase = smem_u32(Qs), kbase = smem_u32(Ks);
    #pragma unroll
    for (int j = 0; j < 4; j++) {
        uint32_t af[4];
        ldmx4(af, qbase + (a_lrow * 36 + j * 8 + a_lcol) * 4);
        #pragma unroll
        for (int ni = 0; ni < 8; ni++) {
            uint32_t bf[2];
            ldmx2(bf, kbase + ((uint32_t)(ni * 8 + (bl15 & 7)) * 36 + j * 8 + ((bl15 >> 3) & 1) * 4) * 4);
            mma16f(acc[ni], af, bf);
        }
    }
    int grp = lane >> 2, qid = lane & 3;
    float* Sp = S + (size_t)bh * NSEQ * NSEQ;
    int r0 = qt * 64 + m_base + grp;
    #pragma unroll
    for (int ni = 0; ni < 8; ni++) {
        int col = kt * 64 + ni * 8 + qid * 2;
        *(float2*)(Sp + (size_t)r0 * NSEQ + col)       = make_float2(acc[ni][0] * 0.125f, acc[ni][1] * 0.125f);
        *(float2*)(Sp + (size_t)(r0 + 8) * NSEQ + col) = make_float2(acc[ni][2] * 0.125f, acc[ni][3] * 0.125f);
    }
}

__global__ __launch_bounds__(128) void softmax_kernel(
    const float* __restrict__ S, __half* __restrict__ P)
{
    size_t row = (size_t)blockIdx.x * 4 + (threadIdx.x >> 5);
    int lane = threadIdx.x & 31;
    const float* p = S + row * NSEQ;
    __half* pp = P + row * NSEQ;
    float v[8];
    float m = -1e30f;
    #pragma unroll
    for (int i = 0; i < 8; i++) { v[i] = p[lane + i * 32]; m = fmaxf(m, v[i]); }
    m = warpmax(m);
    float s = 0.f;
    #pragma unroll
    for (int i = 0; i < 8; i++) { v[i] = expf(v[i] - m); s += v[i]; }
    s = warpsum(s);
    float inv = 1.0f / s;
    #pragma unroll
    for (int i = 0; i < 8; i++) pp[lane + i * 32] = __float2half(v[i] * inv);
}

__global__ __launch_bounds__(128) void attn_av_tc(
    const float* __restrict__ qkv, const __half* __restrict__ P, float* __restrict__ o)
{
    int qt = blockIdx.x, bh = blockIdx.y;
    int b = bh >> 4, h = bh & 15;
    __shared__ uint32_t Ps[64][36];
    __shared__ uint32_t Vs[64][36];
    int tid = threadIdx.x, lane = tid & 31, warp = tid >> 5;
    int l_row = tid >> 1, l_half = tid & 1;
    int m_base = warp * 16;
    uint32_t a_lrow = (uint32_t)(m_base + (lane & 7) + ((lane >> 3) & 1) * 8);
    uint32_t a_lcol = (uint32_t)((lane >> 4) * 4);
    int bl15 = lane & 15;
    float acc[8][4];
    #pragma unroll
    for (int i = 0; i < 8; i++)
        #pragma unroll
        for (int q = 0; q < 4; q++) acc[i][q] = 0.f;
    uint32_t pbase = smem_u32(Ps), vbase = smem_u32(Vs);
    const __half* Pp = P + (size_t)bh * NSEQ * NSEQ + (size_t)(qt * 64 + l_row) * NSEQ + l_half * 32;

    for (int c = 0; c < 4; c++) {
        #pragma unroll
        for (int i = 0; i < 4; i++)
            *(uint4*)&Ps[l_row][l_half * 16 + i * 4] =
                *(const uint4*)((const char*)(Pp + c * 64) + i * 16);
        {
            const float* vp = qkv + (size_t)(b * NSEQ + c * 64 + l_row) * 3 * DIM + 2 * DIM + h * HDIM + l_half * 32;
            uint32_t hv[16];
            #pragma unroll
            for (int i = 0; i < 8; i++) {
                float4 v4 = *(const float4*)(vp + i * 4);
                hv[i * 2]     = hpack2(v4.x, v4.y);
                hv[i * 2 + 1] = hpack2(v4.z, v4.w);
            }
            #pragma unroll
            for (int i = 0; i < 4; i++)
                *(uint4*)&Vs[l_row][l_half * 16 + i * 4] = *(uint4*)(hv + i * 4);
        }
        __syncthreads();
        #pragma unroll
        for (int j = 0; j < 4; j++) {
            uint32_t af[4];
            ldmx4(af, pbase + (a_lrow * 36 + j * 8 + a_lcol) * 4);
            #pragma unroll
            for (int ni = 0; ni < 8; ni++) {
                uint32_t bf[2];
                ldmx2t(bf, vbase + ((uint32_t)(j * 16 + bl15) * 36 + ni * 4) * 4);
                mma16f(acc[ni], af, bf);
            }
        }
        __syncthreads();
    }
    int grp = lane >> 2, qid = lane & 3;
    int r0 = qt * 64 + m_base + grp;
    #pragma unroll
    for (int ni = 0; ni < 8; ni++) {
        int d = ni * 8 + qid * 2;
        *(float2*)(o + (size_t)(b * NSEQ + r0) * DIM + h * HDIM + d)       = make_float2(acc[ni][0], acc[ni][1]);
        *(float2*)(o + (size_t)(b * NSEQ + r0 + 8) * DIM + h * HDIM + d)   = make_float2(acc[ni][2], acc[ni][3]);
    }
}

// ---------------- router ----------------
__global__ __launch_bounds__(128) void router_kernel(
    const float* __restrict__ gh, const float* __restrict__ W, const float* __restrict__ bias)
{
    int t = blockIdx.x;
    int wid = threadIdx.x >> 5, lane = threadIdx.x & 31;
    const float* row = gh + (size_t)t * RHC;
    float s = 0.f;
    for (int k = lane; k < RHC; k += 32) s += row[k] * W[k * NE + wid];
    s = warpsum(s);
    __shared__ float logits[NE];
    if (lane == 0) logits[wid] = s + bias[wid];
    __syncthreads();
    if (threadIdx.x == 0) {
        float l[NE], m = -1e30f;
        #pragma unroll
        for (int e = 0; e < NE; e++) { l[e] = logits[e]; m = fmaxf(m, l[e]); }
        float ssum = 0.f;
        #pragma unroll
        for (int e = 0; e < NE; e++) { l[e] = expf(l[e] - m); ssum += l[e]; }
        float p[NE];
        #pragma unroll
        for (int e = 0; e < NE; e++)
            p[e] = fminf(fmaxf(l[e] / ssum, 1e-9f), 1.0f - 1e-9f);
        int i1 = 0;
        #pragma unroll
        for (int e = 1; e < NE; e++) if (p[e] > p[i1]) i1 = e;
        int i2 = -1;
        #pragma unroll
        for (int e = 0; e < NE; e++) {
            if (e == i1) continue;
            if (i2 < 0 || p[e] > p[i2]) i2 = e;
        }
        float wsum = p[i1] + p[i2];
        int pos = atomicAdd(&g_cnt[i1], 1);
        g_idx[i1 * TT + pos] = t;
        pos = atomicAdd(&g_cnt[i2], 1);
        g_idx[i2 * TT + pos] = t;
        g_te[t] = make_int2(i1, i2);
        g_tw[t] = make_float2(p[i1] / wsum, p[i2] / wsum);
    }
}

__global__ void zero_cnt_kernel() {
    if (threadIdx.x < NE) g_cnt[threadIdx.x] = 0;
}

__global__ __launch_bounds__(256) void combine_kernel(
    const float* __restrict__ x1, const float* __restrict__ eout, float* __restrict__ out)
{
    int t = blockIdx.x, c = threadIdx.x;
    int2 e = g_te[t];
    float2 w = g_tw[t];
    float4 a  = ((const float4*)(x1 + (size_t)t * DIM))[c];
    float4 v1 = ((const float4*)(eout + ((size_t)e.x * TT + t) * DIM))[c];
    float4 v2 = ((const float4*)(eout + ((size_t)e.y * TT + t) * DIM))[c];
    float4 r;
    r.x = a.x + w.x * v1.x + w.y * v2.x;
    r.y = a.y + w.x * v1.y + w.y * v2.y;
    r.z = a.z + w.x * v1.z + w.y * v2.z;
    r.w = a.w + w.x * v1.w + w.y * v2.w;
    ((float4*)(out + (size_t)t * DIM))[c] = r;
}

// ---------------- host launcher ----------------
static void* symaddr(const void* s) {
    void* p = nullptr;
    cudaGetSymbolAddress(&p, s);
    return p;
}

extern "C" void kernel_launch(void* const* d_in, const int* in_sizes, int n_in,
                              void* d_out, int out_size) {
    const float* x       = (const float*)d_in[0];
    const float* cond    = (const float*)d_in[1];
    const float* ln1_g   = (const float*)d_in[2];
    const float* ln1_b   = (const float*)d_in[3];
    const float* qkv_w   = (const float*)d_in[4];
    const float* proj_w  = (const float*)d_in[5];
    const float* proj_b  = (const float*)d_in[6];
    const float* ln2_g   = (const float*)d_in[7];
    const float* ln2_b   = (const float*)d_in[8];
    const float* r_fc1_w = (const float*)d_in[9];
    const float* r_fc1_b = (const float*)d_in[10];
    const float* r_fc2_w = (const float*)d_in[11];
    const float* r_fc2_b = (const float*)d_in[12];
    const float* e_w1    = (const float*)d_in[13];
    const float* e_b1    = (const float*)d_in[14];
    const float* e_w2    = (const float*)d_in[15];
    const float* e_b2    = (const float*)d_in[16];
    float* out = (float*)d_out;

    float* h1    = (float*)symaddr(g_h1);
    float* qkv   = (float*)symaddr(g_qkv);
    float* S     = (float*)symaddr(g_S);
    __half* P    = (__half*)symaddr(g_P);
    float* o     = (float*)symaddr(g_o);
    float* x1    = (float*)symaddr(g_x1);
    float* h2    = (float*)symaddr(g_h2);
    float* condc = (float*)symaddr(g_condc);
    float* gh    = (float*)symaddr(g_gh);
    float* hid   = (float*)symaddr(g_hid);
    float* eout  = (float*)symaddr(g_eout);
    int*   cnt   = (int*)symaddr(g_cnt);
    int*   idx   = (int*)symaddr(g_idx);
    __half* wqkv_h  = (__half*)symaddr(g_wqkv_h);
    __half* wproj_h = (__half*)symaddr(g_wproj_h);
    __half* wfc1_h  = (__half*)symaddr(g_wfc1_h);
    __half* wfc1_l  = (__half*)symaddr(g_wfc1_l);
    __half* we1_h   = (__half*)symaddr(g_we1_h);
    __half* we2_h   = (__half*)symaddr(g_we2_h);

    cudaFuncSetAttribute(gemm_tc2<2,false,false,false,false,false,false>,
                         cudaFuncAttributeMaxDynamicSharedMemorySize, G_SMEM);
    cudaFuncSetAttribute(gemm_tc2<2,false,false,true,false,true,false>,
                         cudaFuncAttributeMaxDynamicSharedMemorySize, G_SMEM);
    cudaFuncSetAttribute(gemm_tc2<3,false,false,true,true,false,true>,
                         cudaFuncAttributeMaxDynamicSharedMemorySize, G_SMEM);
    cudaFuncSetAttribute(gemm_tc2<1,true,false,true,true,false,false>,
                         cudaFuncAttributeMaxDynamicSharedMemorySize, G_SMEM);
    cudaFuncSetAttribute(gemm_tc2<1,false,true,true,false,false,false>,
                         cudaFuncAttributeMaxDynamicSharedMemorySize, G_SMEM);

    zero_cnt_kernel<<<1, 32>>>();

    // pre-split weights: fc1 keeps hi+lo (router precision); qkv/proj/experts hi only
    wsplit_kernel<<<dim3(3 * DIM / 32, DIM / 32, 1), 256>>>(qkv_w, wqkv_h, nullptr, DIM, 3 * DIM, 3 * DIM, 0, 0);
    wsplit_kernel<<<dim3(DIM / 32, DIM / 32, 1), 256>>>(proj_w, wproj_h, nullptr, DIM, DIM, DIM, 0, 0);
    wsplit_kernel<<<dim3(RHC / 32, DIM / 32, 1), 256>>>(r_fc1_w, wfc1_h, wfc1_l, DIM, RHC, RHC, 0, 0);
    wsplit_kernel<<<dim3(DFFC / 32, DIM / 32, NE), 256>>>(e_w1, we1_h, nullptr, DIM, DFFC, DFFC,
                                                          (size_t)DIM * DFFC, (size_t)DFFC * DIM);
    wsplit_kernel<<<dim3(DIM / 32, DFFC / 32, NE), 256>>>(e_w2, we2_h, nullptr, DFFC, DIM, DIM,
                                                          (size_t)DFFC * DIM, (size_t)DIM * DFFC);

    // LN1
    ln_kernel<<<TT, 256>>>(x, ln1_g, ln1_b, h1);

    // QKV = h1 @ qkv_w (2-term: activations split, weights fp16)
    gemm_tc2<2,false,false,false,false,false,false>
        <<<dim3(3 * DIM / 128, TT / 128, 1), 256, G_SMEM>>>(h1, wqkv_h, nullptr, qkv, TT, 3 * DIM, DIM,
            nullptr, 0, nullptr, nullptr, nullptr, nullptr, 0, 0, 0);

    // attention (fp16 tensor cores)
    attn_scores_tc<<<dim3(4, 4, BB * NH), 128>>>(qkv, S);
    softmax_kernel<<<BB * NH * NSEQ / 4, 128>>>(S, P);
    attn_av_tc<<<dim3(4, BB * NH), 128>>>(qkv, P, o);

    // x1 = x + o @ proj_w + proj_b (2-term)
    gemm_tc2<2,false,false,true,false,true,false>
        <<<dim3(DIM / 128, TT / 128, 1), 256, G_SMEM>>>(o, wproj_h, nullptr, x1, TT, DIM, DIM,
            proj_b, 0, x, nullptr, nullptr, nullptr, 0, 0, 0);

    // LN2
    ln_kernel<<<TT, 256>>>(x1, ln2_g, ln2_b, h2);

    // condc (tiny; legacy bf16 3-term)
    gemm_tc_plain<<<dim3(RHC / 128, 1), 256>>>(cond, r_fc1_w + (size_t)DIM * RHC, condc, BB, RHC, CDIM);

    // gh = gelu(h2 @ r_fc1_w[:D] + condc[b] + b1) (3-term — router precision critical)
    gemm_tc2<3,false,false,true,true,false,true>
        <<<dim3(RHC / 128, TT / 128, 1), 256, G_SMEM>>>(h2, wfc1_h, wfc1_l, gh, TT, RHC, DIM,
            r_fc1_b, 0, nullptr, condc, nullptr, nullptr, 0, 0, 0);

    // router
    router_kernel<<<TT, 128>>>(gh, r_fc2_w, r_fc2_b);

    // experts (1-term fp16), merged across NE
    gemm_tc2<1,true,false,true,true,false,false>
        <<<dim3(DFFC / 128, TT / 128, NE), 256, G_SMEM>>>(h2, we1_h, nullptr, hid,
            TT, DFFC, DIM, e_b1, DFFC, nullptr, nullptr,
            idx, cnt, (size_t)DFFC * DIM, 0, TT);
    gemm_tc2<1,false,true,true,false,false,false>
        <<<dim3(DIM / 128, TT / 128, NE), 256, G_SMEM>>>(hid, we2_h, nullptr, eout,
            TT, DIM, DFFC, e_b2, DIM, nullptr, nullptr,
            idx, cnt, (size_t)DIM * DFFC, (size_t)TT * DFFC, TT);

    // out = x1 + w1*eout[e1] + w2*eout[e2]
    combine_kernel<<<TT, 256>>>(x1, eout, out);
}

// round 16
// speedup vs baseline: 5.5190x; 1.1761x over previous
#include <cuda_runtime.h>
#include <cuda_bf16.h>
#include <cuda_fp16.h>
#include <math.h>
#include <stdint.h>

// ---------------- problem constants ----------------
constexpr int BB   = 32;
constexpr int NSEQ = 256;
constexpr int DIM  = 1024;
constexpr int NH   = 16;
constexpr int HDIM = 64;
constexpr int CDIM = 1024;
constexpr int NE   = 4;
constexpr int DFFC = 4096;
constexpr int RHC  = 2048;
constexpr int TT   = BB * NSEQ;   // 8192 tokens

// ---------------- scratch (device globals; no allocation allowed) ----------------
__device__ float  g_h1[TT * DIM];
__device__ __half g_qkv[(size_t)TT * 3 * DIM];          // fp16 now
__device__ float  g_S[(size_t)BB * NH * NSEQ * NSEQ];
__device__ __half g_P[(size_t)BB * NH * NSEQ * NSEQ];
__device__ float  g_o[TT * DIM];
__device__ float  g_x1[TT * DIM];
__device__ float  g_h2[TT * DIM];
__device__ float  g_condc[BB * RHC];
__device__ float  g_gh[(size_t)TT * RHC];
__device__ __half g_hid[(size_t)NE * TT * DFFC];        // fp16 now
__device__ __half g_eout[(size_t)NE * TT * DIM];        // fp16 now
__device__ int    g_cnt[NE];
__device__ int    g_idx[NE * TT];
__device__ int2   g_te[TT];
__device__ float2 g_tw[TT];

// pre-split K-major weights: [N][K] fp16; lo only where needed (fc1)
__device__ __half g_wqkv_h[(size_t)3 * DIM * DIM];
__device__ __half g_wproj_h[(size_t)DIM * DIM];
__device__ __half g_wfc1_h[(size_t)RHC * DIM];
__device__ __half g_wfc1_l[(size_t)RHC * DIM];
__device__ __half g_we1_h[(size_t)NE * DFFC * DIM];
__device__ __half g_we2_h[(size_t)NE * DIM * DFFC];

// ---------------- helpers ----------------
__device__ __forceinline__ float warpsum(float v) {
    #pragma unroll
    for (int o = 16; o; o >>= 1) v += __shfl_xor_sync(0xFFFFFFFFu, v, o);
    return v;
}
__device__ __forceinline__ float warpmax(float v) {
    #pragma unroll
    for (int o = 16; o; o >>= 1) v = fmaxf(v, __shfl_xor_sync(0xFFFFFFFFu, v, o));
    return v;
}
__device__ __forceinline__ float gelu_f(float x) {
    return 0.5f * x * (1.0f + erff(x * 0.70710678118654752f));
}
__device__ __forceinline__ void hsplit2(float x0, float x1, uint32_t& hi, uint32_t& lo) {
    __half2 h = __floats2half2_rn(x0, x1);
    float r0 = x0 - __half2float(__low2half(h));
    float r1 = x1 - __half2float(__high2half(h));
    __half2 l = __floats2half2_rn(r0, r1);
    hi = *reinterpret_cast<uint32_t*>(&h);
    lo = *reinterpret_cast<uint32_t*>(&l);
}
__device__ __forceinline__ uint32_t hpack2(float x0, float x1) {
    __half2 h = __floats2half2_rn(x0, x1);
    return *reinterpret_cast<uint32_t*>(&h);
}
__device__ __forceinline__ void bfsplit2(float x0, float x1, uint32_t& hi, uint32_t& lo) {
    __nv_bfloat162 h = __floats2bfloat162_rn(x0, x1);
    float r0 = x0 - __bfloat162float(h.x);
    float r1 = x1 - __bfloat162float(h.y);
    __nv_bfloat162 l = __floats2bfloat162_rn(r0, r1);
    hi = *reinterpret_cast<uint32_t*>(&h);
    lo = *reinterpret_cast<uint32_t*>(&l);
}
__device__ __forceinline__ void mma16bf(float* c, const uint32_t* a, const uint32_t* b) {
    asm("mma.sync.aligned.m16n8k16.row.col.f32.bf16.bf16.f32 "
        "{%0,%1,%2,%3}, {%4,%5,%6,%7}, {%8,%9}, {%0,%1,%2,%3};"
        : "+f"(c[0]), "+f"(c[1]), "+f"(c[2]), "+f"(c[3])
        : "r"(a[0]), "r"(a[1]), "r"(a[2]), "r"(a[3]), "r"(b[0]), "r"(b[1]));
}
__device__ __forceinline__ void mma16f(float* c, const uint32_t* a, const uint32_t* b) {
    asm("mma.sync.aligned.m16n8k16.row.col.f32.f16.f16.f32 "
        "{%0,%1,%2,%3}, {%4,%5,%6,%7}, {%8,%9}, {%0,%1,%2,%3};"
        : "+f"(c[0]), "+f"(c[1]), "+f"(c[2]), "+f"(c[3])
        : "r"(a[0]), "r"(a[1]), "r"(a[2]), "r"(a[3]), "r"(b[0]), "r"(b[1]));
}
__device__ __forceinline__ void mma16h(uint32_t* c, const uint32_t* a, const uint32_t* b) {
    asm("mma.sync.aligned.m16n8k16.row.col.f16.f16.f16.f16 "
        "{%0,%1}, {%2,%3,%4,%5}, {%6,%7}, {%0,%1};"
        : "+r"(c[0]), "+r"(c[1])
        : "r"(a[0]), "r"(a[1]), "r"(a[2]), "r"(a[3]), "r"(b[0]), "r"(b[1]));
}
__device__ __forceinline__ void ldmx4(uint32_t* r, uint32_t a) {
    asm volatile("ldmatrix.sync.aligned.m8n8.x4.shared.b16 {%0,%1,%2,%3}, [%4];"
        : "=r"(r[0]), "=r"(r[1]), "=r"(r[2]), "=r"(r[3]) : "r"(a));
}
__device__ __forceinline__ void ldmx2(uint32_t* r, uint32_t a) {
    asm volatile("ldmatrix.sync.aligned.m8n8.x2.shared.b16 {%0,%1}, [%2];"
        : "=r"(r[0]), "=r"(r[1]) : "r"(a));
}
__device__ __forceinline__ void ldmx2t(uint32_t* r, uint32_t a) {
    asm volatile("ldmatrix.sync.aligned.m8n8.x2.trans.shared.b16 {%0,%1}, [%2];"
        : "=r"(r[0]), "=r"(r[1]) : "r"(a));
}
__device__ __forceinline__ uint32_t smem_u32(const void* p) {
    uint32_t a;
    asm("{ .reg .u64 t; cvta.to.shared.u64 t, %1; cvt.u32.u64 %0, t; }" : "=r"(a) : "l"(p));
    return a;
}
__device__ __forceinline__ void cp16(uint32_t dst, const void* src) {
    asm volatile("cp.async.ca.shared.global [%0], [%1], 16;" :: "r"(dst), "l"(src));
}
__device__ __forceinline__ void cp_commit() { asm volatile("cp.async.commit_group;" ::: "memory"); }
__device__ __forceinline__ void cp_wait0()  { asm volatile("cp.async.wait_group 0;" ::: "memory"); }

// ---------------- weight transpose + split: W[K,N] -> Wh(/Wl)[N,K] fp16 ----------------
__global__ __launch_bounds__(256) void wsplit_kernel(
    const float* __restrict__ W, __half* __restrict__ Wh, __half* __restrict__ Wl,
    int K, int Nn, int ld, size_t wz, size_t oz)
{
    __shared__ float ts[32][33];
    int z = blockIdx.z;
    const float* Wp = W + (size_t)z * wz;
    int n0 = blockIdx.x * 32, k0 = blockIdx.y * 32;
    int tx = threadIdx.x & 31, ty = threadIdx.x >> 5;
    #pragma unroll
    for (int i = 0; i < 4; i++)
        ts[ty + i * 8][tx] = Wp[(size_t)(k0 + ty + i * 8) * ld + n0 + tx];
    __syncthreads();
    #pragma unroll
    for (int i = 0; i < 4; i++) {
        int n = n0 + ty + i * 8, k = k0 + tx;
        float v = ts[tx][ty + i * 8];
        __half h = __float2half(v);
        Wh[(size_t)z * oz + (size_t)n * K + k] = h;
        if (Wl) Wl[(size_t)z * oz + (size_t)n * K + k] = __float2half(v - __half2float(h));
    }
}

// ---------------- fp16 split GEMM ----------------
// TERMS=3: AhBh(f32) + AlBh(f16) + AhBl(f16); TERMS=2: AhBh + AlBh; TERMS=1: AhBh.
// AHALF: A already fp16 [M][K] (TERMS must be 1) -> loaded by cp.async, no convert.
// HOUT : C written as fp16.
constexpr int G_AH = 0;
constexpr int G_AL = 10240;
constexpr int G_BH = 20480;
constexpr int G_BL = 30720;
constexpr int G_STG = 40960;
constexpr int G_SMEM = 2 * G_STG;     // 81920

template<int TERMS, bool AHALF, bool HOUT, bool GATHER, bool SCATTER,
         bool BIAS, bool GELU, bool RESID, bool CONDC>
__global__ __launch_bounds__(256) void gemm_tc2(
    const void* __restrict__ Av,
    const __half* __restrict__ Bh, const __half* __restrict__ Bl,
    void* __restrict__ Cv, int M, int Nn, int K,
    const float* __restrict__ bias, int biasz,
    const float* __restrict__ res, const float* __restrict__ condc,
    const int* __restrict__ gidx, const int* __restrict__ cntp,
    size_t wz, size_t azoff, int czoff)
{
    extern __shared__ char sm[];
    int ez = blockIdx.z;
    if (cntp) M = cntp[ez];
    int row0 = blockIdx.y * 128;
    if (row0 >= M) return;
    int col0 = blockIdx.x * 128;

    Bh += (size_t)ez * wz;
    if (TERMS == 3) Bl += (size_t)ez * wz;
    const int* gz = (GATHER || SCATTER) ? (gidx + ez * TT) : nullptr;
    size_t crow_base = (size_t)ez * (size_t)czoff;

    uint32_t sb = smem_u32(sm);
    int tid = threadIdx.x, lane = tid & 31, warp = tid >> 5;
    int m_base = (warp >> 2) * 64, n_base = (warp & 3) * 32;

    int l_row  = tid >> 1;
    int l_half = tid & 1;
    int gar = row0 + l_row;
    bool gav = gar < M;
    int garow = gav ? (GATHER ? gz[gar] : gar) : 0;
    const float* ap = AHALF ? nullptr : ((const float*)Av + (size_t)ez * azoff + (size_t)garow * K);
    const char* aph = AHALF ? (const char*)((const __half*)Av + (size_t)ez * azoff + (size_t)garow * K) : nullptr;
    const char* bhp = (const char*)(Bh + (size_t)(col0 + l_row) * K);
    const char* blp = (TERMS == 3) ? (const char*)(Bl + (size_t)(col0 + l_row) * K) : nullptr;
    uint32_t a_sts = sb + (uint32_t)(l_row * 20 + l_half * 8) * 4;
    uint32_t b_sts = sb + (uint32_t)(l_row * 20 + l_half * 8) * 4;

    uint32_t a_lrow = (uint32_t)(m_base + (lane & 7) + ((lane >> 3) & 1) * 8);
    uint32_t a_lcol = (uint32_t)((lane >> 4) * 4);
    int bl15 = lane & 15;
    uint32_t b_lrow = (uint32_t)(n_base + (bl15 & 7));
    uint32_t b_lcol = (uint32_t)(((bl15 >> 3) & 1) * 4);

    float acc[4][4][4];
    uint32_t accl[4][4][2];
    #pragma unroll
    for (int i = 0; i < 4; i++)
        #pragma unroll
        for (int j = 0; j < 4; j++) {
            #pragma unroll
            for (int q = 0; q < 4; q++) acc[i][j][q] = 0.f;
            accl[i][j][0] = 0u; accl[i][j][1] = 0u;
        }

    int nt = K >> 5;
    float4 pa[4];

    auto ldgA = [&](int kt) {
        const float* p = ap + kt * 32 + l_half * 16;
        if (gav) {
            pa[0] = *(const float4*)(p);
            pa[1] = *(const float4*)(p + 4);
            pa[2] = *(const float4*)(p + 8);
            pa[3] = *(const float4*)(p + 12);
        } else {
            pa[0] = pa[1] = pa[2] = pa[3] = make_float4(0.f, 0.f, 0.f, 0.f);
        }
    };
    auto cpA = [&](int kt, int buf) {     // AHALF path: direct fp16 copy
        uint32_t d = a_sts + buf * G_STG;
        const char* sh = aph + (size_t)kt * 64 + l_half * 32;
        cp16(d + G_AH,      sh);
        cp16(d + G_AH + 16, sh + 16);
    };
    auto cpB = [&](int kt, int buf) {
        uint32_t d = b_sts + buf * G_STG;
        const char* sh = bhp + (size_t)kt * 64 + l_half * 32;
        cp16(d + G_BH,      sh);
        cp16(d + G_BH + 16, sh + 16);
        if (TERMS == 3) {
            const char* sl = blp + (size_t)kt * 64 + l_half * 32;
            cp16(d + G_BL,      sl);
            cp16(d + G_BL + 16, sl + 16);
        }
    };
    auto stsA = [&](int buf) {
        uint32_t d = a_sts + buf * G_STG;
        if (TERMS >= 2) {
            uint32_t h[8], l[8];
            hsplit2(pa[0].x, pa[0].y, h[0], l[0]); hsplit2(pa[0].z, pa[0].w, h[1], l[1]);
            hsplit2(pa[1].x, pa[1].y, h[2], l[2]); hsplit2(pa[1].z, pa[1].w, h[3], l[3]);
            hsplit2(pa[2].x, pa[2].y, h[4], l[4]); hsplit2(pa[2].z, pa[2].w, h[5], l[5]);
            hsplit2(pa[3].x, pa[3].y, h[6], l[6]); hsplit2(pa[3].z, pa[3].w, h[7], l[7]);
            *(uint4*)(sm + (d - sb) + G_AH)      = *(uint4*)(h);
            *(uint4*)(sm + (d - sb) + G_AH + 16) = *(uint4*)(h + 4);
            *(uint4*)(sm + (d - sb) + G_AL)      = *(uint4*)(l);
            *(uint4*)(sm + (d - sb) + G_AL + 16) = *(uint4*)(l + 4);
        } else {
            uint32_t h[8];
            h[0] = hpack2(pa[0].x, pa[0].y); h[1] = hpack2(pa[0].z, pa[0].w);
            h[2] = hpack2(pa[1].x, pa[1].y); h[3] = hpack2(pa[1].z, pa[1].w);
            h[4] = hpack2(pa[2].x, pa[2].y); h[5] = hpack2(pa[2].z, pa[2].w);
            h[6] = hpack2(pa[3].x, pa[3].y); h[7] = hpack2(pa[3].z, pa[3].w);
            *(uint4*)(sm + (d - sb) + G_AH)      = *(uint4*)(h);
            *(uint4*)(sm + (d - sb) + G_AH + 16) = *(uint4*)(h + 4);
        }
    };

    // prologue
    if (AHALF) { cpA(0, 0); cpB(0, 0); cp_commit(); }
    else       { ldgA(0); cpB(0, 0); cp_commit(); stsA(0); }
    cp_wait0();
    __syncthreads();

    for (int t = 0; t < nt; t++) {
        int cur = t & 1;
        if (t + 1 < nt) {
            if (AHALF) { cpA(t + 1, cur ^ 1); cpB(t + 1, cur ^ 1); cp_commit(); }
            else       { ldgA(t + 1); cpB(t + 1, cur ^ 1); cp_commit(); }
        }
        uint32_t stage = sb + cur * G_STG;
        #pragma unroll
        for (int j = 0; j < 2; j++) {
            uint32_t a_h[4][4], a_l[4][4], b_h[4][2], b_l[4][2];
            #pragma unroll
            for (int mi = 0; mi < 4; mi++) {
                uint32_t ad = stage + ((a_lrow + mi * 16) * 20 + j * 8 + a_lcol) * 4;
                ldmx4(a_h[mi], ad + G_AH);
                if (TERMS >= 2) ldmx4(a_l[mi], ad + G_AL);
            }
            #pragma unroll
            for (int ni = 0; ni < 4; ni++) {
                uint32_t bd = stage + ((b_lrow + ni * 8) * 20 + j * 8 + b_lcol) * 4;
                ldmx2(b_h[ni], bd + G_BH);
                if (TERMS == 3) ldmx2(b_l[ni], bd + G_BL);
            }
            #pragma unroll
            for (int mi = 0; mi < 4; mi++)
                #pragma unroll
                for (int ni = 0; ni < 4; ni++) {
                    mma16f(acc[mi][ni],  a_h[mi], b_h[ni]);       // hi*hi, fp32 accum
                    if (TERMS >= 2)
                        mma16h(accl[mi][ni], a_l[mi], b_h[ni]);   // lo*hi, fp16 accum
                    if (TERMS == 3)
                        mma16h(accl[mi][ni], a_h[mi], b_l[ni]);   // hi*lo, fp16 accum
                }
        }
        if (t + 1 < nt) {
            if (!AHALF) stsA(cur ^ 1);
            cp_wait0();
            __syncthreads();
        }
    }

    int grp = lane >> 2, qid = lane & 3;
    #pragma unroll
    for (int mi = 0; mi < 4; mi++) {
        int r0 = row0 + m_base + mi * 16 + grp;
        int r1 = r0 + 8;
        bool v0 = r0 < M, v1 = r1 < M;
        size_t cr0 = 0, cr1 = 0;
        if (v0) cr0 = crow_base + (SCATTER ? (size_t)gz[r0] : (size_t)r0);
        if (v1) cr1 = crow_base + (SCATTER ? (size_t)gz[r1] : (size_t)r1);
        #pragma unroll
        for (int ni = 0; ni < 4; ni++) {
            int cb = col0 + n_base + ni * 8 + qid * 2;
            float2 f01 = make_float2(0.f, 0.f), f23 = make_float2(0.f, 0.f);
            if (TERMS >= 2) {
                f01 = __half22float2(*(__half2*)&accl[mi][ni][0]);
                f23 = __half22float2(*(__half2*)&accl[mi][ni][1]);
            }
            #pragma unroll
            for (int hf = 0; hf < 2; hf++) {
                bool valid = hf ? v1 : v0;
                if (!valid) continue;
                int rr = hf ? r1 : r0;
                size_t cr = hf ? cr1 : cr0;
                float e0 = acc[mi][ni][hf * 2 + 0] + (hf ? f23.x : f01.x);
                float e1 = acc[mi][ni][hf * 2 + 1] + (hf ? f23.y : f01.y);
                if (BIAS)  { e0 += bias[biasz * ez + cb]; e1 += bias[biasz * ez + cb + 1]; }
                if (CONDC) {
                    const float* cc = condc + (size_t)(rr >> 8) * Nn + cb;
                    e0 += cc[0]; e1 += cc[1];
                }
                if (GELU)  { e0 = gelu_f(e0); e1 = gelu_f(e1); }
                if (RESID) {
                    const float* rp = res + (size_t)rr * Nn + cb;
                    e0 += rp[0]; e1 += rp[1];
                }
                if (HOUT) {
                    __half2 hv = __floats2half2_rn(e0, e1);
                    *(__half2*)((__half*)Cv + cr * Nn + cb) = hv;
                } else {
                    *(float2*)((float*)Cv + cr * Nn + cb) = make_float2(e0, e1);
                }
            }
        }
    }
}

// ---------------- legacy bf16-split GEMM (tiny condc only) ----------------
__global__ __launch_bounds__(256) void gemm_tc_plain(
    const float* __restrict__ A, const float* __restrict__ Bm, float* __restrict__ C,
    int M, int Nn, int K)
{
    int row0 = blockIdx.y * 128;
    if (row0 >= M) return;
    int col0 = blockIdx.x * 128;
    __shared__ uint32_t Ah[2][128][9];
    __shared__ uint32_t Al[2][128][9];
    __shared__ uint32_t Bh[2][8][132];
    __shared__ uint32_t Bl[2][8][132];
    int tid = threadIdx.x, lane = tid & 31, warp = tid >> 5;
    int grp = lane >> 2, qid = lane & 3;
    int m_base = (warp >> 2) * 64, n_base = (warp & 3) * 32;
    int a_r = tid >> 2, a_k4 = (tid & 3) * 4, a_kp = (tid & 3) * 2;
    int ar1 = row0 + a_r, ar2 = row0 + a_r + 64;
    bool av1 = ar1 < M, av2 = ar2 < M;
    int b_kp = tid >> 5, b_n4 = (tid & 31) * 4;
    float acc[4][4][4];
    #pragma unroll
    for (int i = 0; i < 4; i++)
        #pragma unroll
        for (int j = 0; j < 4; j++)
            #pragma unroll
            for (int q = 0; q < 4; q++) acc[i][j][q] = 0.f;
    int nt = K / 16;
    float4 ra0, ra1, rbE, rbO;
    ra0 = av1 ? *(const float4*)(A + (size_t)ar1 * K + a_k4) : make_float4(0,0,0,0);
    ra1 = av2 ? *(const float4*)(A + (size_t)ar2 * K + a_k4) : make_float4(0,0,0,0);
    rbE = *(const float4*)(Bm + (size_t)(2 * b_kp) * Nn + col0 + b_n4);
    rbO = *(const float4*)(Bm + (size_t)(2 * b_kp + 1) * Nn + col0 + b_n4);
    {
        uint32_t h0, l0, h1, l1;
        bfsplit2(ra0.x, ra0.y, h0, l0); bfsplit2(ra0.z, ra0.w, h1, l1);
        Ah[0][a_r][a_kp] = h0; Ah[0][a_r][a_kp+1] = h1; Al[0][a_r][a_kp] = l0; Al[0][a_r][a_kp+1] = l1;
        bfsplit2(ra1.x, ra1.y, h0, l0); bfsplit2(ra1.z, ra1.w, h1, l1);
        Ah[0][a_r+64][a_kp] = h0; Ah[0][a_r+64][a_kp+1] = h1; Al[0][a_r+64][a_kp] = l0; Al[0][a_r+64][a_kp+1] = l1;
        uint32_t bh4[4], bl4[4];
        bfsplit2(rbE.x, rbO.x, bh4[0], bl4[0]); bfsplit2(rbE.y, rbO.y, bh4[1], bl4[1]);
        bfsplit2(rbE.z, rbO.z, bh4[2], bl4[2]); bfsplit2(rbE.w, rbO.w, bh4[3], bl4[3]);
        *(uint4*)&Bh[0][b_kp][b_n4] = *(uint4*)bh4;
        *(uint4*)&Bl[0][b_kp][b_n4] = *(uint4*)bl4;
    }
    __syncthreads();
    for (int t = 0; t < nt; t++) {
        int cur = t & 1;
        if (t + 1 < nt) {
            int k0 = (t + 1) * 16;
            ra0 = av1 ? *(const float4*)(A + (size_t)ar1 * K + k0 + a_k4) : make_float4(0,0,0,0);
            ra1 = av2 ? *(const float4*)(A + (size_t)ar2 * K + k0 + a_k4) : make_float4(0,0,0,0);
            rbE = *(const float4*)(Bm + (size_t)(k0 + 2 * b_kp) * Nn + col0 + b_n4);
            rbO = *(const float4*)(Bm + (size_t)(k0 + 2 * b_kp + 1) * Nn + col0 + b_n4);
        }
        uint32_t a_h[4][4], a_l[4][4], b_h[4][2], b_l[4][2];
        #pragma unroll
        for (int mi = 0; mi < 4; mi++) {
            int rm = m_base + mi * 16 + grp;
            a_h[mi][0] = Ah[cur][rm][qid];         a_l[mi][0] = Al[cur][rm][qid];
            a_h[mi][1] = Ah[cur][rm + 8][qid];     a_l[mi][1] = Al[cur][rm + 8][qid];
            a_h[mi][2] = Ah[cur][rm][qid + 4];     a_l[mi][2] = Al[cur][rm][qid + 4];
            a_h[mi][3] = Ah[cur][rm + 8][qid + 4]; a_l[mi][3] = Al[cur][rm + 8][qid + 4];
        }
        #pragma unroll
        for (int ni = 0; ni < 4; ni++) {
            int cn = n_base + ni * 8 + grp;
            b_h[ni][0] = Bh[cur][qid][cn];     b_l[ni][0] = Bl[cur][qid][cn];
            b_h[ni][1] = Bh[cur][qid + 4][cn]; b_l[ni][1] = Bl[cur][qid + 4][cn];
        }
        #pragma unroll
        for (int mi = 0; mi < 4; mi++)
            #pragma unroll
            for (int ni = 0; ni < 4; ni++) {
                mma16bf(acc[mi][ni], a_h[mi], b_l[ni]);
                mma16bf(acc[mi][ni], a_l[mi], b_h[ni]);
                mma16bf(acc[mi][ni], a_h[mi], b_h[ni]);
            }
        if (t + 1 < nt) {
            int nxt = (t + 1) & 1;
            uint32_t h0, l0, h1, l1;
            bfsplit2(ra0.x, ra0.y, h0, l0); bfsplit2(ra0.z, ra0.w, h1, l1);
            Ah[nxt][a_r][a_kp] = h0; Ah[nxt][a_r][a_kp+1] = h1; Al[nxt][a_r][a_kp] = l0; Al[nxt][a_r][a_kp+1] = l1;
            bfsplit2(ra1.x, ra1.y, h0, l0); bfsplit2(ra1.z, ra1.w, h1, l1);
            Ah[nxt][a_r+64][a_kp] = h0; Ah[nxt][a_r+64][a_kp+1] = h1; Al[nxt][a_r+64][a_kp] = l0; Al[nxt][a_r+64][a_kp+1] = l1;
            uint32_t bh4[4], bl4[4];
            bfsplit2(rbE.x, rbO.x, bh4[0], bl4[0]); bfsplit2(rbE.y, rbO.y, bh4[1], bl4[1]);
            bfsplit2(rbE.z, rbO.z, bh4[2], bl4[2]); bfsplit2(rbE.w, rbO.w, bh4[3], bl4[3]);
            *(uint4*)&Bh[nxt][b_kp][b_n4] = *(uint4*)bh4;
            *(uint4*)&Bl[nxt][b_kp][b_n4] = *(uint4*)bl4;
            __syncthreads();
        }
    }
    #pragma unroll
    for (int mi = 0; mi < 4; mi++) {
        int r0 = row0 + m_base + mi * 16 + grp;
        int r1 = r0 + 8;
        #pragma unroll
        for (int ni = 0; ni < 4; ni++) {
            int cb = col0 + n_base + ni * 8 + qid * 2;
            if (r0 < M) *(float2*)(C + (size_t)r0 * Nn + cb) = make_float2(acc[mi][ni][0], acc[mi][ni][1]);
            if (r1 < M) *(float2*)(C + (size_t)r1 * Nn + cb) = make_float2(acc[mi][ni][2], acc[mi][ni][3]);
        }
    }
}

// ---------------- LayerNorm ----------------
__global__ __launch_bounds__(256) void ln_kernel(
    const float* __restrict__ x, const float* __restrict__ g,
    const float* __restrict__ bta, float* __restrict__ out)
{
    int t = blockIdx.x, tid = threadIdx.x;
    float4 v = ((const float4*)(x + (size_t)t * DIM))[tid];
    float s  = v.x + v.y + v.z + v.w;
    float sq = v.x * v.x + v.y * v.y + v.z * v.z + v.w * v.w;
    __shared__ float sh[8], sh2[8];
    float ws = warpsum(s), wq = warpsum(sq);
    if ((tid & 31) == 0) { sh[tid >> 5] = ws; sh2[tid >> 5] = wq; }
    __syncthreads();
    if (tid < 32) {
        float a  = (tid < 8) ? sh[tid]  : 0.f;
        float b2 = (tid < 8) ? sh2[tid] : 0.f;
        a = warpsum(a); b2 = warpsum(b2);
        if (tid == 0) { sh[0] = a; sh2[0] = b2; }
    }
    __syncthreads();
    float mu  = sh[0] * (1.0f / DIM);
    float var = sh2[0] * (1.0f / DIM) - mu * mu;
    float inv = rsqrtf(var + 1e-5f);
    float4 gg = ((const float4*)g)[tid], bb = ((const float4*)bta)[tid];
    float4 o;
    o.x = (v.x - mu) * inv * gg.x + bb.x;
    o.y = (v.y - mu) * inv * gg.y + bb.y;
    o.z = (v.z - mu) * inv * gg.z + bb.z;
    o.w = (v.w - mu) * inv * gg.w + bb.w;
    ((float4*)(out + (size_t)t * DIM))[tid] = o;
}

// ---------------- tensor-core attention (qkv fp16) ----------------
__global__ __launch_bounds__(128) void attn_scores_tc(
    const __half* __restrict__ qkv, float* __restrict__ S)
{
    int kt = blockIdx.x, qt = blockIdx.y, bh = blockIdx.z;
    int b = bh >> 4, h = bh & 15;
    __shared__ uint32_t Qs[64][36];
    __shared__ uint32_t Ks[64][36];
    int tid = threadIdx.x, lane = tid & 31, warp = tid >> 5;
    int l_row = tid >> 1, l_half = tid & 1;
    {
        const __half* qp = qkv + (size_t)(b * NSEQ + qt * 64 + l_row) * 3 * DIM + h * HDIM + l_half * 32;
        const __half* kp = qkv + (size_t)(b * NSEQ + kt * 64 + l_row) * 3 * DIM + DIM + h * HDIM + l_half * 32;
        #pragma unroll
        for (int i = 0; i < 4; i++) {
            *(uint4*)&Qs[l_row][l_half * 16 + i * 4] = *(const uint4*)(qp + i * 8);
            *(uint4*)&Ks[l_row][l_half * 16 + i * 4] = *(const uint4*)(kp + i * 8);
        }
    }
    __syncthreads();
    int m_base = warp * 16;
    uint32_t a_lrow = (uint32_t)(m_base + (lane & 7) + ((lane >> 3) & 1) * 8);
    uint32_t a_lcol = (uint32_t)((lane >> 4) * 4);
    int bl15 = lane & 15;
    float acc[8][4];
    #pragma unroll
    for (int i = 0; i < 8; i++)
        #pragma unroll
        for (int q = 0; q < 4; q++) acc[i][q] = 0.f;
    uint32_t qbase = smem_u32(Qs), kbase = smem_u32(Ks);
    #pragma unroll
    for (int j = 0; j < 4; j++) {
        uint32_t af[4];
        ldmx4(af, qbase + (a_lrow * 36 + j * 8 + a_lcol) * 4);
        #pragma unroll
        for (int ni = 0; ni < 8; ni++) {
            uint32_t bf[2];
            ldmx2(bf, kbase + ((uint32_t)(ni * 8 + (bl15 & 7)) * 36 + j * 8 + ((bl15 >> 3) & 1) * 4) * 4);
            mma16f(acc[ni], af, bf);
        }
    }
    int grp = lane >> 2, qid = lane & 3;
    float* Sp = S + (size_t)bh * NSEQ * NSEQ;
    int r0 = qt * 64 + m_base + grp;
    #pragma unroll
    for (int ni = 0; ni < 8; ni++) {
        int col = kt * 64 + ni * 8 + qid * 2;
        *(float2*)(Sp + (size_t)r0 * NSEQ + col)       = make_float2(acc[ni][0] * 0.125f, acc[ni][1] * 0.125f);
        *(float2*)(Sp + (size_t)(r0 + 8) * NSEQ + col) = make_float2(acc[ni][2] * 0.125f, acc[ni][3] * 0.125f);
    }
}

__global__ __launch_bounds__(128) void softmax_kernel(
    const float* __restrict__ S, __half* __restrict__ P)
{
    size_t row = (size_t)blockIdx.x * 4 + (threadIdx.x >> 5);
    int lane = threadIdx.x & 31;
    const float* p = S + row * NSEQ;
    __half* pp = P + row * NSEQ;
    float v[8];
    float m = -1e30f;
    #pragma unroll
    for (int i = 0; i < 8; i++) { v[i] = p[lane + i * 32]; m = fmaxf(m, v[i]); }
    m = warpmax(m);
    float s = 0.f;
    #pragma unroll
    for (int i = 0; i < 8; i++) { v[i] = expf(v[i] - m); s += v[i]; }
    s = warpsum(s);
    float inv = 1.0f / s;
    #pragma unroll
    for (int i = 0; i < 8; i++) pp[lane + i * 32] = __float2half(v[i] * inv);
}

__global__ __launch_bounds__(128) void attn_av_tc(
    const __half* __restrict__ qkv, const __half* __restrict__ P, float* __restrict__ o)
{
    int qt = blockIdx.x, bh = blockIdx.y;
    int b = bh >> 4, h = bh & 15;
    __shared__ uint32_t Ps[64][36];
    __shared__ uint32_t Vs[64][36];
    int tid = threadIdx.x, lane = tid & 31, warp = tid >> 5;
    int l_row = tid >> 1, l_half = tid & 1;
    int m_base = warp * 16;
    uint32_t a_lrow = (uint32_t)(m_base + (lane & 7) + ((lane >> 3) & 1) * 8);
    uint32_t a_lcol = (uint32_t)((lane >> 4) * 4);
    int bl15 = lane & 15;
    float acc[8][4];
    #pragma unroll
    for (int i = 0; i < 8; i++)
        #pragma unroll
        for (int q = 0; q < 4; q++) acc[i][q] = 0.f;
    uint32_t pbase = smem_u32(Ps), vbase = smem_u32(Vs);
    const __half* Pp = P + (size_t)bh * NSEQ * NSEQ + (size_t)(qt * 64 + l_row) * NSEQ + l_half * 32;

    for (int c = 0; c < 4; c++) {
        #pragma unroll
        for (int i = 0; i < 4; i++)
            *(uint4*)&Ps[l_row][l_half * 16 + i * 4] =
                *(const uint4*)((const char*)(Pp + c * 64) + i * 16);
        {
            const __half* vp = qkv + (size_t)(b * NSEQ + c * 64 + l_row) * 3 * DIM + 2 * DIM + h * HDIM + l_half * 32;
            #pragma unroll
            for (int i = 0; i < 4; i++)
                *(uint4*)&Vs[l_row][l_half * 16 + i * 4] = *(const uint4*)(vp + i * 8);
        }
        __syncthreads();
        #pragma unroll
        for (int j = 0; j < 4; j++) {
            uint32_t af[4];
            ldmx4(af, pbase + (a_lrow * 36 + j * 8 + a_lcol) * 4);
            #pragma unroll
            for (int ni = 0; ni < 8; ni++) {
                uint32_t bf[2];
                ldmx2t(bf, vbase + ((uint32_t)(j * 16 + bl15) * 36 + ni * 4) * 4);
                mma16f(acc[ni], af, bf);
            }
        }
        __syncthreads();
    }
    int grp = lane >> 2, qid = lane & 3;
    int r0 = qt * 64 + m_base + grp;
    #pragma unroll
    for (int ni = 0; ni < 8; ni++) {
        int d = ni * 8 + qid * 2;
        *(float2*)(o + (size_t)(b * NSEQ + r0) * DIM + h * HDIM + d)       = make_float2(acc[ni][0], acc[ni][1]);
        *(float2*)(o + (size_t)(b * NSEQ + r0 + 8) * DIM + h * HDIM + d)   = make_float2(acc[ni][2], acc[ni][3]);
    }
}

// ---------------- router ----------------
__global__ __launch_bounds__(128) void router_kernel(
    const float* __restrict__ gh, const float* __restrict__ W, const float* __restrict__ bias)
{
    int t = blockIdx.x;
    int wid = threadIdx.x >> 5, lane = threadIdx.x & 31;
    const float* row = gh + (size_t)t * RHC;
    float s = 0.f;
    for (int k = lane; k < RHC; k += 32) s += row[k] * W[k * NE + wid];
    s = warpsum(s);
    __shared__ float logits[NE];
    if (lane == 0) logits[wid] = s + bias[wid];
    __syncthreads();
    if (threadIdx.x == 0) {
        float l[NE], m = -1e30f;
        #pragma unroll
        for (int e = 0; e < NE; e++) { l[e] = logits[e]; m = fmaxf(m, l[e]); }
        float ssum = 0.f;
        #pragma unroll
        for (int e = 0; e < NE; e++) { l[e] = expf(l[e] - m); ssum += l[e]; }
        float p[NE];
        #pragma unroll
        for (int e = 0; e < NE; e++)
            p[e] = fminf(fmaxf(l[e] / ssum, 1e-9f), 1.0f - 1e-9f);
        int i1 = 0;
        #pragma unroll
        for (int e = 1; e < NE; e++) if (p[e] > p[i1]) i1 = e;
        int i2 = -1;
        #pragma unroll
        for (int e = 0; e < NE; e++) {
            if (e == i1) continue;
            if (i2 < 0 || p[e] > p[i2]) i2 = e;
        }
        float wsum = p[i1] + p[i2];
        int pos = atomicAdd(&g_cnt[i1], 1);
        g_idx[i1 * TT + pos] = t;
        pos = atomicAdd(&g_cnt[i2], 1);
        g_idx[i2 * TT + pos] = t;
        g_te[t] = make_int2(i1, i2);
        g_tw[t] = make_float2(p[i1] / wsum, p[i2] / wsum);
    }
}

__global__ void zero_cnt_kernel() {
    if (threadIdx.x < NE) g_cnt[threadIdx.x] = 0;
}

// out[t] = x1[t] + w1*eout[e1][t] + w2*eout[e2][t]  (eout fp16)
__global__ __launch_bounds__(256) void combine_kernel(
    const float* __restrict__ x1, const __half* __restrict__ eout, float* __restrict__ out)
{
    int t = blockIdx.x, c = threadIdx.x;
    int2 e = g_te[t];
    float2 w = g_tw[t];
    float4 a  = ((const float4*)(x1 + (size_t)t * DIM))[c];
    const __half* p1 = eout + ((size_t)e.x * TT + t) * DIM + c * 4;
    const __half* p2 = eout + ((size_t)e.y * TT + t) * DIM + c * 4;
    float2 v1a = __half22float2(*(const __half2*)(p1));
    float2 v1b = __half22float2(*(const __half2*)(p1 + 2));
    float2 v2a = __half22float2(*(const __half2*)(p2));
    float2 v2b = __half22float2(*(const __half2*)(p2 + 2));
    float4 r;
    r.x = a.x + w.x * v1a.x + w.y * v2a.x;
    r.y = a.y + w.x * v1a.y + w.y * v2a.y;
    r.z = a.z + w.x * v1b.x + w.y * v2b.x;
    r.w = a.w + w.x * v1b.y + w.y * v2b.y;
    ((float4*)(out + (size_t)t * DIM))[c] = r;
}

// ---------------- host launcher ----------------
static void* symaddr(const void* s) {
    void* p = nullptr;
    cudaGetSymbolAddress(&p, s);
    return p;
}

extern "C" void kernel_launch(void* const* d_in, const int* in_sizes, int n_in,
                              void* d_out, int out_size) {
    const float* x       = (const float*)d_in[0];
    const float* cond    = (const float*)d_in[1];
    const float* ln1_g   = (const float*)d_in[2];
    const float* ln1_b   = (const float*)d_in[3];
    const float* qkv_w   = (const float*)d_in[4];
    const float* proj_w  = (const float*)d_in[5];
    const float* proj_b  = (const float*)d_in[6];
    const float* ln2_g   = (const float*)d_in[7];
    const float* ln2_b   = (const float*)d_in[8];
    const float* r_fc1_w = (const float*)d_in[9];
    const float* r_fc1_b = (const float*)d_in[10];
    const float* r_fc2_w = (const float*)d_in[11];
    const float* r_fc2_b = (const float*)d_in[12];
    const float* e_w1    = (const float*)d_in[13];
    const float* e_b1    = (const float*)d_in[14];
    const float* e_w2    = (const float*)d_in[15];
    const float* e_b2    = (const float*)d_in[16];
    float* out = (float*)d_out;

    float*  h1    = (float*)symaddr(g_h1);
    __half* qkv   = (__half*)symaddr(g_qkv);
    float*  S     = (float*)symaddr(g_S);
    __half* P     = (__half*)symaddr(g_P);
    float*  o     = (float*)symaddr(g_o);
    float*  x1    = (float*)symaddr(g_x1);
    float*  h2    = (float*)symaddr(g_h2);
    float*  condc = (float*)symaddr(g_condc);
    float*  gh    = (float*)symaddr(g_gh);
    __half* hid   = (__half*)symaddr(g_hid);
    __half* eout  = (__half*)symaddr(g_eout);
    int*    cnt   = (int*)symaddr(g_cnt);
    int*    idx   = (int*)symaddr(g_idx);
    __half* wqkv_h  = (__half*)symaddr(g_wqkv_h);
    __half* wproj_h = (__half*)symaddr(g_wproj_h);
    __half* wfc1_h  = (__half*)symaddr(g_wfc1_h);
    __half* wfc1_l  = (__half*)symaddr(g_wfc1_l);
    __half* we1_h   = (__half*)symaddr(g_we1_h);
    __half* we2_h   = (__half*)symaddr(g_we2_h);

    cudaFuncSetAttribute(gemm_tc2<1,false,true,false,false,false,false,false,false>,
                         cudaFuncAttributeMaxDynamicSharedMemorySize, G_SMEM);
    cudaFuncSetAttribute(gemm_tc2<2,false,false,false,false,true,false,true,false>,
                         cudaFuncAttributeMaxDynamicSharedMemorySize, G_SMEM);
    cudaFuncSetAttribute(gemm_tc2<3,false,false,false,false,true,true,false,true>,
                         cudaFuncAttributeMaxDynamicSharedMemorySize, G_SMEM);
    cudaFuncSetAttribute(gemm_tc2<1,false,true,true,false,true,true,false,false>,
                         cudaFuncAttributeMaxDynamicSharedMemorySize, G_SMEM);
    cudaFuncSetAttribute(gemm_tc2<1,true,true,false,true,true,false,false,false>,
                         cudaFuncAttributeMaxDynamicSharedMemorySize, G_SMEM);

    zero_cnt_kernel<<<1, 32>>>();

    // pre-split weights: fc1 keeps hi+lo (router precision); qkv/proj/experts hi only
    wsplit_kernel<<<dim3(3 * DIM / 32, DIM / 32, 1), 256>>>(qkv_w, wqkv_h, nullptr, DIM, 3 * DIM, 3 * DIM, 0, 0);
    wsplit_kernel<<<dim3(DIM / 32, DIM / 32, 1), 256>>>(proj_w, wproj_h, nullptr, DIM, DIM, DIM, 0, 0);
    wsplit_kernel<<<dim3(RHC / 32, DIM / 32, 1), 256>>>(r_fc1_w, wfc1_h, wfc1_l, DIM, RHC, RHC, 0, 0);
    wsplit_kernel<<<dim3(DFFC / 32, DIM / 32, NE), 256>>>(e_w1, we1_h, nullptr, DIM, DFFC, DFFC,
                                                          (size_t)DIM * DFFC, (size_t)DFFC * DIM);
    wsplit_kernel<<<dim3(DIM / 32, DFFC / 32, NE), 256>>>(e_w2, we2_h, nullptr, DFFC, DIM, DIM,
                                                          (size_t)DFFC * DIM, (size_t)DIM * DFFC);

    // LN1
    ln_kernel<<<TT, 256>>>(x, ln1_g, ln1_b, h1);

    // QKV = h1 @ qkv_w (1-term; qkv consumed only through fp16 attention) -> fp16 out
    gemm_tc2<1,false,true,false,false,false,false,false,false>
        <<<dim3(3 * DIM / 128, TT / 128, 1), 256, G_SMEM>>>(h1, wqkv_h, nullptr, qkv, TT, 3 * DIM, DIM,
            nullptr, 0, nullptr, nullptr, nullptr, nullptr, 0, 0, 0);

    // attention (fp16 tensor cores, qkv fp16 in)
    attn_scores_tc<<<dim3(4, 4, BB * NH), 128>>>(qkv, S);
    softmax_kernel<<<BB * NH * NSEQ / 4, 128>>>(S, P);
    attn_av_tc<<<dim3(4, BB * NH), 128>>>(qkv, P, o);

    // x1 = x + o @ proj_w + proj_b (2-term)
    gemm_tc2<2,false,false,false,false,true,false,true,false>
        <<<dim3(DIM / 128, TT / 128, 1), 256, G_SMEM>>>(o, wproj_h, nullptr, x1, TT, DIM, DIM,
            proj_b, 0, x, nullptr, nullptr, nullptr, 0, 0, 0);

    // LN2
    ln_kernel<<<TT, 256>>>(x1, ln2_g, ln2_b, h2);

    // condc (tiny; legacy bf16 3-term)
    gemm_tc_plain<<<dim3(RHC / 128, 1), 256>>>(cond, r_fc1_w + (size_t)DIM * RHC, condc, BB, RHC, CDIM);

    // gh = gelu(h2 @ r_fc1_w[:D] + condc[b] + b1) (3-term — router precision critical)
    gemm_tc2<3,false,false,false,false,true,true,false,true>
        <<<dim3(RHC / 128, TT / 128, 1), 256, G_SMEM>>>(h2, wfc1_h, wfc1_l, gh, TT, RHC, DIM,
            r_fc1_b, 0, nullptr, condc, nullptr, nullptr, 0, 0, 0);

    // router
    router_kernel<<<TT, 128>>>(gh, r_fc2_w, r_fc2_b);

    // experts (1-term fp16), merged across NE; hid/eout fp16
    gemm_tc2<1,false,true,true,false,true,true,false,false>
        <<<dim3(DFFC / 128, TT / 128, NE), 256, G_SMEM>>>(h2, we1_h, nullptr, hid,
            TT, DFFC, DIM, e_b1, DFFC, nullptr, nullptr,
            idx, cnt, (size_t)DFFC * DIM, 0, TT);
    gemm_tc2<1,true,true,false,true,true,false,false,false>
        <<<dim3(DIM / 128, TT / 128, NE), 256, G_SMEM>>>(hid, we2_h, nullptr, eout,
            TT, DIM, DFFC, e_b2, DIM, nullptr, nullptr,
            idx, cnt, (size_t)DIM * DFFC, (size_t)TT * DFFC, TT);

    // out = x1 + w1*eout[e1] + w2*eout[e2]
    combine_kernel<<<TT, 256>>>(x1, eout, out);
}